// round 1
// baseline (speedup 1.0000x reference)
#include <cuda_runtime.h>

typedef unsigned long long UL;

// ---------------- device scratch (no allocations allowed) ----------------
__device__ float g_agg [50000 * 128];   // segment-sum of edge_feat per node
__device__ float g_aggc[50000 * 3];     // segment-sum of trans per node
__device__ float g_eb1 [128];           // e_b1  + prompt @ e_w1[273:401]
__device__ float g_nb1 [128];           // n_b1  + prompt @ n_w1[256:384]
__device__ float g_aeb1[128];           // ae_b1 + prompt @ ae_w1[128:256]
__device__ float g_apb1[128];           // ap_b1 + prompt @ ap_w1[128:256]

// ---------------- small helpers ----------------
__device__ __forceinline__ UL bc2(float x) {
    UL r; asm("mov.b64 %0,{%1,%1};" : "=l"(r) : "f"(x)); return r;
}
__device__ __forceinline__ UL pk2(float x, float y) {
    UL r; asm("mov.b64 %0,{%1,%2};" : "=l"(r) : "f"(x), "f"(y)); return r;
}
__device__ __forceinline__ float2 up2(UL v) {
    float2 f; asm("mov.b64 {%0,%1},%2;" : "=f"(f.x), "=f"(f.y) : "l"(v)); return f;
}
__device__ __forceinline__ void fma2(UL &d, UL a, UL b) {
    asm("fma.rn.f32x2 %0,%1,%2,%0;" : "+l"(d) : "l"(a), "l"(b));
}
__device__ __forceinline__ float silu_f(float x) {
    return __fdividef(x, 1.0f + __expf(-x));
}

// ---------------- 64x128 register-tiled GEMM (f32x2 packed FFMA) --------
// Xs: [64][xs_stride] smem input tile.  Wg: global row-major [K][128].
// Every thread owns 4 edges x 8 cols (as 4 f32x2 col-pairs) -> acc[16] u64.
// e0 = warprow*32 + er*4, c0 = warpcol*32 + cr*8.
__device__ __forceinline__ void gemm_tile(
    const float* __restrict__ Xs, int xs_stride,
    const float* __restrict__ Wg, int K,
    const float* __restrict__ biasg,
    float* Wbuf, int tid, int e0, int c0, UL* acc)
{
    float4 b0 = __ldg(reinterpret_cast<const float4*>(biasg + c0));
    float4 b1 = __ldg(reinterpret_cast<const float4*>(biasg + c0 + 4));
    UL bp0 = pk2(b0.x, b0.y), bp1 = pk2(b0.z, b0.w);
    UL bp2 = pk2(b1.x, b1.y), bp3 = pk2(b1.z, b1.w);
#pragma unroll
    for (int j = 0; j < 4; j++) {
        acc[j*4+0] = bp0; acc[j*4+1] = bp1; acc[j*4+2] = bp2; acc[j*4+3] = bp3;
    }

    for (int kb = 0; kb < K; kb += 128) {
        int kc = K - kb; if (kc > 128) kc = 128;
        __syncthreads();
        {   // stage weight chunk [kc][128] into smem
            const float4* src = reinterpret_cast<const float4*>(Wg) + (long)kb * 32;
            float4* dst = reinterpret_cast<float4*>(Wbuf);
            int tot = kc * 32;
            for (int i = tid; i < tot; i += 256) dst[i] = __ldg(src + i);
        }
        __syncthreads();
        const float* x0 = Xs + (e0 + 0) * xs_stride + kb;
        const float* x1 = Xs + (e0 + 1) * xs_stride + kb;
        const float* x2 = Xs + (e0 + 2) * xs_stride + kb;
        const float* x3 = Xs + (e0 + 3) * xs_stride + kb;
        const float* wp = Wbuf + c0;
#pragma unroll 4
        for (int kk = 0; kk < kc; kk++) {
            UL a0 = bc2(x0[kk]), a1 = bc2(x1[kk]), a2 = bc2(x2[kk]), a3 = bc2(x3[kk]);
            ulonglong2 wA = *reinterpret_cast<const ulonglong2*>(wp + (long)kk * 128);
            ulonglong2 wB = *reinterpret_cast<const ulonglong2*>(wp + (long)kk * 128 + 4);
            fma2(acc[0],  a0, wA.x); fma2(acc[1],  a0, wA.y);
            fma2(acc[2],  a0, wB.x); fma2(acc[3],  a0, wB.y);
            fma2(acc[4],  a1, wA.x); fma2(acc[5],  a1, wA.y);
            fma2(acc[6],  a1, wB.x); fma2(acc[7],  a1, wB.y);
            fma2(acc[8],  a2, wA.x); fma2(acc[9],  a2, wA.y);
            fma2(acc[10], a2, wB.x); fma2(acc[11], a2, wB.y);
            fma2(acc[12], a3, wA.x); fma2(acc[13], a3, wA.y);
            fma2(acc[14], a3, wB.x); fma2(acc[15], a3, wB.y);
        }
    }
}

// ---------------- prompt-bias precompute ----------------
__global__ void prep_kernel(
    const float* __restrict__ prompt,
    const float* __restrict__ e_w1,  const float* __restrict__ e_b1,
    const float* __restrict__ n_w1,  const float* __restrict__ n_b1,
    const float* __restrict__ ae_w1, const float* __restrict__ ae_b1,
    const float* __restrict__ ap_w1, const float* __restrict__ ap_b1)
{
    int n = threadIdx.x;  // 128 threads
    float s1 = e_b1[n], s2 = n_b1[n], s3 = ae_b1[n], s4 = ap_b1[n];
    for (int j = 0; j < 128; j++) {
        float p = prompt[j];
        s1 = fmaf(p, e_w1 [(273 + j) * 128 + n], s1);
        s2 = fmaf(p, n_w1 [(256 + j) * 128 + n], s2);
        s3 = fmaf(p, ae_w1[(128 + j) * 128 + n], s3);
        s4 = fmaf(p, ap_w1[(128 + j) * 128 + n], s4);
    }
    g_eb1[n] = s1; g_nb1[n] = s2; g_aeb1[n] = s3; g_apb1[n] = s4;
}

// ---------------- zero scratch ----------------
__global__ void zero_kernel(int N)
{
    long stride = (long)gridDim.x * blockDim.x;
    long t1 = (long)N * 128;
    for (long i = blockIdx.x * (long)blockDim.x + threadIdx.x; i < t1; i += stride)
        g_agg[i] = 0.0f;
    long t2 = (long)N * 3;
    for (long i = blockIdx.x * (long)blockDim.x + threadIdx.x; i < t2; i += stride)
        g_aggc[i] = 0.0f;
}

// ---------------- fused edge kernel ----------------
// smem layout (floats): Xs[64*277] | Ys[64*133] | Wbuf[128*128] | cd[64*4] | sES[64] | rowi[64]
#define EDGE_XS 277
#define TILE_YS 133
#define EDGE_SMEM ((64*277 + 64*133 + 128*128 + 64*4 + 64 + 64) * 4)

__global__ void __launch_bounds__(256, 1) edge_kernel(
    const float* __restrict__ h, const int* __restrict__ ei,
    const float* __restrict__ coord, const float* __restrict__ eattr,
    const float* __restrict__ e_w1, const float* __restrict__ e_w2,
    const float* __restrict__ e_b2,
    const float* __restrict__ ae_w1, const float* __restrict__ ae_w2,
    int E)
{
    extern __shared__ float sm[];
    float*  Xs   = sm;
    float*  Ys   = Xs + 64 * EDGE_XS;
    float*  Wbuf = Ys + 64 * TILE_YS;
    float4* cd   = reinterpret_cast<float4*>(Wbuf + 128 * 128);
    float*  sES  = reinterpret_cast<float*>(cd + 64);
    int*    rowi = reinterpret_cast<int*>(sES + 64);

    const int tid = threadIdx.x;
    const int e_base = blockIdx.x * 64;
    const int* rowg = ei;
    const int* colg = ei + E;

    // ------- stage X tile: [h[row] | h[col] | radial | edge_attr] = 273 dims -------
    {
        const int el = tid & 63, part = tid >> 6;
        int e = e_base + el;
        bool v = e < E;
        long r = v ? (long)rowg[e] : 0;
        long c = v ? (long)colg[e] : 0;
        const float4* hr = reinterpret_cast<const float4*>(h) + r * 32 + part * 8;
        const float4* hc = reinterpret_cast<const float4*>(h) + c * 32 + part * 8;
        float* xr = Xs + el * EDGE_XS + part * 32;
#pragma unroll
        for (int i = 0; i < 8; i++) {
            float4 a = v ? __ldg(hr + i) : make_float4(0.f, 0.f, 0.f, 0.f);
            xr[4*i+0] = a.x; xr[4*i+1] = a.y; xr[4*i+2] = a.z; xr[4*i+3] = a.w;
        }
#pragma unroll
        for (int i = 0; i < 8; i++) {
            float4 b = v ? __ldg(hc + i) : make_float4(0.f, 0.f, 0.f, 0.f);
            xr[128+4*i+0] = b.x; xr[128+4*i+1] = b.y; xr[128+4*i+2] = b.z; xr[128+4*i+3] = b.w;
        }
        if (part == 0) {
            rowi[el] = (int)r;
            float dx = 0.f, dy = 0.f, dz = 0.f;
            if (v) {
                dx = coord[r*3+0] - coord[c*3+0];
                dy = coord[r*3+1] - coord[c*3+1];
                dz = coord[r*3+2] - coord[c*3+2];
            }
            float rad = dx*dx + dy*dy + dz*dz;
            Xs[el * EDGE_XS + 256] = rad;
            float inv = 1.0f / fmaxf(sqrtf(rad), 1e-12f);
            cd[el] = make_float4(dx, dy, dz, inv);
        } else if (part == 1) {
            const float4* ea = reinterpret_cast<const float4*>(eattr) + (long)e * 4;
#pragma unroll
            for (int i = 0; i < 4; i++) {
                float4 a = v ? __ldg(ea + i) : make_float4(0.f, 0.f, 0.f, 0.f);
                float* xq = Xs + el * EDGE_XS + 257 + 4 * i;
                xq[0] = a.x; xq[1] = a.y; xq[2] = a.z; xq[3] = a.w;
            }
        }
    }
    // (first __syncthreads inside gemm_tile makes the staged tile visible)

    const int warp = tid >> 5, lane = tid & 31;
    const int e0 = (warp >> 2) * 32 + (lane >> 2) * 4;
    const int c0 = (warp & 3) * 32 + (lane & 3) * 8;

    UL acc[16];

    // ------- GEMM1: [64 x 273] @ e_w1[0:273] + eb1_eff -> SiLU -> Ys -------
    gemm_tile(Xs, EDGE_XS, e_w1, 273, g_eb1, Wbuf, tid, e0, c0, acc);
#pragma unroll
    for (int j = 0; j < 4; j++) {
        float* yr = Ys + (e0 + j) * TILE_YS + c0;
#pragma unroll
        for (int p = 0; p < 4; p++) {
            float2 f = up2(acc[j*4+p]);
            yr[2*p]   = silu_f(f.x);
            yr[2*p+1] = silu_f(f.y);
        }
    }

    // ------- GEMM2: [64 x 128] @ e_w2 + e_b2 -> SiLU = edge_feat -------
    gemm_tile(Ys, TILE_YS, e_w2, 128, e_b2, Wbuf, tid, e0, c0, acc);
    __syncthreads();  // all warps done reading Ys before overwrite
#pragma unroll
    for (int j = 0; j < 4; j++) {
        float z[8];
#pragma unroll
        for (int p = 0; p < 4; p++) {
            float2 f = up2(acc[j*4+p]);
            z[2*p] = silu_f(f.x); z[2*p+1] = silu_f(f.y);
        }
        float* yr = Ys + (e0 + j) * TILE_YS + c0;
#pragma unroll
        for (int i = 0; i < 8; i++) yr[i] = z[i];
        int eg = e_base + e0 + j;
        if (eg < E) {
            float* dst = g_agg + (long)rowi[e0 + j] * 128 + c0;
#pragma unroll
            for (int i = 0; i < 8; i++) atomicAdd(dst + i, z[i]);
        }
    }
    if (tid < 64) sES[tid] = 0.0f;

    // ------- GEMM3: edge_feat @ ae_w1[0:128] + aeb1_eff -> SiLU -> dot ae_w2 -------
    gemm_tile(Ys, TILE_YS, ae_w1, 128, g_aeb1, Wbuf, tid, e0, c0, acc);
    {
        float4 w0 = __ldg(reinterpret_cast<const float4*>(ae_w2 + c0));
        float4 w1 = __ldg(reinterpret_cast<const float4*>(ae_w2 + c0 + 4));
        float wv[8] = { w0.x, w0.y, w0.z, w0.w, w1.x, w1.y, w1.z, w1.w };
#pragma unroll
        for (int j = 0; j < 4; j++) {
            float p = 0.0f;
#pragma unroll
            for (int q = 0; q < 4; q++) {
                float2 f = up2(acc[j*4+q]);
                p += silu_f(f.x) * wv[2*q];
                p += silu_f(f.y) * wv[2*q+1];
            }
            p += __shfl_xor_sync(0xffffffffu, p, 1);
            p += __shfl_xor_sync(0xffffffffu, p, 2);
            if ((lane & 3) == 0) atomicAdd(&sES[e0 + j], p);
        }
    }
    __syncthreads();
    if (tid < 64) {
        int eg = e_base + tid;
        if (eg < E) {
            float s = sES[tid];
            float4 c = cd[tid];
            float f = s * c.w;  // phi(e) / max(||d||,1e-12)
            float* dst = g_aggc + (long)rowi[tid] * 3;
            atomicAdd(dst + 0, c.x * f);
            atomicAdd(dst + 1, c.y * f);
            atomicAdd(dst + 2, c.z * f);
        }
    }
}

// ---------------- fused node kernel ----------------
// smem: Xn[64*261] | Yn[64*133] | Wbuf[128*128] | sES[64]
#define NODE_XS 261
#define NODE_SMEM ((64*261 + 64*133 + 128*128 + 64) * 4)

__global__ void __launch_bounds__(256, 1) node_kernel(
    const float* __restrict__ h, const float* __restrict__ coordg,
    const float* __restrict__ n_w1, const float* __restrict__ n_w2,
    const float* __restrict__ n_b2,
    const float* __restrict__ ap_w1, const float* __restrict__ ap_w2,
    float* __restrict__ out, int N)
{
    extern __shared__ float sm[];
    float* Xn   = sm;
    float* Yn   = Xn + 64 * NODE_XS;
    float* Wbuf = Yn + 64 * TILE_YS;
    float* sES  = Wbuf + 128 * 128;

    const int tid = threadIdx.x;
    const int nb = blockIdx.x * 64;

    // ------- stage [h | agg] = 256 dims -------
    {
        const int el = tid & 63, part = tid >> 6;
        int n = nb + el;
        bool v = n < N;
        long nn = v ? (long)n : 0;
        const float4* hr = reinterpret_cast<const float4*>(h) + nn * 32 + part * 8;
        const float4* ar = reinterpret_cast<const float4*>(g_agg) + nn * 32 + part * 8;
        float* xr = Xn + el * NODE_XS + part * 32;
#pragma unroll
        for (int i = 0; i < 8; i++) {
            float4 a = v ? __ldg(hr + i) : make_float4(0.f, 0.f, 0.f, 0.f);
            xr[4*i+0] = a.x; xr[4*i+1] = a.y; xr[4*i+2] = a.z; xr[4*i+3] = a.w;
        }
#pragma unroll
        for (int i = 0; i < 8; i++) {
            float4 a = v ? ar[i] : make_float4(0.f, 0.f, 0.f, 0.f);
            xr[128+4*i+0] = a.x; xr[128+4*i+1] = a.y; xr[128+4*i+2] = a.z; xr[128+4*i+3] = a.w;
        }
    }

    const int warp = tid >> 5, lane = tid & 31;
    const int e0 = (warp >> 2) * 32 + (lane >> 2) * 4;
    const int c0 = (warp & 3) * 32 + (lane & 3) * 8;

    UL acc[16];

    // ------- node GEMM1: [64 x 256] @ n_w1[0:256] + nb1_eff -> SiLU -------
    gemm_tile(Xn, NODE_XS, n_w1, 256, g_nb1, Wbuf, tid, e0, c0, acc);
#pragma unroll
    for (int j = 0; j < 4; j++) {
        float* yr = Yn + (e0 + j) * TILE_YS + c0;
#pragma unroll
        for (int p = 0; p < 4; p++) {
            float2 f = up2(acc[j*4+p]);
            yr[2*p]   = silu_f(f.x);
            yr[2*p+1] = silu_f(f.y);
        }
    }

    // ------- node GEMM2: @ n_w2 + n_b2 -> SiLU -> h_out = h + . -------
    gemm_tile(Yn, TILE_YS, n_w2, 128, n_b2, Wbuf, tid, e0, c0, acc);
    __syncthreads();
#pragma unroll
    for (int j = 0; j < 4; j++) {
        int n = nb + e0 + j;
        float ho[8];
        const float* xh = Xn + (e0 + j) * NODE_XS + c0;
#pragma unroll
        for (int p = 0; p < 4; p++) {
            float2 f = up2(acc[j*4+p]);
            ho[2*p]   = silu_f(f.x) + xh[2*p];
            ho[2*p+1] = silu_f(f.y) + xh[2*p+1];
        }
        float* yr = Yn + (e0 + j) * TILE_YS + c0;
#pragma unroll
        for (int i = 0; i < 8; i++) yr[i] = ho[i];
        if (n < N) {
            float* o = out + (long)n * 128 + c0;
#pragma unroll
            for (int i = 0; i < 8; i++) o[i] = ho[i];
        }
    }
    if (tid < 64) sES[tid] = 0.0f;

    // ------- acc-point MLP: h_out @ ap_w1[0:128] + apb1_eff -> SiLU -> dot ap_w2 -------
    gemm_tile(Yn, TILE_YS, ap_w1, 128, g_apb1, Wbuf, tid, e0, c0, acc);
    {
        float4 w0 = __ldg(reinterpret_cast<const float4*>(ap_w2 + c0));
        float4 w1 = __ldg(reinterpret_cast<const float4*>(ap_w2 + c0 + 4));
        float wv[8] = { w0.x, w0.y, w0.z, w0.w, w1.x, w1.y, w1.z, w1.w };
#pragma unroll
        for (int j = 0; j < 4; j++) {
            float p = 0.0f;
#pragma unroll
            for (int q = 0; q < 4; q++) {
                float2 f = up2(acc[j*4+q]);
                p += silu_f(f.x) * wv[2*q];
                p += silu_f(f.y) * wv[2*q+1];
            }
            p += __shfl_xor_sync(0xffffffffu, p, 1);
            p += __shfl_xor_sync(0xffffffffu, p, 2);
            if ((lane & 3) == 0) atomicAdd(&sES[e0 + j], p);
        }
    }
    __syncthreads();
    if (tid < 64) {
        int n = nb + tid;
        if (n < N) {
            float s = sES[tid];
            long base_c = (long)N * 128;
            long base_a = (long)N * 131;
            out[base_c + (long)n*3 + 0] = coordg[n*3+0];
            out[base_c + (long)n*3 + 1] = coordg[n*3+1];
            out[base_c + (long)n*3 + 2] = coordg[n*3+2];
            out[base_a + (long)n*3 + 0] = g_aggc[n*3+0] * s;
            out[base_a + (long)n*3 + 1] = g_aggc[n*3+1] * s;
            out[base_a + (long)n*3 + 2] = g_aggc[n*3+2] * s;
        }
    }
}

// ---------------- launch ----------------
extern "C" void kernel_launch(void* const* d_in, const int* in_sizes, int n_in,
                              void* d_out, int out_size)
{
    const float* h      = (const float*)d_in[0];
    const int*   ei     = (const int*)  d_in[1];
    const float* coord  = (const float*)d_in[2];
    const float* eattr  = (const float*)d_in[3];
    const float* prompt = (const float*)d_in[4];
    const float* e_w1   = (const float*)d_in[5];
    const float* e_b1   = (const float*)d_in[6];
    const float* e_w2   = (const float*)d_in[7];
    const float* e_b2   = (const float*)d_in[8];
    const float* n_w1   = (const float*)d_in[9];
    const float* n_b1   = (const float*)d_in[10];
    const float* n_w2   = (const float*)d_in[11];
    const float* n_b2   = (const float*)d_in[12];
    const float* ae_w1  = (const float*)d_in[13];
    const float* ae_b1  = (const float*)d_in[14];
    const float* ae_w2  = (const float*)d_in[15];
    const float* ap_w1  = (const float*)d_in[16];
    const float* ap_b1  = (const float*)d_in[17];
    const float* ap_w2  = (const float*)d_in[18];
    float* out = (float*)d_out;

    int N = in_sizes[0] / 128;
    int E = in_sizes[1] / 2;

    cudaFuncSetAttribute(edge_kernel, cudaFuncAttributeMaxDynamicSharedMemorySize, EDGE_SMEM);
    cudaFuncSetAttribute(node_kernel, cudaFuncAttributeMaxDynamicSharedMemorySize, NODE_SMEM);

    prep_kernel<<<1, 128>>>(prompt, e_w1, e_b1, n_w1, n_b1, ae_w1, ae_b1, ap_w1, ap_b1);
    zero_kernel<<<264, 256>>>(N);
    edge_kernel<<<(E + 63) / 64, 256, EDGE_SMEM>>>(h, ei, coord, eattr,
                                                   e_w1, e_w2, e_b2, ae_w1, ae_w2, E);
    node_kernel<<<(N + 63) / 64, 256, NODE_SMEM>>>(h, coord, n_w1, n_w2, n_b2,
                                                   ap_w1, ap_w2, out, N);
}

// round 4
// speedup vs baseline: 1.1659x; 1.1659x over previous
#include <cuda_runtime.h>

typedef unsigned long long UL;

// ---------------- device scratch (no allocations allowed) ----------------
__device__ float g_agg [50000 * 128];   // segment-sum of edge_feat per node
__device__ float g_aggc[50000 * 3];     // segment-sum of trans per node
__device__ float g_eb1 [128];           // e_b1  + prompt @ e_w1[273:401]
__device__ float g_nb1 [128];           // n_b1  + prompt @ n_w1[256:384]
__device__ float g_aeb1[128];           // ae_b1 + prompt @ ae_w1[128:256]
__device__ float g_apb1[128];           // ap_b1 + prompt @ ap_w1[128:256]

// ---------------- small helpers ----------------
__device__ __forceinline__ UL bc2(float x) {
    UL r; asm("mov.b64 %0,{%1,%1};" : "=l"(r) : "f"(x)); return r;
}
__device__ __forceinline__ UL pk2(float x, float y) {
    UL r; asm("mov.b64 %0,{%1,%2};" : "=l"(r) : "f"(x), "f"(y)); return r;
}
__device__ __forceinline__ float2 up2(UL v) {
    float2 f; asm("mov.b64 {%0,%1},%2;" : "=f"(f.x), "=f"(f.y) : "l"(v)); return f;
}
__device__ __forceinline__ void fma2(UL &d, UL a, UL b) {
    asm("fma.rn.f32x2 %0,%1,%2,%0;" : "+l"(d) : "l"(a), "l"(b));
}
__device__ __forceinline__ float silu_f(float x) {
    return __fdividef(x, 1.0f + __expf(-x));
}

// ---------------- register-tiled GEMM, weights streamed from L2 --------
// Xs: [tile][xs_stride] smem (odd stride -> conflict-free scalar loads).
// Wg: global row-major [K][128] (L2-resident, broadcast across CTAs).
// Thread owns 4 rows x 8 cols (4 f32x2 col-pairs per row) -> acc[16] u64.
// Weight rows are double-buffered 2 k-steps ahead in registers.
// NOTE: one W row = 128 floats = 32 ulonglong2 (row stride *32 in u64x2 units).
template<int K>
__device__ __forceinline__ void gemm_stream(
    const float* Xs, int xs_stride,
    const float* __restrict__ Wg,
    const float* __restrict__ biasg,
    int e0, int c0, UL* acc)
{
    float4 b0 = __ldg(reinterpret_cast<const float4*>(biasg + c0));
    float4 b1 = __ldg(reinterpret_cast<const float4*>(biasg + c0 + 4));
    UL bp0 = pk2(b0.x, b0.y), bp1 = pk2(b0.z, b0.w);
    UL bp2 = pk2(b1.x, b1.y), bp3 = pk2(b1.z, b1.w);
#pragma unroll
    for (int j = 0; j < 4; j++) {
        acc[j*4+0] = bp0; acc[j*4+1] = bp1; acc[j*4+2] = bp2; acc[j*4+3] = bp3;
    }

    const float* x0 = Xs + (e0 + 0) * xs_stride;
    const float* x1 = Xs + (e0 + 1) * xs_stride;
    const float* x2 = Xs + (e0 + 2) * xs_stride;
    const float* x3 = Xs + (e0 + 3) * xs_stride;
    // one W row = 128 floats = 32 ulonglong2
    const ulonglong2* wA = reinterpret_cast<const ulonglong2*>(Wg + c0);
    const ulonglong2* wB = reinterpret_cast<const ulonglong2*>(Wg + c0 + 4);

    constexpr int KE = K & ~1;

    ulonglong2 cA0 = __ldg(wA),      cB0 = __ldg(wB);        // row 0
    ulonglong2 cA1 = __ldg(wA + 32), cB1 = __ldg(wB + 32);   // row 1

#pragma unroll 2
    for (int k = 0; k < KE; k += 2) {
        int k2 = (k + 2 < K) ? (k + 2) : (K - 1);
        int k3 = (k + 3 < K) ? (k + 3) : (K - 1);
        ulonglong2 nA0 = __ldg(wA + (long)k2 * 32), nB0 = __ldg(wB + (long)k2 * 32);
        ulonglong2 nA1 = __ldg(wA + (long)k3 * 32), nB1 = __ldg(wB + (long)k3 * 32);

        UL s0 = bc2(x0[k]), s1 = bc2(x1[k]), s2 = bc2(x2[k]), s3 = bc2(x3[k]);
        fma2(acc[0],  s0, cA0.x); fma2(acc[1],  s0, cA0.y);
        fma2(acc[2],  s0, cB0.x); fma2(acc[3],  s0, cB0.y);
        fma2(acc[4],  s1, cA0.x); fma2(acc[5],  s1, cA0.y);
        fma2(acc[6],  s1, cB0.x); fma2(acc[7],  s1, cB0.y);
        fma2(acc[8],  s2, cA0.x); fma2(acc[9],  s2, cA0.y);
        fma2(acc[10], s2, cB0.x); fma2(acc[11], s2, cB0.y);
        fma2(acc[12], s3, cA0.x); fma2(acc[13], s3, cA0.y);
        fma2(acc[14], s3, cB0.x); fma2(acc[15], s3, cB0.y);

        s0 = bc2(x0[k+1]); s1 = bc2(x1[k+1]); s2 = bc2(x2[k+1]); s3 = bc2(x3[k+1]);
        fma2(acc[0],  s0, cA1.x); fma2(acc[1],  s0, cA1.y);
        fma2(acc[2],  s0, cB1.x); fma2(acc[3],  s0, cB1.y);
        fma2(acc[4],  s1, cA1.x); fma2(acc[5],  s1, cA1.y);
        fma2(acc[6],  s1, cB1.x); fma2(acc[7],  s1, cB1.y);
        fma2(acc[8],  s2, cA1.x); fma2(acc[9],  s2, cA1.y);
        fma2(acc[10], s2, cB1.x); fma2(acc[11], s2, cB1.y);
        fma2(acc[12], s3, cA1.x); fma2(acc[13], s3, cA1.y);
        fma2(acc[14], s3, cB1.x); fma2(acc[15], s3, cB1.y);

        cA0 = nA0; cB0 = nB0; cA1 = nA1; cB1 = nB1;
    }
    if (K & 1) {  // tail row K-1: rotation left it in cA0/cB0
        UL s0 = bc2(x0[K-1]), s1 = bc2(x1[K-1]), s2 = bc2(x2[K-1]), s3 = bc2(x3[K-1]);
        fma2(acc[0],  s0, cA0.x); fma2(acc[1],  s0, cA0.y);
        fma2(acc[2],  s0, cB0.x); fma2(acc[3],  s0, cB0.y);
        fma2(acc[4],  s1, cA0.x); fma2(acc[5],  s1, cA0.y);
        fma2(acc[6],  s1, cB0.x); fma2(acc[7],  s1, cB0.y);
        fma2(acc[8],  s2, cA0.x); fma2(acc[9],  s2, cA0.y);
        fma2(acc[10], s2, cB0.x); fma2(acc[11], s2, cB0.y);
        fma2(acc[12], s3, cA0.x); fma2(acc[13], s3, cA0.y);
        fma2(acc[14], s3, cB0.x); fma2(acc[15], s3, cB0.y);
    }
}

// ---------------- prompt-bias precompute ----------------
__global__ void prep_kernel(
    const float* __restrict__ prompt,
    const float* __restrict__ e_w1,  const float* __restrict__ e_b1,
    const float* __restrict__ n_w1,  const float* __restrict__ n_b1,
    const float* __restrict__ ae_w1, const float* __restrict__ ae_b1,
    const float* __restrict__ ap_w1, const float* __restrict__ ap_b1)
{
    int n = threadIdx.x;  // 128 threads
    float s1 = e_b1[n], s2 = n_b1[n], s3 = ae_b1[n], s4 = ap_b1[n];
    for (int j = 0; j < 128; j++) {
        float p = prompt[j];
        s1 = fmaf(p, e_w1 [(273 + j) * 128 + n], s1);
        s2 = fmaf(p, n_w1 [(256 + j) * 128 + n], s2);
        s3 = fmaf(p, ae_w1[(128 + j) * 128 + n], s3);
        s4 = fmaf(p, ap_w1[(128 + j) * 128 + n], s4);
    }
    g_eb1[n] = s1; g_nb1[n] = s2; g_aeb1[n] = s3; g_apb1[n] = s4;
}

// ---------------- zero scratch ----------------
__global__ void zero_kernel(int N)
{
    long stride = (long)gridDim.x * blockDim.x;
    long t1 = (long)N * 128;
    for (long i = blockIdx.x * (long)blockDim.x + threadIdx.x; i < t1; i += stride)
        g_agg[i] = 0.0f;
    long t2 = (long)N * 3;
    for (long i = blockIdx.x * (long)blockDim.x + threadIdx.x; i < t2; i += stride)
        g_aggc[i] = 0.0f;
}

// ---------------- fused edge kernel ----------------
// 128 edges per CTA, 512 threads, 16 warps.
#define EDGE_XS 277
#define TILE_YS 133
#define EDGE_SMEM ((128*277 + 128*133) * 4 + 128*16 + 128*4 + 128*4)

__global__ void __launch_bounds__(512, 1) edge_kernel(
    const float* __restrict__ h, const int* __restrict__ ei,
    const float* __restrict__ coord, const float* __restrict__ eattr,
    const float* __restrict__ e_w1, const float* __restrict__ e_w2,
    const float* __restrict__ e_b2,
    const float* __restrict__ ae_w1, const float* __restrict__ ae_w2,
    int E)
{
    extern __shared__ float sm[];
    float*  Xs   = sm;
    float*  Ys   = Xs + 128 * EDGE_XS;
    float4* cd   = reinterpret_cast<float4*>(Ys + 128 * TILE_YS);
    float*  sES  = reinterpret_cast<float*>(cd + 128);
    int*    rowi = reinterpret_cast<int*>(sES + 128);

    const int tid = threadIdx.x;
    const int e_base = blockIdx.x * 128;
    const int* rowg = ei;
    const int* colg = ei + E;

    // ------- stage X tile: [h[row] | h[col] | radial | edge_attr] = 273 dims ----
    {
        const int el = tid & 127, part = tid >> 7;   // 4 parts of 32 floats
        int e = e_base + el;
        bool v = e < E;
        long r = v ? (long)rowg[e] : 0;
        long c = v ? (long)colg[e] : 0;
        const float4* hr = reinterpret_cast<const float4*>(h) + r * 32 + part * 8;
        const float4* hc = reinterpret_cast<const float4*>(h) + c * 32 + part * 8;
        float* xr = Xs + el * EDGE_XS + part * 32;
#pragma unroll
        for (int i = 0; i < 8; i++) {
            float4 a = v ? __ldg(hr + i) : make_float4(0.f, 0.f, 0.f, 0.f);
            xr[4*i+0] = a.x; xr[4*i+1] = a.y; xr[4*i+2] = a.z; xr[4*i+3] = a.w;
        }
#pragma unroll
        for (int i = 0; i < 8; i++) {
            float4 b = v ? __ldg(hc + i) : make_float4(0.f, 0.f, 0.f, 0.f);
            xr[128+4*i+0] = b.x; xr[128+4*i+1] = b.y; xr[128+4*i+2] = b.z; xr[128+4*i+3] = b.w;
        }
        if (part == 0) {
            rowi[el] = (int)r;
            float dx = 0.f, dy = 0.f, dz = 0.f;
            if (v) {
                dx = coord[r*3+0] - coord[c*3+0];
                dy = coord[r*3+1] - coord[c*3+1];
                dz = coord[r*3+2] - coord[c*3+2];
            }
            float rad = dx*dx + dy*dy + dz*dz;
            Xs[el * EDGE_XS + 256] = rad;
            float inv = 1.0f / fmaxf(sqrtf(rad), 1e-12f);
            cd[el] = make_float4(dx, dy, dz, inv);
        } else if (part == 1) {
            const float4* ea = reinterpret_cast<const float4*>(eattr) + (long)e * 4;
#pragma unroll
            for (int i = 0; i < 4; i++) {
                float4 a = v ? __ldg(ea + i) : make_float4(0.f, 0.f, 0.f, 0.f);
                float* xq = Xs + el * EDGE_XS + 257 + 4 * i;
                xq[0] = a.x; xq[1] = a.y; xq[2] = a.z; xq[3] = a.w;
            }
        }
    }
    __syncthreads();

    const int warp = tid >> 5, lane = tid & 31;
    const int e0 = (warp >> 2) * 32 + (lane >> 2) * 4;
    const int c0 = (warp & 3) * 32 + (lane & 3) * 8;

    UL acc[16];

    // ------- GEMM1: [128 x 273] @ e_w1[0:273] + eb1_eff -> SiLU -> Ys -------
    gemm_stream<273>(Xs, EDGE_XS, e_w1, g_eb1, e0, c0, acc);
#pragma unroll
    for (int j = 0; j < 4; j++) {
        float* yr = Ys + (e0 + j) * TILE_YS + c0;
#pragma unroll
        for (int p = 0; p < 4; p++) {
            float2 f = up2(acc[j*4+p]);
            yr[2*p]   = silu_f(f.x);
            yr[2*p+1] = silu_f(f.y);
        }
    }
    __syncthreads();

    // ------- GEMM2: [128 x 128] @ e_w2 + e_b2 -> SiLU = edge_feat -------
    gemm_stream<128>(Ys, TILE_YS, e_w2, e_b2, e0, c0, acc);
    __syncthreads();  // all warps done reading Ys before overwrite
#pragma unroll
    for (int j = 0; j < 4; j++) {
        float z[8];
#pragma unroll
        for (int p = 0; p < 4; p++) {
            float2 f = up2(acc[j*4+p]);
            z[2*p] = silu_f(f.x); z[2*p+1] = silu_f(f.y);
        }
        float* yr = Ys + (e0 + j) * TILE_YS + c0;
#pragma unroll
        for (int i = 0; i < 8; i++) yr[i] = z[i];
        int eg = e_base + e0 + j;
        if (eg < E) {
            float* dst = g_agg + (long)rowi[e0 + j] * 128 + c0;
            atomicAdd(reinterpret_cast<float4*>(dst),
                      make_float4(z[0], z[1], z[2], z[3]));
            atomicAdd(reinterpret_cast<float4*>(dst + 4),
                      make_float4(z[4], z[5], z[6], z[7]));
        }
    }
    if (tid < 128) sES[tid] = 0.0f;
    __syncthreads();

    // ------- GEMM3: edge_feat @ ae_w1[0:128] + aeb1_eff -> SiLU -> dot ae_w2 ---
    gemm_stream<128>(Ys, TILE_YS, ae_w1, g_aeb1, e0, c0, acc);
    {
        float4 w0 = __ldg(reinterpret_cast<const float4*>(ae_w2 + c0));
        float4 w1 = __ldg(reinterpret_cast<const float4*>(ae_w2 + c0 + 4));
        float wv[8] = { w0.x, w0.y, w0.z, w0.w, w1.x, w1.y, w1.z, w1.w };
#pragma unroll
        for (int j = 0; j < 4; j++) {
            float p = 0.0f;
#pragma unroll
            for (int q = 0; q < 4; q++) {
                float2 f = up2(acc[j*4+q]);
                p += silu_f(f.x) * wv[2*q];
                p += silu_f(f.y) * wv[2*q+1];
            }
            p += __shfl_xor_sync(0xffffffffu, p, 1);
            p += __shfl_xor_sync(0xffffffffu, p, 2);
            if ((lane & 3) == 0) atomicAdd(&sES[e0 + j], p);
        }
    }
    __syncthreads();
    if (tid < 128) {
        int eg = e_base + tid;
        if (eg < E) {
            float s = sES[tid];
            float4 c = cd[tid];
            float f = s * c.w;  // phi(e) / max(||d||,1e-12)
            float* dst = g_aggc + (long)rowi[tid] * 3;
            atomicAdd(dst + 0, c.x * f);
            atomicAdd(dst + 1, c.y * f);
            atomicAdd(dst + 2, c.z * f);
        }
    }
}

// ---------------- fused node kernel ----------------
// 128 nodes per CTA, 512 threads.
#define NODE_XS 261
#define NODE_SMEM ((128*261 + 128*133) * 4 + 128*4)

__global__ void __launch_bounds__(512, 1) node_kernel(
    const float* __restrict__ h, const float* __restrict__ coordg,
    const float* __restrict__ n_w1, const float* __restrict__ n_w2,
    const float* __restrict__ n_b2,
    const float* __restrict__ ap_w1, const float* __restrict__ ap_w2,
    float* __restrict__ out, int N)
{
    extern __shared__ float sm[];
    float* Xn   = sm;
    float* Yn   = Xn + 128 * NODE_XS;
    float* sES  = Yn + 128 * TILE_YS;

    const int tid = threadIdx.x;
    const int nb = blockIdx.x * 128;

    // ------- stage [h | agg] = 256 dims -------
    {
        const int el = tid & 127, part = tid >> 7;
        int n = nb + el;
        bool v = n < N;
        long nn = v ? (long)n : 0;
        const float4* hr = reinterpret_cast<const float4*>(h) + nn * 32 + part * 8;
        const float4* ar = reinterpret_cast<const float4*>(g_agg) + nn * 32 + part * 8;
        float* xr = Xn + el * NODE_XS + part * 32;
#pragma unroll
        for (int i = 0; i < 8; i++) {
            float4 a = v ? __ldg(hr + i) : make_float4(0.f, 0.f, 0.f, 0.f);
            xr[4*i+0] = a.x; xr[4*i+1] = a.y; xr[4*i+2] = a.z; xr[4*i+3] = a.w;
        }
#pragma unroll
        for (int i = 0; i < 8; i++) {
            float4 a = v ? ar[i] : make_float4(0.f, 0.f, 0.f, 0.f);
            xr[128+4*i+0] = a.x; xr[128+4*i+1] = a.y; xr[128+4*i+2] = a.z; xr[128+4*i+3] = a.w;
        }
    }
    __syncthreads();

    const int warp = tid >> 5, lane = tid & 31;
    const int e0 = (warp >> 2) * 32 + (lane >> 2) * 4;
    const int c0 = (warp & 3) * 32 + (lane & 3) * 8;

    UL acc[16];

    // ------- node GEMM1: [128 x 256] @ n_w1[0:256] + nb1_eff -> SiLU -------
    gemm_stream<256>(Xn, NODE_XS, n_w1, g_nb1, e0, c0, acc);
#pragma unroll
    for (int j = 0; j < 4; j++) {
        float* yr = Yn + (e0 + j) * TILE_YS + c0;
#pragma unroll
        for (int p = 0; p < 4; p++) {
            float2 f = up2(acc[j*4+p]);
            yr[2*p]   = silu_f(f.x);
            yr[2*p+1] = silu_f(f.y);
        }
    }
    __syncthreads();

    // ------- node GEMM2: @ n_w2 + n_b2 -> SiLU -> h_out = h + . -------
    gemm_stream<128>(Yn, TILE_YS, n_w2, n_b2, e0, c0, acc);
    __syncthreads();
#pragma unroll
    for (int j = 0; j < 4; j++) {
        int n = nb + e0 + j;
        float ho[8];
        const float* xh = Xn + (e0 + j) * NODE_XS + c0;
#pragma unroll
        for (int p = 0; p < 4; p++) {
            float2 f = up2(acc[j*4+p]);
            ho[2*p]   = silu_f(f.x) + xh[2*p];
            ho[2*p+1] = silu_f(f.y) + xh[2*p+1];
        }
        float* yr = Yn + (e0 + j) * TILE_YS + c0;
#pragma unroll
        for (int i = 0; i < 8; i++) yr[i] = ho[i];
        if (n < N) {
            float* o = out + (long)n * 128 + c0;
#pragma unroll
            for (int i = 0; i < 8; i++) o[i] = ho[i];
        }
    }
    if (tid < 128) sES[tid] = 0.0f;
    __syncthreads();

    // ------- acc-point MLP: h_out @ ap_w1[0:128] + apb1_eff -> SiLU -> dot ap_w2 -
    gemm_stream<128>(Yn, TILE_YS, ap_w1, g_apb1, e0, c0, acc);
    {
        float4 w0 = __ldg(reinterpret_cast<const float4*>(ap_w2 + c0));
        float4 w1 = __ldg(reinterpret_cast<const float4*>(ap_w2 + c0 + 4));
        float wv[8] = { w0.x, w0.y, w0.z, w0.w, w1.x, w1.y, w1.z, w1.w };
#pragma unroll
        for (int j = 0; j < 4; j++) {
            float p = 0.0f;
#pragma unroll
            for (int q = 0; q < 4; q++) {
                float2 f = up2(acc[j*4+q]);
                p += silu_f(f.x) * wv[2*q];
                p += silu_f(f.y) * wv[2*q+1];
            }
            p += __shfl_xor_sync(0xffffffffu, p, 1);
            p += __shfl_xor_sync(0xffffffffu, p, 2);
            if ((lane & 3) == 0) atomicAdd(&sES[e0 + j], p);
        }
    }
    __syncthreads();
    if (tid < 128) {
        int n = nb + tid;
        if (n < N) {
            float s = sES[tid];
            long base_c = (long)N * 128;
            long base_a = (long)N * 131;
            out[base_c + (long)n*3 + 0] = coordg[n*3+0];
            out[base_c + (long)n*3 + 1] = coordg[n*3+1];
            out[base_c + (long)n*3 + 2] = coordg[n*3+2];
            out[base_a + (long)n*3 + 0] = g_aggc[n*3+0] * s;
            out[base_a + (long)n*3 + 1] = g_aggc[n*3+1] * s;
            out[base_a + (long)n*3 + 2] = g_aggc[n*3+2] * s;
        }
    }
}

// ---------------- launch ----------------
extern "C" void kernel_launch(void* const* d_in, const int* in_sizes, int n_in,
                              void* d_out, int out_size)
{
    const float* h      = (const float*)d_in[0];
    const int*   ei     = (const int*)  d_in[1];
    const float* coord  = (const float*)d_in[2];
    const float* eattr  = (const float*)d_in[3];
    const float* prompt = (const float*)d_in[4];
    const float* e_w1   = (const float*)d_in[5];
    const float* e_b1   = (const float*)d_in[6];
    const float* e_w2   = (const float*)d_in[7];
    const float* e_b2   = (const float*)d_in[8];
    const float* n_w1   = (const float*)d_in[9];
    const float* n_b1   = (const float*)d_in[10];
    const float* n_w2   = (const float*)d_in[11];
    const float* n_b2   = (const float*)d_in[12];
    const float* ae_w1  = (const float*)d_in[13];
    const float* ae_b1  = (const float*)d_in[14];
    const float* ae_w2  = (const float*)d_in[15];
    const float* ap_w1  = (const float*)d_in[16];
    const float* ap_b1  = (const float*)d_in[17];
    const float* ap_w2  = (const float*)d_in[18];
    float* out = (float*)d_out;

    int N = in_sizes[0] / 128;
    int E = in_sizes[1] / 2;

    cudaFuncSetAttribute(edge_kernel, cudaFuncAttributeMaxDynamicSharedMemorySize, EDGE_SMEM);
    cudaFuncSetAttribute(node_kernel, cudaFuncAttributeMaxDynamicSharedMemorySize, NODE_SMEM);

    prep_kernel<<<1, 128>>>(prompt, e_w1, e_b1, n_w1, n_b1, ae_w1, ae_b1, ap_w1, ap_b1);
    zero_kernel<<<264, 256>>>(N);
    edge_kernel<<<(E + 127) / 128, 512, EDGE_SMEM>>>(h, ei, coord, eattr,
                                                     e_w1, e_w2, e_b2, ae_w1, ae_w2, E);
    node_kernel<<<(N + 127) / 128, 512, NODE_SMEM>>>(h, coord, n_w1, n_w2, n_b2,
                                                     ap_w1, ap_w2, out, N);
}

// round 5
// speedup vs baseline: 1.3206x; 1.1327x over previous
#include <cuda_runtime.h>

typedef unsigned long long UL;

// ---------------- device scratch (no allocations allowed) ----------------
__device__ float g_agg [50000 * 128];   // segment-sum of edge_feat per node
__device__ float g_aggc[50000 * 3];     // segment-sum of trans per node
__device__ float g_eb1 [128];           // e_b1  + prompt @ e_w1[273:401]
__device__ float g_nb1 [128];           // n_b1  + prompt @ n_w1[256:384]
__device__ float g_aeb1[128];           // ae_b1 + prompt @ ae_w1[128:256]
__device__ float g_apb1[128];           // ap_b1 + prompt @ ap_w1[128:256]

// ---------------- small helpers ----------------
__device__ __forceinline__ UL bc2(float x) {
    UL r; asm("mov.b64 %0,{%1,%1};" : "=l"(r) : "f"(x)); return r;
}
__device__ __forceinline__ UL pk2(float x, float y) {
    UL r; asm("mov.b64 %0,{%1,%2};" : "=l"(r) : "f"(x), "f"(y)); return r;
}
__device__ __forceinline__ float2 up2(UL v) {
    float2 f; asm("mov.b64 {%0,%1},%2;" : "=f"(f.x), "=f"(f.y) : "l"(v)); return f;
}
__device__ __forceinline__ void fma2(UL &d, UL a, UL b) {
    asm("fma.rn.f32x2 %0,%1,%2,%0;" : "+l"(d) : "l"(a), "l"(b));
}
__device__ __forceinline__ float silu_f(float x) {
    return __fdividef(x, 1.0f + __expf(-x));
}

// 16 packed FMAs for one k-row: 4 edge-rows x 4 col-pairs
#define FMAROW(WA, WB, S0, S1, S2, S3)                            \
    do {                                                          \
        fma2(acc[0],  S0, WA.x); fma2(acc[1],  S0, WA.y);         \
        fma2(acc[2],  S0, WB.x); fma2(acc[3],  S0, WB.y);         \
        fma2(acc[4],  S1, WA.x); fma2(acc[5],  S1, WA.y);         \
        fma2(acc[6],  S1, WB.x); fma2(acc[7],  S1, WB.y);         \
        fma2(acc[8],  S2, WA.x); fma2(acc[9],  S2, WA.y);         \
        fma2(acc[10], S2, WB.x); fma2(acc[11], S2, WB.y);         \
        fma2(acc[12], S3, WA.x); fma2(acc[13], S3, WA.y);         \
        fma2(acc[14], S3, WB.x); fma2(acc[15], S3, WB.y);         \
    } while (0)

// ---------------- register-tiled GEMM, weights streamed from L2 --------
// Xs: [tile][xs_stride] smem (odd stride -> conflict-free scalar loads).
// Wg: global row-major [K][128] (L2-resident, broadcast across CTAs).
// Thread owns 4 rows x 8 cols (4 f32x2 col-pairs per row) -> acc[16] u64.
// 4-slot rotating weight pipeline: consume row r, immediately reload the
// slot with row r+4 -> every LDG has ~3 rows (~380 contended cycles) of
// lookahead, covering the ~262cyc L2 latency.  One W row = 512 bytes.
template<int K>
__device__ __forceinline__ void gemm_stream(
    const float* Xs, int xs_stride,
    const float* __restrict__ Wg,
    const float* __restrict__ biasg,
    int e0, int c0, UL* acc)
{
    float4 b0 = __ldg(reinterpret_cast<const float4*>(biasg + c0));
    float4 b1 = __ldg(reinterpret_cast<const float4*>(biasg + c0 + 4));
    UL bp0 = pk2(b0.x, b0.y), bp1 = pk2(b0.z, b0.w);
    UL bp2 = pk2(b1.x, b1.y), bp3 = pk2(b1.z, b1.w);
#pragma unroll
    for (int j = 0; j < 4; j++) {
        acc[j*4+0] = bp0; acc[j*4+1] = bp1; acc[j*4+2] = bp2; acc[j*4+3] = bp3;
    }

    const float* x0 = Xs + (e0 + 0) * xs_stride;
    const float* x1 = Xs + (e0 + 1) * xs_stride;
    const float* x2 = Xs + (e0 + 2) * xs_stride;
    const float* x3 = Xs + (e0 + 3) * xs_stride;
    const char* wa = reinterpret_cast<const char*>(Wg + c0);
    const char* wb = reinterpret_cast<const char*>(Wg + c0 + 4);

    ulonglong2 A0 = __ldg(reinterpret_cast<const ulonglong2*>(wa));
    ulonglong2 B0 = __ldg(reinterpret_cast<const ulonglong2*>(wb));
    ulonglong2 A1 = __ldg(reinterpret_cast<const ulonglong2*>(wa + 512));
    ulonglong2 B1 = __ldg(reinterpret_cast<const ulonglong2*>(wb + 512));
    ulonglong2 A2 = __ldg(reinterpret_cast<const ulonglong2*>(wa + 1024));
    ulonglong2 B2 = __ldg(reinterpret_cast<const ulonglong2*>(wb + 1024));
    ulonglong2 A3 = __ldg(reinterpret_cast<const ulonglong2*>(wa + 1536));
    ulonglong2 B3 = __ldg(reinterpret_cast<const ulonglong2*>(wb + 1536));

    constexpr int KM = K & ~3;   // main loop consumes rows 0..KM-1

    for (int k = 0; k < KM; k += 4) {
        {   // row k  (slot 0), reload slot with row k+4
            UL s0 = bc2(x0[k]), s1 = bc2(x1[k]), s2 = bc2(x2[k]), s3 = bc2(x3[k]);
            FMAROW(A0, B0, s0, s1, s2, s3);
            long off = (long)((k + 4 < K) ? (k + 4) : (K - 1)) << 9;
            A0 = __ldg(reinterpret_cast<const ulonglong2*>(wa + off));
            B0 = __ldg(reinterpret_cast<const ulonglong2*>(wb + off));
        }
        {   // row k+1 (slot 1)
            UL s0 = bc2(x0[k+1]), s1 = bc2(x1[k+1]), s2 = bc2(x2[k+1]), s3 = bc2(x3[k+1]);
            FMAROW(A1, B1, s0, s1, s2, s3);
            long off = (long)((k + 5 < K) ? (k + 5) : (K - 1)) << 9;
            A1 = __ldg(reinterpret_cast<const ulonglong2*>(wa + off));
            B1 = __ldg(reinterpret_cast<const ulonglong2*>(wb + off));
        }
        {   // row k+2 (slot 2)
            UL s0 = bc2(x0[k+2]), s1 = bc2(x1[k+2]), s2 = bc2(x2[k+2]), s3 = bc2(x3[k+2]);
            FMAROW(A2, B2, s0, s1, s2, s3);
            long off = (long)((k + 6 < K) ? (k + 6) : (K - 1)) << 9;
            A2 = __ldg(reinterpret_cast<const ulonglong2*>(wa + off));
            B2 = __ldg(reinterpret_cast<const ulonglong2*>(wb + off));
        }
        {   // row k+3 (slot 3)
            UL s0 = bc2(x0[k+3]), s1 = bc2(x1[k+3]), s2 = bc2(x2[k+3]), s3 = bc2(x3[k+3]);
            FMAROW(A3, B3, s0, s1, s2, s3);
            long off = (long)((k + 7 < K) ? (k + 7) : (K - 1)) << 9;
            A3 = __ldg(reinterpret_cast<const ulonglong2*>(wa + off));
            B3 = __ldg(reinterpret_cast<const ulonglong2*>(wb + off));
        }
    }
    // tail rows KM..K-1 (<=3): slot t holds row KM+t after the rotation
    if (K - KM >= 1) {
        UL s0 = bc2(x0[KM]), s1 = bc2(x1[KM]), s2 = bc2(x2[KM]), s3 = bc2(x3[KM]);
        FMAROW(A0, B0, s0, s1, s2, s3);
    }
    if (K - KM >= 2) {
        UL s0 = bc2(x0[KM+1]), s1 = bc2(x1[KM+1]), s2 = bc2(x2[KM+1]), s3 = bc2(x3[KM+1]);
        FMAROW(A1, B1, s0, s1, s2, s3);
    }
    if (K - KM >= 3) {
        UL s0 = bc2(x0[KM+2]), s1 = bc2(x1[KM+2]), s2 = bc2(x2[KM+2]), s3 = bc2(x3[KM+2]);
        FMAROW(A2, B2, s0, s1, s2, s3);
    }
}

// ---------------- prompt-bias precompute (4 blocks, one per bias) -------
__global__ void prep_kernel(
    const float* __restrict__ prompt,
    const float* __restrict__ e_w1,  const float* __restrict__ e_b1,
    const float* __restrict__ n_w1,  const float* __restrict__ n_b1,
    const float* __restrict__ ae_w1, const float* __restrict__ ae_b1,
    const float* __restrict__ ap_w1, const float* __restrict__ ap_b1)
{
    int n = threadIdx.x;  // 128 threads
    int b = blockIdx.x;
    const float* w; const float* bias; float* dst; int off;
    if (b == 0)      { w = e_w1;  bias = e_b1;  dst = g_eb1;  off = 273; }
    else if (b == 1) { w = n_w1;  bias = n_b1;  dst = g_nb1;  off = 256; }
    else if (b == 2) { w = ae_w1; bias = ae_b1; dst = g_aeb1; off = 128; }
    else             { w = ap_w1; bias = ap_b1; dst = g_apb1; off = 128; }
    float s = bias[n];
    for (int j = 0; j < 128; j++)
        s = fmaf(prompt[j], w[(off + j) * 128 + n], s);
    dst[n] = s;
}

// ---------------- zero scratch ----------------
__global__ void zero_kernel(int N)
{
    long stride = (long)gridDim.x * blockDim.x;
    long t1 = (long)N * 128;
    for (long i = blockIdx.x * (long)blockDim.x + threadIdx.x; i < t1; i += stride)
        g_agg[i] = 0.0f;
    long t2 = (long)N * 3;
    for (long i = blockIdx.x * (long)blockDim.x + threadIdx.x; i < t2; i += stride)
        g_aggc[i] = 0.0f;
}

// ---------------- fused edge kernel ----------------
// 128 edges per CTA, 512 threads, 16 warps.
#define EDGE_XS 277
#define TILE_YS 133
#define EDGE_SMEM ((128*277 + 128*133) * 4 + 128*16 + 128*4 + 128*4)

__global__ void __launch_bounds__(512, 1) edge_kernel(
    const float* __restrict__ h, const int* __restrict__ ei,
    const float* __restrict__ coord, const float* __restrict__ eattr,
    const float* __restrict__ e_w1, const float* __restrict__ e_w2,
    const float* __restrict__ e_b2,
    const float* __restrict__ ae_w1, const float* __restrict__ ae_w2,
    int E)
{
    extern __shared__ float sm[];
    float*  Xs   = sm;
    float*  Ys   = Xs + 128 * EDGE_XS;
    float4* cd   = reinterpret_cast<float4*>(Ys + 128 * TILE_YS);
    float*  sES  = reinterpret_cast<float*>(cd + 128);
    int*    rowi = reinterpret_cast<int*>(sES + 128);

    const int tid = threadIdx.x;
    const int e_base = blockIdx.x * 128;
    const int* rowg = ei;
    const int* colg = ei + E;

    // ------- stage X tile: [h[row] | h[col] | radial | edge_attr] = 273 dims ----
    {
        const int el = tid & 127, part = tid >> 7;   // 4 parts of 32 floats
        int e = e_base + el;
        bool v = e < E;
        long r = v ? (long)rowg[e] : 0;
        long c = v ? (long)colg[e] : 0;
        const float4* hr = reinterpret_cast<const float4*>(h) + r * 32 + part * 8;
        const float4* hc = reinterpret_cast<const float4*>(h) + c * 32 + part * 8;
        float* xr = Xs + el * EDGE_XS + part * 32;
#pragma unroll
        for (int i = 0; i < 8; i++) {
            float4 a = v ? __ldg(hr + i) : make_float4(0.f, 0.f, 0.f, 0.f);
            xr[4*i+0] = a.x; xr[4*i+1] = a.y; xr[4*i+2] = a.z; xr[4*i+3] = a.w;
        }
#pragma unroll
        for (int i = 0; i < 8; i++) {
            float4 b = v ? __ldg(hc + i) : make_float4(0.f, 0.f, 0.f, 0.f);
            xr[128+4*i+0] = b.x; xr[128+4*i+1] = b.y; xr[128+4*i+2] = b.z; xr[128+4*i+3] = b.w;
        }
        if (part == 0) {
            rowi[el] = (int)r;
            float dx = 0.f, dy = 0.f, dz = 0.f;
            if (v) {
                dx = coord[r*3+0] - coord[c*3+0];
                dy = coord[r*3+1] - coord[c*3+1];
                dz = coord[r*3+2] - coord[c*3+2];
            }
            float rad = dx*dx + dy*dy + dz*dz;
            Xs[el * EDGE_XS + 256] = rad;
            float inv = 1.0f / fmaxf(sqrtf(rad), 1e-12f);
            cd[el] = make_float4(dx, dy, dz, inv);
        } else if (part == 1) {
            const float4* ea = reinterpret_cast<const float4*>(eattr) + (long)e * 4;
#pragma unroll
            for (int i = 0; i < 4; i++) {
                float4 a = v ? __ldg(ea + i) : make_float4(0.f, 0.f, 0.f, 0.f);
                float* xq = Xs + el * EDGE_XS + 257 + 4 * i;
                xq[0] = a.x; xq[1] = a.y; xq[2] = a.z; xq[3] = a.w;
            }
        }
    }
    __syncthreads();

    const int warp = tid >> 5, lane = tid & 31;
    const int e0 = (warp >> 2) * 32 + (lane >> 2) * 4;
    const int c0 = (warp & 3) * 32 + (lane & 3) * 8;

    UL acc[16];

    // ------- GEMM1: [128 x 273] @ e_w1[0:273] + eb1_eff -> SiLU -> Ys -------
    gemm_stream<273>(Xs, EDGE_XS, e_w1, g_eb1, e0, c0, acc);
#pragma unroll
    for (int j = 0; j < 4; j++) {
        float* yr = Ys + (e0 + j) * TILE_YS + c0;
#pragma unroll
        for (int p = 0; p < 4; p++) {
            float2 f = up2(acc[j*4+p]);
            yr[2*p]   = silu_f(f.x);
            yr[2*p+1] = silu_f(f.y);
        }
    }
    __syncthreads();

    // ------- GEMM2: [128 x 128] @ e_w2 + e_b2 -> SiLU = edge_feat -------
    gemm_stream<128>(Ys, TILE_YS, e_w2, e_b2, e0, c0, acc);
    __syncthreads();  // all warps done reading Ys before overwrite
#pragma unroll
    for (int j = 0; j < 4; j++) {
        float z[8];
#pragma unroll
        for (int p = 0; p < 4; p++) {
            float2 f = up2(acc[j*4+p]);
            z[2*p] = silu_f(f.x); z[2*p+1] = silu_f(f.y);
        }
        float* yr = Ys + (e0 + j) * TILE_YS + c0;
#pragma unroll
        for (int i = 0; i < 8; i++) yr[i] = z[i];
        int eg = e_base + e0 + j;
        if (eg < E) {
            float* dst = g_agg + (long)rowi[e0 + j] * 128 + c0;
            atomicAdd(reinterpret_cast<float4*>(dst),
                      make_float4(z[0], z[1], z[2], z[3]));
            atomicAdd(reinterpret_cast<float4*>(dst + 4),
                      make_float4(z[4], z[5], z[6], z[7]));
        }
    }
    if (tid < 128) sES[tid] = 0.0f;
    __syncthreads();

    // ------- GEMM3: edge_feat @ ae_w1[0:128] + aeb1_eff -> SiLU -> dot ae_w2 ---
    gemm_stream<128>(Ys, TILE_YS, ae_w1, g_aeb1, e0, c0, acc);
    {
        float4 w0 = __ldg(reinterpret_cast<const float4*>(ae_w2 + c0));
        float4 w1 = __ldg(reinterpret_cast<const float4*>(ae_w2 + c0 + 4));
        float wv[8] = { w0.x, w0.y, w0.z, w0.w, w1.x, w1.y, w1.z, w1.w };
#pragma unroll
        for (int j = 0; j < 4; j++) {
            float p = 0.0f;
#pragma unroll
            for (int q = 0; q < 4; q++) {
                float2 f = up2(acc[j*4+q]);
                p += silu_f(f.x) * wv[2*q];
                p += silu_f(f.y) * wv[2*q+1];
            }
            p += __shfl_xor_sync(0xffffffffu, p, 1);
            p += __shfl_xor_sync(0xffffffffu, p, 2);
            if ((lane & 3) == 0) atomicAdd(&sES[e0 + j], p);
        }
    }
    __syncthreads();
    if (tid < 128) {
        int eg = e_base + tid;
        if (eg < E) {
            float s = sES[tid];
            float4 c = cd[tid];
            float f = s * c.w;  // phi(e) / max(||d||,1e-12)
            float* dst = g_aggc + (long)rowi[tid] * 3;
            atomicAdd(dst + 0, c.x * f);
            atomicAdd(dst + 1, c.y * f);
            atomicAdd(dst + 2, c.z * f);
        }
    }
}

// ---------------- fused node kernel ----------------
// 128 nodes per CTA, 512 threads.
#define NODE_XS 261
#define NODE_SMEM ((128*261 + 128*133) * 4 + 128*4)

__global__ void __launch_bounds__(512, 1) node_kernel(
    const float* __restrict__ h, const float* __restrict__ coordg,
    const float* __restrict__ n_w1, const float* __restrict__ n_w2,
    const float* __restrict__ n_b2,
    const float* __restrict__ ap_w1, const float* __restrict__ ap_w2,
    float* __restrict__ out, int N)
{
    extern __shared__ float sm[];
    float* Xn   = sm;
    float* Yn   = Xn + 128 * NODE_XS;
    float* sES  = Yn + 128 * TILE_YS;

    const int tid = threadIdx.x;
    const int nb = blockIdx.x * 128;

    // ------- stage [h | agg] = 256 dims -------
    {
        const int el = tid & 127, part = tid >> 7;
        int n = nb + el;
        bool v = n < N;
        long nn = v ? (long)n : 0;
        const float4* hr = reinterpret_cast<const float4*>(h) + nn * 32 + part * 8;
        const float4* ar = reinterpret_cast<const float4*>(g_agg) + nn * 32 + part * 8;
        float* xr = Xn + el * NODE_XS + part * 32;
#pragma unroll
        for (int i = 0; i < 8; i++) {
            float4 a = v ? __ldg(hr + i) : make_float4(0.f, 0.f, 0.f, 0.f);
            xr[4*i+0] = a.x; xr[4*i+1] = a.y; xr[4*i+2] = a.z; xr[4*i+3] = a.w;
        }
#pragma unroll
        for (int i = 0; i < 8; i++) {
            float4 a = v ? ar[i] : make_float4(0.f, 0.f, 0.f, 0.f);
            xr[128+4*i+0] = a.x; xr[128+4*i+1] = a.y; xr[128+4*i+2] = a.z; xr[128+4*i+3] = a.w;
        }
    }
    __syncthreads();

    const int warp = tid >> 5, lane = tid & 31;
    const int e0 = (warp >> 2) * 32 + (lane >> 2) * 4;
    const int c0 = (warp & 3) * 32 + (lane & 3) * 8;

    UL acc[16];

    // ------- node GEMM1: [128 x 256] @ n_w1[0:256] + nb1_eff -> SiLU -------
    gemm_stream<256>(Xn, NODE_XS, n_w1, g_nb1, e0, c0, acc);
#pragma unroll
    for (int j = 0; j < 4; j++) {
        float* yr = Yn + (e0 + j) * TILE_YS + c0;
#pragma unroll
        for (int p = 0; p < 4; p++) {
            float2 f = up2(acc[j*4+p]);
            yr[2*p]   = silu_f(f.x);
            yr[2*p+1] = silu_f(f.y);
        }
    }
    __syncthreads();

    // ------- node GEMM2: @ n_w2 + n_b2 -> SiLU -> h_out = h + . -------
    gemm_stream<128>(Yn, TILE_YS, n_w2, n_b2, e0, c0, acc);
    __syncthreads();
#pragma unroll
    for (int j = 0; j < 4; j++) {
        int n = nb + e0 + j;
        float ho[8];
        const float* xh = Xn + (e0 + j) * NODE_XS + c0;
#pragma unroll
        for (int p = 0; p < 4; p++) {
            float2 f = up2(acc[j*4+p]);
            ho[2*p]   = silu_f(f.x) + xh[2*p];
            ho[2*p+1] = silu_f(f.y) + xh[2*p+1];
        }
        float* yr = Yn + (e0 + j) * TILE_YS + c0;
#pragma unroll
        for (int i = 0; i < 8; i++) yr[i] = ho[i];
        if (n < N) {
            float* o = out + (long)n * 128 + c0;
#pragma unroll
            for (int i = 0; i < 8; i++) o[i] = ho[i];
        }
    }
    if (tid < 128) sES[tid] = 0.0f;
    __syncthreads();

    // ------- acc-point MLP: h_out @ ap_w1[0:128] + apb1_eff -> SiLU -> dot ap_w2 -
    gemm_stream<128>(Yn, TILE_YS, ap_w1, g_apb1, e0, c0, acc);
    {
        float4 w0 = __ldg(reinterpret_cast<const float4*>(ap_w2 + c0));
        float4 w1 = __ldg(reinterpret_cast<const float4*>(ap_w2 + c0 + 4));
        float wv[8] = { w0.x, w0.y, w0.z, w0.w, w1.x, w1.y, w1.z, w1.w };
#pragma unroll
        for (int j = 0; j < 4; j++) {
            float p = 0.0f;
#pragma unroll
            for (int q = 0; q < 4; q++) {
                float2 f = up2(acc[j*4+q]);
                p += silu_f(f.x) * wv[2*q];
                p += silu_f(f.y) * wv[2*q+1];
            }
            p += __shfl_xor_sync(0xffffffffu, p, 1);
            p += __shfl_xor_sync(0xffffffffu, p, 2);
            if ((lane & 3) == 0) atomicAdd(&sES[e0 + j], p);
        }
    }
    __syncthreads();
    if (tid < 128) {
        int n = nb + tid;
        if (n < N) {
            float s = sES[tid];
            long base_c = (long)N * 128;
            long base_a = (long)N * 131;
            out[base_c + (long)n*3 + 0] = coordg[n*3+0];
            out[base_c + (long)n*3 + 1] = coordg[n*3+1];
            out[base_c + (long)n*3 + 2] = coordg[n*3+2];
            out[base_a + (long)n*3 + 0] = g_aggc[n*3+0] * s;
            out[base_a + (long)n*3 + 1] = g_aggc[n*3+1] * s;
            out[base_a + (long)n*3 + 2] = g_aggc[n*3+2] * s;
        }
    }
}

// ---------------- launch ----------------
extern "C" void kernel_launch(void* const* d_in, const int* in_sizes, int n_in,
                              void* d_out, int out_size)
{
    const float* h      = (const float*)d_in[0];
    const int*   ei     = (const int*)  d_in[1];
    const float* coord  = (const float*)d_in[2];
    const float* eattr  = (const float*)d_in[3];
    const float* prompt = (const float*)d_in[4];
    const float* e_w1   = (const float*)d_in[5];
    const float* e_b1   = (const float*)d_in[6];
    const float* e_w2   = (const float*)d_in[7];
    const float* e_b2   = (const float*)d_in[8];
    const float* n_w1   = (const float*)d_in[9];
    const float* n_b1   = (const float*)d_in[10];
    const float* n_w2   = (const float*)d_in[11];
    const float* n_b2   = (const float*)d_in[12];
    const float* ae_w1  = (const float*)d_in[13];
    const float* ae_b1  = (const float*)d_in[14];
    const float* ae_w2  = (const float*)d_in[15];
    const float* ap_w1  = (const float*)d_in[16];
    const float* ap_b1  = (const float*)d_in[17];
    const float* ap_w2  = (const float*)d_in[18];
    float* out = (float*)d_out;

    int N = in_sizes[0] / 128;
    int E = in_sizes[1] / 2;

    cudaFuncSetAttribute(edge_kernel, cudaFuncAttributeMaxDynamicSharedMemorySize, EDGE_SMEM);
    cudaFuncSetAttribute(node_kernel, cudaFuncAttributeMaxDynamicSharedMemorySize, NODE_SMEM);

    prep_kernel<<<4, 128>>>(prompt, e_w1, e_b1, n_w1, n_b1, ae_w1, ae_b1, ap_w1, ap_b1);
    zero_kernel<<<264, 256>>>(N);
    edge_kernel<<<(E + 127) / 128, 512, EDGE_SMEM>>>(h, ei, coord, eattr,
                                                     e_w1, e_w2, e_b2, ae_w1, ae_w2, E);
    node_kernel<<<(N + 127) / 128, 512, NODE_SMEM>>>(h, coord, n_w1, n_w2, n_b2,
                                                     ap_w1, ap_w2, out, N);
}

// round 6
// speedup vs baseline: 1.3372x; 1.0126x over previous
#include <cuda_runtime.h>

typedef unsigned long long UL;

// ---------------- device scratch (no allocations allowed) ----------------
__device__ float g_agg [50000 * 128];   // segment-sum of edge_feat per node
__device__ float g_aggc[50000 * 3];     // segment-sum of trans per node
__device__ float g_eb1 [128];           // e_b1  + prompt @ e_w1[273:401]
__device__ float g_nb1 [128];           // n_b1  + prompt @ n_w1[256:384]
__device__ float g_aeb1[128];           // ae_b1 + prompt @ ae_w1[128:256]
__device__ float g_apb1[128];           // ap_b1 + prompt @ ap_w1[128:256]

// ---------------- small helpers ----------------
__device__ __forceinline__ UL bc2(float x) {
    UL r; asm("mov.b64 %0,{%1,%1};" : "=l"(r) : "f"(x)); return r;
}
__device__ __forceinline__ UL pk2(float x, float y) {
    UL r; asm("mov.b64 %0,{%1,%2};" : "=l"(r) : "f"(x), "f"(y)); return r;
}
__device__ __forceinline__ float2 up2(UL v) {
    float2 f; asm("mov.b64 {%0,%1},%2;" : "=f"(f.x), "=f"(f.y) : "l"(v)); return f;
}
__device__ __forceinline__ void fma2(UL &d, UL a, UL b) {
    asm("fma.rn.f32x2 %0,%1,%2,%0;" : "+l"(d) : "l"(a), "l"(b));
}
__device__ __forceinline__ float silu_f(float x) {
    return __fdividef(x, 1.0f + __expf(-x));
}
__device__ __forceinline__ void cpa16(unsigned dst, const float* src) {
    asm volatile("cp.async.cg.shared.global [%0], [%1], 16;" :: "r"(dst), "l"(src));
}
#define CPA_COMMIT() asm volatile("cp.async.commit_group;" ::: "memory")

// 16 packed FMAs for one k-row: 4 edge-rows x 4 col-pairs
#define FMAROW(WA, WB, S0, S1, S2, S3)                            \
    do {                                                          \
        fma2(acc[0],  S0, WA.x); fma2(acc[1],  S0, WA.y);         \
        fma2(acc[2],  S0, WB.x); fma2(acc[3],  S0, WB.y);         \
        fma2(acc[4],  S1, WA.x); fma2(acc[5],  S1, WA.y);         \
        fma2(acc[6],  S1, WB.x); fma2(acc[7],  S1, WB.y);         \
        fma2(acc[8],  S2, WA.x); fma2(acc[9],  S2, WA.y);         \
        fma2(acc[10], S2, WB.x); fma2(acc[11], S2, WB.y);         \
        fma2(acc[12], S3, WA.x); fma2(acc[13], S3, WA.y);         \
        fma2(acc[14], S3, WB.x); fma2(acc[15], S3, WB.y);         \
    } while (0)

// ---------------- GEMM with cp.async double-buffered smem weights -------
// Xs: [tile][xs_stride] smem (odd stride -> conflict-free scalar loads).
// Wg: global row-major [K_alloc>=ceil16(K)][128]. Weights staged through
// Wbuf[2][16*128] in 16-row chunks: one cp.async.16 per thread per chunk,
// committed a full chunk (~2000 cyc) ahead of consumption.
// Thread owns 4 rows x 8 cols (4 f32x2 col-pairs per row) -> acc[16] u64.
template<int K>
__device__ __forceinline__ void gemm_smem(
    const float* Xs, int xs_stride,
    const float* __restrict__ Wg,
    const float* __restrict__ biasg,
    float* Wbuf, int tid, int e0, int c0, UL* acc)
{
    float4 b0 = __ldg(reinterpret_cast<const float4*>(biasg + c0));
    float4 b1 = __ldg(reinterpret_cast<const float4*>(biasg + c0 + 4));
    UL bp0 = pk2(b0.x, b0.y), bp1 = pk2(b0.z, b0.w);
    UL bp2 = pk2(b1.x, b1.y), bp3 = pk2(b1.z, b1.w);
#pragma unroll
    for (int j = 0; j < 4; j++) {
        acc[j*4+0] = bp0; acc[j*4+1] = bp1; acc[j*4+2] = bp2; acc[j*4+3] = bp3;
    }

    constexpr int CH = (K + 15) / 16;   // chunks of 16 k-rows

    // per-thread staging slot: row = tid/32 (0..15), 4 floats at (tid%32)*4
    const int srow = tid >> 5;
    const int scol = (tid & 31) * 4;
    const float* src = Wg + srow * 128 + scol;
    unsigned dstb = (unsigned)__cvta_generic_to_shared(Wbuf) + (srow * 128 + scol) * 4;

    cpa16(dstb, src);            // stage chunk 0 -> buf 0
    CPA_COMMIT();

    const float* x0 = Xs + (e0 + 0) * xs_stride;
    const float* x1 = Xs + (e0 + 1) * xs_stride;
    const float* x2 = Xs + (e0 + 2) * xs_stride;
    const float* x3 = Xs + (e0 + 3) * xs_stride;

    for (int c = 0; c < CH; c++) {
        if (c + 1 < CH) {
            cpa16(dstb + ((c + 1) & 1) * 8192, src + (c + 1) * 16 * 128);
            CPA_COMMIT();
            asm volatile("cp.async.wait_group 1;" ::: "memory");
        } else {
            asm volatile("cp.async.wait_group 0;" ::: "memory");
        }
        __syncthreads();

        const float* wb = Wbuf + (c & 1) * 2048 + c0;
        const int kb = c * 16;
        if (kb + 16 <= K) {
#pragma unroll
            for (int kk = 0; kk < 16; kk++) {
                int k = kb + kk;
                UL s0 = bc2(x0[k]), s1 = bc2(x1[k]), s2 = bc2(x2[k]), s3 = bc2(x3[k]);
                ulonglong2 a = *reinterpret_cast<const ulonglong2*>(wb + kk * 128);
                ulonglong2 b = *reinterpret_cast<const ulonglong2*>(wb + kk * 128 + 4);
                FMAROW(a, b, s0, s1, s2, s3);
            }
        } else {
            for (int kk = 0; kk < K - kb; kk++) {
                int k = kb + kk;
                UL s0 = bc2(x0[k]), s1 = bc2(x1[k]), s2 = bc2(x2[k]), s3 = bc2(x3[k]);
                ulonglong2 a = *reinterpret_cast<const ulonglong2*>(wb + kk * 128);
                ulonglong2 b = *reinterpret_cast<const ulonglong2*>(wb + kk * 128 + 4);
                FMAROW(a, b, s0, s1, s2, s3);
            }
        }
        __syncthreads();
    }
}

// ---------------- prompt-bias precompute (4 blocks, one per bias) -------
__global__ void prep_kernel(
    const float* __restrict__ prompt,
    const float* __restrict__ e_w1,  const float* __restrict__ e_b1,
    const float* __restrict__ n_w1,  const float* __restrict__ n_b1,
    const float* __restrict__ ae_w1, const float* __restrict__ ae_b1,
    const float* __restrict__ ap_w1, const float* __restrict__ ap_b1)
{
    int n = threadIdx.x;  // 128 threads
    int b = blockIdx.x;
    const float* w; const float* bias; float* dst; int off;
    if (b == 0)      { w = e_w1;  bias = e_b1;  dst = g_eb1;  off = 273; }
    else if (b == 1) { w = n_w1;  bias = n_b1;  dst = g_nb1;  off = 256; }
    else if (b == 2) { w = ae_w1; bias = ae_b1; dst = g_aeb1; off = 128; }
    else             { w = ap_w1; bias = ap_b1; dst = g_apb1; off = 128; }
    float s = bias[n];
    for (int j = 0; j < 128; j++)
        s = fmaf(prompt[j], w[(off + j) * 128 + n], s);
    dst[n] = s;
}

// ---------------- zero scratch ----------------
__global__ void zero_kernel(int N)
{
    long stride = (long)gridDim.x * blockDim.x;
    long t1 = (long)N * 128;
    for (long i = blockIdx.x * (long)blockDim.x + threadIdx.x; i < t1; i += stride)
        g_agg[i] = 0.0f;
    long t2 = (long)N * 3;
    for (long i = blockIdx.x * (long)blockDim.x + threadIdx.x; i < t2; i += stride)
        g_aggc[i] = 0.0f;
}

// ---------------- fused edge kernel ----------------
// 128 edges per CTA, 512 threads, 16 warps.
// smem (floats): Xs[128*277]=35456 | Ys[128*129]=16512 | Wbuf[2*16*128]=4096
//              | cd[128*4]=512 | sES[128] | rowi[128]  -> 56832 f = 227328 B
#define EDGE_XS 277
#define TILE_YS 129
#define EDGE_SMEM 227328

__global__ void __launch_bounds__(512, 1) edge_kernel(
    const float* __restrict__ h, const int* __restrict__ ei,
    const float* __restrict__ coord, const float* __restrict__ eattr,
    const float* __restrict__ e_w1, const float* __restrict__ e_w2,
    const float* __restrict__ e_b2,
    const float* __restrict__ ae_w1, const float* __restrict__ ae_w2,
    int E)
{
    extern __shared__ float sm[];
    float*  Xs   = sm;                               // 35456
    float*  Ys   = Xs + 128 * EDGE_XS;               // 16512
    float*  Wbuf = Ys + 128 * TILE_YS;               // 4096
    float4* cd   = reinterpret_cast<float4*>(Wbuf + 4096);   // 512 f
    float*  sES  = reinterpret_cast<float*>(cd + 128);       // 128
    int*    rowi = reinterpret_cast<int*>(sES + 128);        // 128

    const int tid = threadIdx.x;
    const int e_base = blockIdx.x * 128;
    const int* rowg = ei;
    const int* colg = ei + E;

    // ------- stage X tile: [h[row] | h[col] | radial | edge_attr] = 273 dims ----
    {
        const int el = tid & 127, part = tid >> 7;   // 4 parts of 32 floats
        int e = e_base + el;
        bool v = e < E;
        long r = v ? (long)rowg[e] : 0;
        long c = v ? (long)colg[e] : 0;
        const float4* hr = reinterpret_cast<const float4*>(h) + r * 32 + part * 8;
        const float4* hc = reinterpret_cast<const float4*>(h) + c * 32 + part * 8;
        float* xr = Xs + el * EDGE_XS + part * 32;
#pragma unroll
        for (int i = 0; i < 8; i++) {
            float4 a = v ? __ldg(hr + i) : make_float4(0.f, 0.f, 0.f, 0.f);
            xr[4*i+0] = a.x; xr[4*i+1] = a.y; xr[4*i+2] = a.z; xr[4*i+3] = a.w;
        }
#pragma unroll
        for (int i = 0; i < 8; i++) {
            float4 b = v ? __ldg(hc + i) : make_float4(0.f, 0.f, 0.f, 0.f);
            xr[128+4*i+0] = b.x; xr[128+4*i+1] = b.y; xr[128+4*i+2] = b.z; xr[128+4*i+3] = b.w;
        }
        if (part == 0) {
            rowi[el] = (int)r;
            float dx = 0.f, dy = 0.f, dz = 0.f;
            if (v) {
                dx = coord[r*3+0] - coord[c*3+0];
                dy = coord[r*3+1] - coord[c*3+1];
                dz = coord[r*3+2] - coord[c*3+2];
            }
            float rad = dx*dx + dy*dy + dz*dz;
            Xs[el * EDGE_XS + 256] = rad;
            float inv = 1.0f / fmaxf(sqrtf(rad), 1e-12f);
            cd[el] = make_float4(dx, dy, dz, inv);
        } else if (part == 1) {
            const float4* ea = reinterpret_cast<const float4*>(eattr) + (long)e * 4;
#pragma unroll
            for (int i = 0; i < 4; i++) {
                float4 a = v ? __ldg(ea + i) : make_float4(0.f, 0.f, 0.f, 0.f);
                float* xq = Xs + el * EDGE_XS + 257 + 4 * i;
                xq[0] = a.x; xq[1] = a.y; xq[2] = a.z; xq[3] = a.w;
            }
        }
    }
    // Xs visibility is guaranteed by the first __syncthreads inside gemm_smem

    const int warp = tid >> 5, lane = tid & 31;
    const int e0 = (warp >> 2) * 32 + (lane >> 2) * 4;
    const int c0 = (warp & 3) * 32 + (lane & 3) * 8;

    UL acc[16];

    // ------- GEMM1: [128 x 273] @ e_w1[0:273] + eb1_eff -> SiLU -> Ys -------
    // (tail chunk stages e_w1 rows 273..287 which exist: e_w1 has 401 rows)
    gemm_smem<273>(Xs, EDGE_XS, e_w1, g_eb1, Wbuf, tid, e0, c0, acc);
#pragma unroll
    for (int j = 0; j < 4; j++) {
        float* yr = Ys + (e0 + j) * TILE_YS + c0;
#pragma unroll
        for (int p = 0; p < 4; p++) {
            float2 f = up2(acc[j*4+p]);
            yr[2*p]   = silu_f(f.x);
            yr[2*p+1] = silu_f(f.y);
        }
    }

    // ------- GEMM2: [128 x 128] @ e_w2 + e_b2 -> SiLU = edge_feat -------
    gemm_smem<128>(Ys, TILE_YS, e_w2, e_b2, Wbuf, tid, e0, c0, acc);
    // last internal sync of gemm_smem ordered every warp's reads; safe to overwrite Ys
#pragma unroll
    for (int j = 0; j < 4; j++) {
        float z[8];
#pragma unroll
        for (int p = 0; p < 4; p++) {
            float2 f = up2(acc[j*4+p]);
            z[2*p] = silu_f(f.x); z[2*p+1] = silu_f(f.y);
        }
        float* yr = Ys + (e0 + j) * TILE_YS + c0;
#pragma unroll
        for (int i = 0; i < 8; i++) yr[i] = z[i];
        int eg = e_base + e0 + j;
        if (eg < E) {
            float* dst = g_agg + (long)rowi[e0 + j] * 128 + c0;
            atomicAdd(reinterpret_cast<float4*>(dst),
                      make_float4(z[0], z[1], z[2], z[3]));
            atomicAdd(reinterpret_cast<float4*>(dst + 4),
                      make_float4(z[4], z[5], z[6], z[7]));
        }
    }
    if (tid < 128) sES[tid] = 0.0f;

    // ------- GEMM3: edge_feat @ ae_w1[0:128] + aeb1_eff -> SiLU -> dot ae_w2 ---
    gemm_smem<128>(Ys, TILE_YS, ae_w1, g_aeb1, Wbuf, tid, e0, c0, acc);
    {
        float4 w0 = __ldg(reinterpret_cast<const float4*>(ae_w2 + c0));
        float4 w1 = __ldg(reinterpret_cast<const float4*>(ae_w2 + c0 + 4));
        float wv[8] = { w0.x, w0.y, w0.z, w0.w, w1.x, w1.y, w1.z, w1.w };
#pragma unroll
        for (int j = 0; j < 4; j++) {
            float p = 0.0f;
#pragma unroll
            for (int q = 0; q < 4; q++) {
                float2 f = up2(acc[j*4+q]);
                p += silu_f(f.x) * wv[2*q];
                p += silu_f(f.y) * wv[2*q+1];
            }
            p += __shfl_xor_sync(0xffffffffu, p, 1);
            p += __shfl_xor_sync(0xffffffffu, p, 2);
            if ((lane & 3) == 0) atomicAdd(&sES[e0 + j], p);
        }
    }
    __syncthreads();
    if (tid < 128) {
        int eg = e_base + tid;
        if (eg < E) {
            float s = sES[tid];
            float4 c = cd[tid];
            float f = s * c.w;  // phi(e) / max(||d||,1e-12)
            float* dst = g_aggc + (long)rowi[tid] * 3;
            atomicAdd(dst + 0, c.x * f);
            atomicAdd(dst + 1, c.y * f);
            atomicAdd(dst + 2, c.z * f);
        }
    }
}

// ---------------- fused node kernel ----------------
// 128 nodes per CTA, 512 threads.
// smem: Xn[128*261]=33408 | Yn[128*129]=16512 | Wbuf 4096 | sES 128 -> 216576 B
#define NODE_XS 261
#define NODE_SMEM 216576

__global__ void __launch_bounds__(512, 1) node_kernel(
    const float* __restrict__ h, const float* __restrict__ coordg,
    const float* __restrict__ n_w1, const float* __restrict__ n_w2,
    const float* __restrict__ n_b2,
    const float* __restrict__ ap_w1, const float* __restrict__ ap_w2,
    float* __restrict__ out, int N)
{
    extern __shared__ float sm[];
    float* Xn   = sm;
    float* Yn   = Xn + 128 * NODE_XS;
    float* Wbuf = Yn + 128 * TILE_YS;
    float* sES  = Wbuf + 4096;

    const int tid = threadIdx.x;
    const int nb = blockIdx.x * 128;

    // ------- stage [h | agg] = 256 dims -------
    {
        const int el = tid & 127, part = tid >> 7;
        int n = nb + el;
        bool v = n < N;
        long nn = v ? (long)n : 0;
        const float4* hr = reinterpret_cast<const float4*>(h) + nn * 32 + part * 8;
        const float4* ar = reinterpret_cast<const float4*>(g_agg) + nn * 32 + part * 8;
        float* xr = Xn + el * NODE_XS + part * 32;
#pragma unroll
        for (int i = 0; i < 8; i++) {
            float4 a = v ? __ldg(hr + i) : make_float4(0.f, 0.f, 0.f, 0.f);
            xr[4*i+0] = a.x; xr[4*i+1] = a.y; xr[4*i+2] = a.z; xr[4*i+3] = a.w;
        }
#pragma unroll
        for (int i = 0; i < 8; i++) {
            float4 a = v ? ar[i] : make_float4(0.f, 0.f, 0.f, 0.f);
            xr[128+4*i+0] = a.x; xr[128+4*i+1] = a.y; xr[128+4*i+2] = a.z; xr[128+4*i+3] = a.w;
        }
    }

    const int warp = tid >> 5, lane = tid & 31;
    const int e0 = (warp >> 2) * 32 + (lane >> 2) * 4;
    const int c0 = (warp & 3) * 32 + (lane & 3) * 8;

    UL acc[16];

    // ------- node GEMM1: [128 x 256] @ n_w1[0:256] + nb1_eff -> SiLU -------
    gemm_smem<256>(Xn, NODE_XS, n_w1, g_nb1, Wbuf, tid, e0, c0, acc);
#pragma unroll
    for (int j = 0; j < 4; j++) {
        float* yr = Yn + (e0 + j) * TILE_YS + c0;
#pragma unroll
        for (int p = 0; p < 4; p++) {
            float2 f = up2(acc[j*4+p]);
            yr[2*p]   = silu_f(f.x);
            yr[2*p+1] = silu_f(f.y);
        }
    }

    // ------- node GEMM2: @ n_w2 + n_b2 -> SiLU -> h_out = h + . -------
    gemm_smem<128>(Yn, TILE_YS, n_w2, n_b2, Wbuf, tid, e0, c0, acc);
#pragma unroll
    for (int j = 0; j < 4; j++) {
        int n = nb + e0 + j;
        float ho[8];
        const float* xh = Xn + (e0 + j) * NODE_XS + c0;
#pragma unroll
        for (int p = 0; p < 4; p++) {
            float2 f = up2(acc[j*4+p]);
            ho[2*p]   = silu_f(f.x) + xh[2*p];
            ho[2*p+1] = silu_f(f.y) + xh[2*p+1];
        }
        float* yr = Yn + (e0 + j) * TILE_YS + c0;
#pragma unroll
        for (int i = 0; i < 8; i++) yr[i] = ho[i];
        if (n < N) {
            float* o = out + (long)n * 128 + c0;
#pragma unroll
            for (int i = 0; i < 8; i++) o[i] = ho[i];
        }
    }
    if (tid < 128) sES[tid] = 0.0f;

    // ------- acc-point MLP: h_out @ ap_w1[0:128] + apb1_eff -> SiLU -> dot ap_w2 -
    gemm_smem<128>(Yn, TILE_YS, ap_w1, g_apb1, Wbuf, tid, e0, c0, acc);
    {
        float4 w0 = __ldg(reinterpret_cast<const float4*>(ap_w2 + c0));
        float4 w1 = __ldg(reinterpret_cast<const float4*>(ap_w2 + c0 + 4));
        float wv[8] = { w0.x, w0.y, w0.z, w0.w, w1.x, w1.y, w1.z, w1.w };
#pragma unroll
        for (int j = 0; j < 4; j++) {
            float p = 0.0f;
#pragma unroll
            for (int q = 0; q < 4; q++) {
                float2 f = up2(acc[j*4+q]);
                p += silu_f(f.x) * wv[2*q];
                p += silu_f(f.y) * wv[2*q+1];
            }
            p += __shfl_xor_sync(0xffffffffu, p, 1);
            p += __shfl_xor_sync(0xffffffffu, p, 2);
            if ((lane & 3) == 0) atomicAdd(&sES[e0 + j], p);
        }
    }
    __syncthreads();
    if (tid < 128) {
        int n = nb + tid;
        if (n < N) {
            float s = sES[tid];
            long base_c = (long)N * 128;
            long base_a = (long)N * 131;
            out[base_c + (long)n*3 + 0] = coordg[n*3+0];
            out[base_c + (long)n*3 + 1] = coordg[n*3+1];
            out[base_c + (long)n*3 + 2] = coordg[n*3+2];
            out[base_a + (long)n*3 + 0] = g_aggc[n*3+0] * s;
            out[base_a + (long)n*3 + 1] = g_aggc[n*3+1] * s;
            out[base_a + (long)n*3 + 2] = g_aggc[n*3+2] * s;
        }
    }
}

// ---------------- launch ----------------
extern "C" void kernel_launch(void* const* d_in, const int* in_sizes, int n_in,
                              void* d_out, int out_size)
{
    const float* h      = (const float*)d_in[0];
    const int*   ei     = (const int*)  d_in[1];
    const float* coord  = (const float*)d_in[2];
    const float* eattr  = (const float*)d_in[3];
    const float* prompt = (const float*)d_in[4];
    const float* e_w1   = (const float*)d_in[5];
    const float* e_b1   = (const float*)d_in[6];
    const float* e_w2   = (const float*)d_in[7];
    const float* e_b2   = (const float*)d_in[8];
    const float* n_w1   = (const float*)d_in[9];
    const float* n_b1   = (const float*)d_in[10];
    const float* n_w2   = (const float*)d_in[11];
    const float* n_b2   = (const float*)d_in[12];
    const float* ae_w1  = (const float*)d_in[13];
    const float* ae_b1  = (const float*)d_in[14];
    const float* ae_w2  = (const float*)d_in[15];
    const float* ap_w1  = (const float*)d_in[16];
    const float* ap_b1  = (const float*)d_in[17];
    const float* ap_w2  = (const float*)d_in[18];
    float* out = (float*)d_out;

    int N = in_sizes[0] / 128;
    int E = in_sizes[1] / 2;

    cudaFuncSetAttribute(edge_kernel, cudaFuncAttributeMaxDynamicSharedMemorySize, EDGE_SMEM);
    cudaFuncSetAttribute(node_kernel, cudaFuncAttributeMaxDynamicSharedMemorySize, NODE_SMEM);

    prep_kernel<<<4, 128>>>(prompt, e_w1, e_b1, n_w1, n_b1, ae_w1, ae_b1, ap_w1, ap_b1);
    zero_kernel<<<264, 256>>>(N);
    edge_kernel<<<(E + 127) / 128, 512, EDGE_SMEM>>>(h, ei, coord, eattr,
                                                     e_w1, e_w2, e_b2, ae_w1, ae_w2, E);
    node_kernel<<<(N + 127) / 128, 512, NODE_SMEM>>>(h, coord, n_w1, n_w2, n_b2,
                                                     ap_w1, ap_w2, out, N);
}

// round 7
// speedup vs baseline: 1.3375x; 1.0002x over previous
#include <cuda_runtime.h>

typedef unsigned long long UL;

// ---------------- device scratch (no allocations allowed) ----------------
__device__ float g_agg [50000 * 128];   // segment-sum of edge_feat per node
__device__ float g_aggc[50000 * 3];     // segment-sum of trans per node
__device__ float g_eb1 [128];           // e_b1  + prompt @ e_w1[273:401]
__device__ float g_nb1 [128];           // n_b1  + prompt @ n_w1[256:384]
__device__ float g_aeb1[128];           // ae_b1 + prompt @ ae_w1[128:256]
__device__ float g_apb1[128];           // ap_b1 + prompt @ ap_w1[128:256]

// ---------------- small helpers ----------------
__device__ __forceinline__ UL bc2(float x) {
    UL r; asm("mov.b64 %0,{%1,%1};" : "=l"(r) : "f"(x)); return r;
}
__device__ __forceinline__ UL pk2(float x, float y) {
    UL r; asm("mov.b64 %0,{%1,%2};" : "=l"(r) : "f"(x), "f"(y)); return r;
}
__device__ __forceinline__ float2 up2(UL v) {
    float2 f; asm("mov.b64 {%0,%1},%2;" : "=f"(f.x), "=f"(f.y) : "l"(v)); return f;
}
__device__ __forceinline__ void fma2(UL &d, UL a, UL b) {
    asm("fma.rn.f32x2 %0,%1,%2,%0;" : "+l"(d) : "l"(a), "l"(b));
}
__device__ __forceinline__ float silu_f(float x) {
    return __fdividef(x, 1.0f + __expf(-x));
}
__device__ __forceinline__ void cpa16(unsigned dst, const float* src) {
    asm volatile("cp.async.cg.shared.global [%0], [%1], 16;" :: "r"(dst), "l"(src));
}
#define CPA_COMMIT() asm volatile("cp.async.commit_group;" ::: "memory")

// 16 packed FMAs for one k-row: 4 edge-rows x 4 col-pairs
#define FMAROW(WA, WB, S0, S1, S2, S3)                            \
    do {                                                          \
        fma2(acc[0],  S0, WA.x); fma2(acc[1],  S0, WA.y);         \
        fma2(acc[2],  S0, WB.x); fma2(acc[3],  S0, WB.y);         \
        fma2(acc[4],  S1, WA.x); fma2(acc[5],  S1, WA.y);         \
        fma2(acc[6],  S1, WB.x); fma2(acc[7],  S1, WB.y);         \
        fma2(acc[8],  S2, WA.x); fma2(acc[9],  S2, WA.y);         \
        fma2(acc[10], S2, WB.x); fma2(acc[11], S2, WB.y);         \
        fma2(acc[12], S3, WA.x); fma2(acc[13], S3, WA.y);         \
        fma2(acc[14], S3, WB.x); fma2(acc[15], S3, WB.y);         \
    } while (0)

// ---------------- GEMM with cp.async double-buffered smem weights -------
// Xs: [tile][xs_stride] smem (odd stride -> conflict-free scalar loads).
// Wg: global row-major [K_alloc>=ceil16(K)][128]. Weights staged through
// Wbuf[2][16*128] in 16-row chunks: one cp.async.16 per thread per chunk,
// committed a full chunk (~2000 cyc) ahead of consumption.
// Thread owns 4 rows x 8 cols (4 f32x2 col-pairs per row) -> acc[16] u64.
template<int K>
__device__ __forceinline__ void gemm_smem(
    const float* Xs, int xs_stride,
    const float* __restrict__ Wg,
    const float* __restrict__ biasg,
    float* Wbuf, int tid, int e0, int c0, UL* acc)
{
    float4 b0 = __ldg(reinterpret_cast<const float4*>(biasg + c0));
    float4 b1 = __ldg(reinterpret_cast<const float4*>(biasg + c0 + 4));
    UL bp0 = pk2(b0.x, b0.y), bp1 = pk2(b0.z, b0.w);
    UL bp2 = pk2(b1.x, b1.y), bp3 = pk2(b1.z, b1.w);
#pragma unroll
    for (int j = 0; j < 4; j++) {
        acc[j*4+0] = bp0; acc[j*4+1] = bp1; acc[j*4+2] = bp2; acc[j*4+3] = bp3;
    }

    constexpr int CH = (K + 15) / 16;   // chunks of 16 k-rows

    // per-thread staging slot: row = tid/32 (0..15), 4 floats at (tid%32)*4
    const int srow = tid >> 5;
    const int scol = (tid & 31) * 4;
    const float* src = Wg + srow * 128 + scol;
    unsigned dstb = (unsigned)__cvta_generic_to_shared(Wbuf) + (srow * 128 + scol) * 4;

    cpa16(dstb, src);            // stage chunk 0 -> buf 0
    CPA_COMMIT();

    const float* x0 = Xs + (e0 + 0) * xs_stride;
    const float* x1 = Xs + (e0 + 1) * xs_stride;
    const float* x2 = Xs + (e0 + 2) * xs_stride;
    const float* x3 = Xs + (e0 + 3) * xs_stride;

    for (int c = 0; c < CH; c++) {
        if (c + 1 < CH) {
            cpa16(dstb + ((c + 1) & 1) * 8192, src + (c + 1) * 16 * 128);
            CPA_COMMIT();
            asm volatile("cp.async.wait_group 1;" ::: "memory");
        } else {
            asm volatile("cp.async.wait_group 0;" ::: "memory");
        }
        __syncthreads();

        const float* wb = Wbuf + (c & 1) * 2048 + c0;
        const int kb = c * 16;
        if (kb + 16 <= K) {
#pragma unroll
            for (int kk = 0; kk < 16; kk++) {
                int k = kb + kk;
                UL s0 = bc2(x0[k]), s1 = bc2(x1[k]), s2 = bc2(x2[k]), s3 = bc2(x3[k]);
                ulonglong2 a = *reinterpret_cast<const ulonglong2*>(wb + kk * 128);
                ulonglong2 b = *reinterpret_cast<const ulonglong2*>(wb + kk * 128 + 4);
                FMAROW(a, b, s0, s1, s2, s3);
            }
        } else {
            for (int kk = 0; kk < K - kb; kk++) {
                int k = kb + kk;
                UL s0 = bc2(x0[k]), s1 = bc2(x1[k]), s2 = bc2(x2[k]), s3 = bc2(x3[k]);
                ulonglong2 a = *reinterpret_cast<const ulonglong2*>(wb + kk * 128);
                ulonglong2 b = *reinterpret_cast<const ulonglong2*>(wb + kk * 128 + 4);
                FMAROW(a, b, s0, s1, s2, s3);
            }
        }
        __syncthreads();
    }
}

// ---------------- prompt-bias precompute (4 blocks, one per bias) -------
__global__ void prep_kernel(
    const float* __restrict__ prompt,
    const float* __restrict__ e_w1,  const float* __restrict__ e_b1,
    const float* __restrict__ n_w1,  const float* __restrict__ n_b1,
    const float* __restrict__ ae_w1, const float* __restrict__ ae_b1,
    const float* __restrict__ ap_w1, const float* __restrict__ ap_b1)
{
    int n = threadIdx.x;  // 128 threads
    int b = blockIdx.x;
    const float* w; const float* bias; float* dst; int off;
    if (b == 0)      { w = e_w1;  bias = e_b1;  dst = g_eb1;  off = 273; }
    else if (b == 1) { w = n_w1;  bias = n_b1;  dst = g_nb1;  off = 256; }
    else if (b == 2) { w = ae_w1; bias = ae_b1; dst = g_aeb1; off = 128; }
    else             { w = ap_w1; bias = ap_b1; dst = g_apb1; off = 128; }
    float s = bias[n];
    for (int j = 0; j < 128; j++)
        s = fmaf(prompt[j], w[(off + j) * 128 + n], s);
    dst[n] = s;
}

// ---------------- zero scratch ----------------
__global__ void zero_kernel(int N)
{
    long stride = (long)gridDim.x * blockDim.x;
    long t1 = (long)N * 128;
    for (long i = blockIdx.x * (long)blockDim.x + threadIdx.x; i < t1; i += stride)
        g_agg[i] = 0.0f;
    long t2 = (long)N * 3;
    for (long i = blockIdx.x * (long)blockDim.x + threadIdx.x; i < t2; i += stride)
        g_aggc[i] = 0.0f;
}

// ---------------- fused edge kernel ----------------
// 128 edges per CTA, 512 threads, 16 warps.
// smem (floats): Xs[128*277]=35456 | Ys[128*129]=16512 | Wbuf[2*16*128]=4096
//              | cd[128*4]=512 | sES[128] | rowi[128]  -> 56832 f = 227328 B
#define EDGE_XS 277
#define TILE_YS 129
#define EDGE_SMEM 227328

__global__ void __launch_bounds__(512, 1) edge_kernel(
    const float* __restrict__ h, const int* __restrict__ ei,
    const float* __restrict__ coord, const float* __restrict__ eattr,
    const float* __restrict__ e_w1, const float* __restrict__ e_w2,
    const float* __restrict__ e_b2,
    const float* __restrict__ ae_w1, const float* __restrict__ ae_w2,
    int E)
{
    extern __shared__ float sm[];
    float*  Xs   = sm;                               // 35456
    float*  Ys   = Xs + 128 * EDGE_XS;               // 16512
    float*  Wbuf = Ys + 128 * TILE_YS;               // 4096
    float4* cd   = reinterpret_cast<float4*>(Wbuf + 4096);   // 512 f
    float*  sES  = reinterpret_cast<float*>(cd + 128);       // 128
    int*    rowi = reinterpret_cast<int*>(sES + 128);        // 128

    const int tid = threadIdx.x;
    const int e_base = blockIdx.x * 128;
    const int* rowg = ei;
    const int* colg = ei + E;

    // ------- stage X tile: [h[row] | h[col] | radial | edge_attr] = 273 dims ----
    {
        const int el = tid & 127, part = tid >> 7;   // 4 parts of 32 floats
        int e = e_base + el;
        bool v = e < E;
        long r = v ? (long)rowg[e] : 0;
        long c = v ? (long)colg[e] : 0;
        const float4* hr = reinterpret_cast<const float4*>(h) + r * 32 + part * 8;
        const float4* hc = reinterpret_cast<const float4*>(h) + c * 32 + part * 8;
        float* xr = Xs + el * EDGE_XS + part * 32;
#pragma unroll
        for (int i = 0; i < 8; i++) {
            float4 a = v ? __ldg(hr + i) : make_float4(0.f, 0.f, 0.f, 0.f);
            xr[4*i+0] = a.x; xr[4*i+1] = a.y; xr[4*i+2] = a.z; xr[4*i+3] = a.w;
        }
#pragma unroll
        for (int i = 0; i < 8; i++) {
            float4 b = v ? __ldg(hc + i) : make_float4(0.f, 0.f, 0.f, 0.f);
            xr[128+4*i+0] = b.x; xr[128+4*i+1] = b.y; xr[128+4*i+2] = b.z; xr[128+4*i+3] = b.w;
        }
        if (part == 0) {
            rowi[el] = (int)r;
            float dx = 0.f, dy = 0.f, dz = 0.f;
            if (v) {
                dx = coord[r*3+0] - coord[c*3+0];
                dy = coord[r*3+1] - coord[c*3+1];
                dz = coord[r*3+2] - coord[c*3+2];
            }
            float rad = dx*dx + dy*dy + dz*dz;
            Xs[el * EDGE_XS + 256] = rad;
            float inv = 1.0f / fmaxf(sqrtf(rad), 1e-12f);
            cd[el] = make_float4(dx, dy, dz, inv);
        } else if (part == 1) {
            const float4* ea = reinterpret_cast<const float4*>(eattr) + (long)e * 4;
#pragma unroll
            for (int i = 0; i < 4; i++) {
                float4 a = v ? __ldg(ea + i) : make_float4(0.f, 0.f, 0.f, 0.f);
                float* xq = Xs + el * EDGE_XS + 257 + 4 * i;
                xq[0] = a.x; xq[1] = a.y; xq[2] = a.z; xq[3] = a.w;
            }
        }
    }
    // Xs visibility is guaranteed by the first __syncthreads inside gemm_smem

    const int warp = tid >> 5, lane = tid & 31;
    const int e0 = (warp >> 2) * 32 + (lane >> 2) * 4;
    const int c0 = (warp & 3) * 32 + (lane & 3) * 8;

    UL acc[16];

    // ------- GEMM1: [128 x 273] @ e_w1[0:273] + eb1_eff -> SiLU -> Ys -------
    // (tail chunk stages e_w1 rows 273..287 which exist: e_w1 has 401 rows)
    gemm_smem<273>(Xs, EDGE_XS, e_w1, g_eb1, Wbuf, tid, e0, c0, acc);
#pragma unroll
    for (int j = 0; j < 4; j++) {
        float* yr = Ys + (e0 + j) * TILE_YS + c0;
#pragma unroll
        for (int p = 0; p < 4; p++) {
            float2 f = up2(acc[j*4+p]);
            yr[2*p]   = silu_f(f.x);
            yr[2*p+1] = silu_f(f.y);
        }
    }

    // ------- GEMM2: [128 x 128] @ e_w2 + e_b2 -> SiLU = edge_feat -------
    gemm_smem<128>(Ys, TILE_YS, e_w2, e_b2, Wbuf, tid, e0, c0, acc);
    // last internal sync of gemm_smem ordered every warp's reads; safe to overwrite Ys
#pragma unroll
    for (int j = 0; j < 4; j++) {
        float z[8];
#pragma unroll
        for (int p = 0; p < 4; p++) {
            float2 f = up2(acc[j*4+p]);
            z[2*p] = silu_f(f.x); z[2*p+1] = silu_f(f.y);
        }
        float* yr = Ys + (e0 + j) * TILE_YS + c0;
#pragma unroll
        for (int i = 0; i < 8; i++) yr[i] = z[i];
        int eg = e_base + e0 + j;
        if (eg < E) {
            float* dst = g_agg + (long)rowi[e0 + j] * 128 + c0;
            atomicAdd(reinterpret_cast<float4*>(dst),
                      make_float4(z[0], z[1], z[2], z[3]));
            atomicAdd(reinterpret_cast<float4*>(dst + 4),
                      make_float4(z[4], z[5], z[6], z[7]));
        }
    }
    if (tid < 128) sES[tid] = 0.0f;

    // ------- GEMM3: edge_feat @ ae_w1[0:128] + aeb1_eff -> SiLU -> dot ae_w2 ---
    gemm_smem<128>(Ys, TILE_YS, ae_w1, g_aeb1, Wbuf, tid, e0, c0, acc);
    {
        float4 w0 = __ldg(reinterpret_cast<const float4*>(ae_w2 + c0));
        float4 w1 = __ldg(reinterpret_cast<const float4*>(ae_w2 + c0 + 4));
        float wv[8] = { w0.x, w0.y, w0.z, w0.w, w1.x, w1.y, w1.z, w1.w };
#pragma unroll
        for (int j = 0; j < 4; j++) {
            float p = 0.0f;
#pragma unroll
            for (int q = 0; q < 4; q++) {
                float2 f = up2(acc[j*4+q]);
                p += silu_f(f.x) * wv[2*q];
                p += silu_f(f.y) * wv[2*q+1];
            }
            p += __shfl_xor_sync(0xffffffffu, p, 1);
            p += __shfl_xor_sync(0xffffffffu, p, 2);
            if ((lane & 3) == 0) atomicAdd(&sES[e0 + j], p);
        }
    }
    __syncthreads();
    if (tid < 128) {
        int eg = e_base + tid;
        if (eg < E) {
            float s = sES[tid];
            float4 c = cd[tid];
            float f = s * c.w;  // phi(e) / max(||d||,1e-12)
            float* dst = g_aggc + (long)rowi[tid] * 3;
            atomicAdd(dst + 0, c.x * f);
            atomicAdd(dst + 1, c.y * f);
            atomicAdd(dst + 2, c.z * f);
        }
    }
}

// ---------------- fused node kernel ----------------
// 128 nodes per CTA, 512 threads.
// smem: Xn[128*261]=33408 | Yn[128*129]=16512 | Wbuf 4096 | sES 128 -> 216576 B
#define NODE_XS 261
#define NODE_SMEM 216576

__global__ void __launch_bounds__(512, 1) node_kernel(
    const float* __restrict__ h, const float* __restrict__ coordg,
    const float* __restrict__ n_w1, const float* __restrict__ n_w2,
    const float* __restrict__ n_b2,
    const float* __restrict__ ap_w1, const float* __restrict__ ap_w2,
    float* __restrict__ out, int N)
{
    extern __shared__ float sm[];
    float* Xn   = sm;
    float* Yn   = Xn + 128 * NODE_XS;
    float* Wbuf = Yn + 128 * TILE_YS;
    float* sES  = Wbuf + 4096;

    const int tid = threadIdx.x;
    const int nb = blockIdx.x * 128;

    // ------- stage [h | agg] = 256 dims -------
    {
        const int el = tid & 127, part = tid >> 7;
        int n = nb + el;
        bool v = n < N;
        long nn = v ? (long)n : 0;
        const float4* hr = reinterpret_cast<const float4*>(h) + nn * 32 + part * 8;
        const float4* ar = reinterpret_cast<const float4*>(g_agg) + nn * 32 + part * 8;
        float* xr = Xn + el * NODE_XS + part * 32;
#pragma unroll
        for (int i = 0; i < 8; i++) {
            float4 a = v ? __ldg(hr + i) : make_float4(0.f, 0.f, 0.f, 0.f);
            xr[4*i+0] = a.x; xr[4*i+1] = a.y; xr[4*i+2] = a.z; xr[4*i+3] = a.w;
        }
#pragma unroll
        for (int i = 0; i < 8; i++) {
            float4 a = v ? ar[i] : make_float4(0.f, 0.f, 0.f, 0.f);
            xr[128+4*i+0] = a.x; xr[128+4*i+1] = a.y; xr[128+4*i+2] = a.z; xr[128+4*i+3] = a.w;
        }
    }

    const int warp = tid >> 5, lane = tid & 31;
    const int e0 = (warp >> 2) * 32 + (lane >> 2) * 4;
    const int c0 = (warp & 3) * 32 + (lane & 3) * 8;

    UL acc[16];

    // ------- node GEMM1: [128 x 256] @ n_w1[0:256] + nb1_eff -> SiLU -------
    gemm_smem<256>(Xn, NODE_XS, n_w1, g_nb1, Wbuf, tid, e0, c0, acc);
#pragma unroll
    for (int j = 0; j < 4; j++) {
        float* yr = Yn + (e0 + j) * TILE_YS + c0;
#pragma unroll
        for (int p = 0; p < 4; p++) {
            float2 f = up2(acc[j*4+p]);
            yr[2*p]   = silu_f(f.x);
            yr[2*p+1] = silu_f(f.y);
        }
    }

    // ------- node GEMM2: @ n_w2 + n_b2 -> SiLU -> h_out = h + . -------
    gemm_smem<128>(Yn, TILE_YS, n_w2, n_b2, Wbuf, tid, e0, c0, acc);
#pragma unroll
    for (int j = 0; j < 4; j++) {
        int n = nb + e0 + j;
        float ho[8];
        const float* xh = Xn + (e0 + j) * NODE_XS + c0;
#pragma unroll
        for (int p = 0; p < 4; p++) {
            float2 f = up2(acc[j*4+p]);
            ho[2*p]   = silu_f(f.x) + xh[2*p];
            ho[2*p+1] = silu_f(f.y) + xh[2*p+1];
        }
        float* yr = Yn + (e0 + j) * TILE_YS + c0;
#pragma unroll
        for (int i = 0; i < 8; i++) yr[i] = ho[i];
        if (n < N) {
            float* o = out + (long)n * 128 + c0;
#pragma unroll
            for (int i = 0; i < 8; i++) o[i] = ho[i];
        }
    }
    if (tid < 128) sES[tid] = 0.0f;

    // ------- acc-point MLP: h_out @ ap_w1[0:128] + apb1_eff -> SiLU -> dot ap_w2 -
    gemm_smem<128>(Yn, TILE_YS, ap_w1, g_apb1, Wbuf, tid, e0, c0, acc);
    {
        float4 w0 = __ldg(reinterpret_cast<const float4*>(ap_w2 + c0));
        float4 w1 = __ldg(reinterpret_cast<const float4*>(ap_w2 + c0 + 4));
        float wv[8] = { w0.x, w0.y, w0.z, w0.w, w1.x, w1.y, w1.z, w1.w };
#pragma unroll
        for (int j = 0; j < 4; j++) {
            float p = 0.0f;
#pragma unroll
            for (int q = 0; q < 4; q++) {
                float2 f = up2(acc[j*4+q]);
                p += silu_f(f.x) * wv[2*q];
                p += silu_f(f.y) * wv[2*q+1];
            }
            p += __shfl_xor_sync(0xffffffffu, p, 1);
            p += __shfl_xor_sync(0xffffffffu, p, 2);
            if ((lane & 3) == 0) atomicAdd(&sES[e0 + j], p);
        }
    }
    __syncthreads();
    if (tid < 128) {
        int n = nb + tid;
        if (n < N) {
            float s = sES[tid];
            long base_c = (long)N * 128;
            long base_a = (long)N * 131;
            out[base_c + (long)n*3 + 0] = coordg[n*3+0];
            out[base_c + (long)n*3 + 1] = coordg[n*3+1];
            out[base_c + (long)n*3 + 2] = coordg[n*3+2];
            out[base_a + (long)n*3 + 0] = g_aggc[n*3+0] * s;
            out[base_a + (long)n*3 + 1] = g_aggc[n*3+1] * s;
            out[base_a + (long)n*3 + 2] = g_aggc[n*3+2] * s;
        }
    }
}

// ---------------- launch ----------------
extern "C" void kernel_launch(void* const* d_in, const int* in_sizes, int n_in,
                              void* d_out, int out_size)
{
    const float* h      = (const float*)d_in[0];
    const int*   ei     = (const int*)  d_in[1];
    const float* coord  = (const float*)d_in[2];
    const float* eattr  = (const float*)d_in[3];
    const float* prompt = (const float*)d_in[4];
    const float* e_w1   = (const float*)d_in[5];
    const float* e_b1   = (const float*)d_in[6];
    const float* e_w2   = (const float*)d_in[7];
    const float* e_b2   = (const float*)d_in[8];
    const float* n_w1   = (const float*)d_in[9];
    const float* n_b1   = (const float*)d_in[10];
    const float* n_w2   = (const float*)d_in[11];
    const float* n_b2   = (const float*)d_in[12];
    const float* ae_w1  = (const float*)d_in[13];
    const float* ae_b1  = (const float*)d_in[14];
    const float* ae_w2  = (const float*)d_in[15];
    const float* ap_w1  = (const float*)d_in[16];
    const float* ap_b1  = (const float*)d_in[17];
    const float* ap_w2  = (const float*)d_in[18];
    float* out = (float*)d_out;

    int N = in_sizes[0] / 128;
    int E = in_sizes[1] / 2;

    cudaFuncSetAttribute(edge_kernel, cudaFuncAttributeMaxDynamicSharedMemorySize, EDGE_SMEM);
    cudaFuncSetAttribute(node_kernel, cudaFuncAttributeMaxDynamicSharedMemorySize, NODE_SMEM);

    prep_kernel<<<4, 128>>>(prompt, e_w1, e_b1, n_w1, n_b1, ae_w1, ae_b1, ap_w1, ap_b1);
    zero_kernel<<<264, 256>>>(N);
    edge_kernel<<<(E + 127) / 128, 512, EDGE_SMEM>>>(h, ei, coord, eattr,
                                                     e_w1, e_w2, e_b2, ae_w1, ae_w2, E);
    node_kernel<<<(N + 127) / 128, 512, NODE_SMEM>>>(h, coord, n_w1, n_w2, n_b2,
                                                     ap_w1, ap_w2, out, N);
}

// round 8
// speedup vs baseline: 2.2139x; 1.6552x over previous
#include <cuda_runtime.h>

typedef unsigned long long UL;

// ---------------- device scratch (no allocations allowed) ----------------
__device__ float g_agg [50000 * 128];   // segment-sum of edge_feat per node
__device__ float g_aggc[50000 * 3];     // segment-sum of trans per node
__device__ float g_P   [50048 * 256];   // per-node projections [P1 | P2]
__device__ float g_eb1 [128];           // e_b1  + prompt @ e_w1[273:401]
__device__ float g_nb1 [128];           // n_b1  + prompt @ n_w1[256:384]
__device__ float g_aeb1[128];           // ae_b1 + prompt @ ae_w1[128:256]
__device__ float g_apb1[128];           // ap_b1 + prompt @ ap_w1[128:256]

// ---------------- small helpers ----------------
__device__ __forceinline__ UL bc2(float x) {
    UL r; asm("mov.b64 %0,{%1,%1};" : "=l"(r) : "f"(x)); return r;
}
__device__ __forceinline__ UL pk2(float x, float y) {
    UL r; asm("mov.b64 %0,{%1,%2};" : "=l"(r) : "f"(x), "f"(y)); return r;
}
__device__ __forceinline__ float2 up2(UL v) {
    float2 f; asm("mov.b64 {%0,%1},%2;" : "=f"(f.x), "=f"(f.y) : "l"(v)); return f;
}
__device__ __forceinline__ void fma2(UL &d, UL a, UL b) {
    asm("fma.rn.f32x2 %0,%1,%2,%0;" : "+l"(d) : "l"(a), "l"(b));
}
__device__ __forceinline__ float silu_f(float x) {
    return __fdividef(x, 1.0f + __expf(-x));
}
__device__ __forceinline__ void cpa16(unsigned dst, const float* src) {
    asm volatile("cp.async.cg.shared.global [%0], [%1], 16;" :: "r"(dst), "l"(src));
}
#define CPA_COMMIT() asm volatile("cp.async.commit_group;" ::: "memory")

// 16 packed FMAs for one k-row: 4 rows x 4 col-pairs
#define FMAROW(WA, WB, S0, S1, S2, S3)                            \
    do {                                                          \
        fma2(acc[0],  S0, WA.x); fma2(acc[1],  S0, WA.y);         \
        fma2(acc[2],  S0, WB.x); fma2(acc[3],  S0, WB.y);         \
        fma2(acc[4],  S1, WA.x); fma2(acc[5],  S1, WA.y);         \
        fma2(acc[6],  S1, WB.x); fma2(acc[7],  S1, WB.y);         \
        fma2(acc[8],  S2, WA.x); fma2(acc[9],  S2, WA.y);         \
        fma2(acc[10], S2, WB.x); fma2(acc[11], S2, WB.y);         \
        fma2(acc[12], S3, WA.x); fma2(acc[13], S3, WA.y);         \
        fma2(acc[14], S3, WB.x); fma2(acc[15], S3, WB.y);         \
    } while (0)

__device__ __forceinline__ void init_acc_bias(const float* biasg, int c0, UL* acc)
{
    float4 b0 = __ldg(reinterpret_cast<const float4*>(biasg + c0));
    float4 b1 = __ldg(reinterpret_cast<const float4*>(biasg + c0 + 4));
    UL bp0 = pk2(b0.x, b0.y), bp1 = pk2(b0.z, b0.w);
    UL bp2 = pk2(b1.x, b1.y), bp3 = pk2(b1.z, b1.w);
#pragma unroll
    for (int j = 0; j < 4; j++) {
        acc[j*4+0] = bp0; acc[j*4+1] = bp1; acc[j*4+2] = bp2; acc[j*4+3] = bp3;
    }
}
__device__ __forceinline__ void init_acc_zero(UL* acc)
{
    UL z = pk2(0.0f, 0.0f);
#pragma unroll
    for (int j = 0; j < 16; j++) acc[j] = z;
}

// ------- GEMM on TRANSPOSED X tile with cp.async smem weights ----------
// XsT: [K][128] smem (k-row reads are contiguous -> LDS.128, no pad).
// Wg: global row-major [>=ceil16(K)][128]. Weights staged through
// Wbuf[2][16*128] in 16-row chunks (one cp.async.16 per thread).
// Thread owns 4 rows x 8 cols; caller pre-initializes acc[16].
template<int K>
__device__ __forceinline__ void gemm_smem_t(
    const float* XsT, const float* __restrict__ Wg,
    float* Wbuf, int tid, int e0, int c0, UL* acc)
{
    constexpr int CH = (K + 15) / 16;

    const int srow = tid >> 5;
    const int scol = (tid & 31) * 4;
    const float* src = Wg + srow * 128 + scol;
    unsigned dstb = (unsigned)__cvta_generic_to_shared(Wbuf) + (srow * 128 + scol) * 4;

    cpa16(dstb, src);
    CPA_COMMIT();

    const float* xb = XsT + e0;

    for (int c = 0; c < CH; c++) {
        if (c + 1 < CH) {
            cpa16(dstb + ((c + 1) & 1) * 8192, src + (c + 1) * 2048);
            CPA_COMMIT();
            asm volatile("cp.async.wait_group 1;" ::: "memory");
        } else {
            asm volatile("cp.async.wait_group 0;" ::: "memory");
        }
        __syncthreads();

        const float* wb = Wbuf + (c & 1) * 2048 + c0;
        const int kb = c * 16;
        if (kb + 16 <= K) {
#pragma unroll
            for (int kk = 0; kk < 16; kk++) {
                float4 xv = *reinterpret_cast<const float4*>(xb + (kb + kk) * 128);
                ulonglong2 a = *reinterpret_cast<const ulonglong2*>(wb + kk * 128);
                ulonglong2 b = *reinterpret_cast<const ulonglong2*>(wb + kk * 128 + 4);
                UL s0 = bc2(xv.x), s1 = bc2(xv.y), s2 = bc2(xv.z), s3 = bc2(xv.w);
                FMAROW(a, b, s0, s1, s2, s3);
            }
        } else {
            for (int kk = 0; kk < K - kb; kk++) {
                float4 xv = *reinterpret_cast<const float4*>(xb + (kb + kk) * 128);
                ulonglong2 a = *reinterpret_cast<const ulonglong2*>(wb + kk * 128);
                ulonglong2 b = *reinterpret_cast<const ulonglong2*>(wb + kk * 128 + 4);
                UL s0 = bc2(xv.x), s1 = bc2(xv.y), s2 = bc2(xv.z), s3 = bc2(xv.w);
                FMAROW(a, b, s0, s1, s2, s3);
            }
        }
        __syncthreads();
    }
}

// write 8 cols x 4 rows of silu(acc) into transposed tile T[col][row128]
__device__ __forceinline__ void epilogue_silu_T(
    UL* acc, float* T, int e0, int c0)
{
#pragma unroll
    for (int p = 0; p < 4; p++) {
        float2 f0 = up2(acc[0*4+p]), f1 = up2(acc[1*4+p]);
        float2 f2 = up2(acc[2*4+p]), f3 = up2(acc[3*4+p]);
        *reinterpret_cast<float4*>(T + (c0 + 2*p) * 128 + e0) =
            make_float4(silu_f(f0.x), silu_f(f1.x), silu_f(f2.x), silu_f(f3.x));
        *reinterpret_cast<float4*>(T + (c0 + 2*p + 1) * 128 + e0) =
            make_float4(silu_f(f0.y), silu_f(f1.y), silu_f(f2.y), silu_f(f3.y));
    }
}

// ---------------- prompt-bias precompute (4 blocks, one per bias) -------
__global__ void prep_kernel(
    const float* __restrict__ prompt,
    const float* __restrict__ e_w1,  const float* __restrict__ e_b1,
    const float* __restrict__ n_w1,  const float* __restrict__ n_b1,
    const float* __restrict__ ae_w1, const float* __restrict__ ae_b1,
    const float* __restrict__ ap_w1, const float* __restrict__ ap_b1)
{
    int n = threadIdx.x;
    int b = blockIdx.x;
    const float* w; const float* bias; float* dst; int off;
    if (b == 0)      { w = e_w1;  bias = e_b1;  dst = g_eb1;  off = 273; }
    else if (b == 1) { w = n_w1;  bias = n_b1;  dst = g_nb1;  off = 256; }
    else if (b == 2) { w = ae_w1; bias = ae_b1; dst = g_aeb1; off = 128; }
    else             { w = ap_w1; bias = ap_b1; dst = g_apb1; off = 128; }
    float s = bias[n];
    for (int j = 0; j < 128; j++)
        s = fmaf(prompt[j], w[(off + j) * 128 + n], s);
    dst[n] = s;
}

// ---------------- zero scratch ----------------
__global__ void zero_kernel(int N)
{
    long stride = (long)gridDim.x * blockDim.x;
    long t1 = (long)N * 128;
    for (long i = blockIdx.x * (long)blockDim.x + threadIdx.x; i < t1; i += stride)
        g_agg[i] = 0.0f;
    long t2 = (long)N * 3;
    for (long i = blockIdx.x * (long)blockDim.x + threadIdx.x; i < t2; i += stride)
        g_aggc[i] = 0.0f;
}

// ---------------- node projection kernel: g_P = h @ [W1a | W1b] ---------
// 128 nodes per CTA, 512 threads.  smem: hT[128][128] | Wbuf[2][2048]
#define PROJ_SMEM ((128*128 + 4096) * 4)

__global__ void __launch_bounds__(512, 1) proj_kernel(
    const float* __restrict__ h, const float* __restrict__ e_w1, int N)
{
    extern __shared__ float sm[];
    float* hT   = sm;
    float* Wbuf = hT + 128 * 128;

    const int tid = threadIdx.x;
    const int nb = blockIdx.x * 128;
    {
        const int el = tid & 127, part = tid >> 7;   // part covers 32 k
        int n = nb + el;
        bool v = n < N;
        long nn = v ? (long)n : 0;
        const float4* hr = reinterpret_cast<const float4*>(h) + nn * 32 + part * 8;
#pragma unroll
        for (int i = 0; i < 8; i++) {
            float4 a = v ? __ldg(hr + i) : make_float4(0.f, 0.f, 0.f, 0.f);
            int k = part * 32 + 4 * i;
            hT[(k+0)*128 + el] = a.x; hT[(k+1)*128 + el] = a.y;
            hT[(k+2)*128 + el] = a.z; hT[(k+3)*128 + el] = a.w;
        }
    }
    const int warp = tid >> 5, lane = tid & 31;
    const int e0 = (warp >> 2) * 32 + (lane >> 2) * 4;
    const int c0 = (warp & 3) * 32 + (lane & 3) * 8;

    UL acc[16];

    // P1 = h @ e_w1[0:128]
    init_acc_zero(acc);
    gemm_smem_t<128>(hT, e_w1, Wbuf, tid, e0, c0, acc);
#pragma unroll
    for (int j = 0; j < 4; j++) {
        int n = nb + e0 + j;
        if (n < N) {
            float2 f0 = up2(acc[j*4+0]), f1 = up2(acc[j*4+1]);
            float2 f2 = up2(acc[j*4+2]), f3 = up2(acc[j*4+3]);
            float* o = g_P + (long)n * 256 + c0;
            *reinterpret_cast<float4*>(o)     = make_float4(f0.x, f0.y, f1.x, f1.y);
            *reinterpret_cast<float4*>(o + 4) = make_float4(f2.x, f2.y, f3.x, f3.y);
        }
    }

    // P2 = h @ e_w1[128:256]
    init_acc_zero(acc);
    gemm_smem_t<128>(hT, e_w1 + 128 * 128, Wbuf, tid, e0, c0, acc);
#pragma unroll
    for (int j = 0; j < 4; j++) {
        int n = nb + e0 + j;
        if (n < N) {
            float2 f0 = up2(acc[j*4+0]), f1 = up2(acc[j*4+1]);
            float2 f2 = up2(acc[j*4+2]), f3 = up2(acc[j*4+3]);
            float* o = g_P + (long)n * 256 + 128 + c0;
            *reinterpret_cast<float4*>(o)     = make_float4(f0.x, f0.y, f1.x, f1.y);
            *reinterpret_cast<float4*>(o + 4) = make_float4(f2.x, f2.y, f3.x, f3.y);
        }
    }
}

// ---------------- fused edge kernel ----------------
// 128 edges per CTA, 512 threads.
// smem (floats): XeT[20][128]=2560 | YsT[128][128]=16384 | Wbuf 4096
//              | cd 512 | sES 128 | rowi 128 | coli 128  -> 95744 B
#define EDGE_SMEM ((20*128 + 128*128 + 4096 + 512 + 128 + 128 + 128) * 4)

__global__ void __launch_bounds__(512, 1) edge_kernel(
    const int* __restrict__ ei,
    const float* __restrict__ coord, const float* __restrict__ eattr,
    const float* __restrict__ e_w1, const float* __restrict__ e_w2,
    const float* __restrict__ e_b2,
    const float* __restrict__ ae_w1, const float* __restrict__ ae_w2,
    int E)
{
    extern __shared__ float sm[];
    float*  XeT  = sm;                                   // 2560
    float*  YsT  = XeT + 20 * 128;                       // 16384
    float*  Wbuf = YsT + 128 * 128;                      // 4096
    float4* cd   = reinterpret_cast<float4*>(Wbuf + 4096);
    float*  sES  = reinterpret_cast<float*>(cd + 128);
    int*    rowi = reinterpret_cast<int*>(sES + 128);
    int*    coli = rowi + 128;

    const int tid = threadIdx.x;
    const int e_base = blockIdx.x * 128;
    const int* rowg = ei;
    const int* colg = ei + E;

    // ------- stage small XeT: row0 = radial, rows 1..16 = eattr^T -------
    {
        const int el = tid & 127, part = tid >> 7;
        int e = e_base + el;
        bool v = e < E;
        if (part == 0) {
            long r = v ? (long)rowg[e] : 0;
            long c = v ? (long)colg[e] : 0;
            rowi[el] = (int)r;
            coli[el] = (int)c;
            float dx = 0.f, dy = 0.f, dz = 0.f;
            if (v) {
                dx = coord[r*3+0] - coord[c*3+0];
                dy = coord[r*3+1] - coord[c*3+1];
                dz = coord[r*3+2] - coord[c*3+2];
            }
            float rad = dx*dx + dy*dy + dz*dz;
            XeT[el] = rad;                       // k = 0
            float inv = 1.0f / fmaxf(sqrtf(rad), 1e-12f);
            cd[el] = make_float4(dx, dy, dz, inv);
        } else if (part == 1) {
            const float4* ea = reinterpret_cast<const float4*>(eattr) + (long)e * 4;
#pragma unroll
            for (int i = 0; i < 4; i++) {
                float4 a = v ? __ldg(ea + i) : make_float4(0.f, 0.f, 0.f, 0.f);
                int k = 1 + 4 * i;
                XeT[(k+0)*128 + el] = a.x; XeT[(k+1)*128 + el] = a.y;
                XeT[(k+2)*128 + el] = a.z; XeT[(k+3)*128 + el] = a.w;
            }
        }
    }
    __syncthreads();

    const int warp = tid >> 5, lane = tid & 31;
    const int e0 = (warp >> 2) * 32 + (lane >> 2) * 4;
    const int c0 = (warp & 3) * 32 + (lane & 3) * 8;

    UL acc[16];

    // ------- acc init: eb1_eff + P1[row] + P2[col]  (the K=256 part) ----
    {
        float4 b0 = __ldg(reinterpret_cast<const float4*>(g_eb1 + c0));
        float4 b1 = __ldg(reinterpret_cast<const float4*>(g_eb1 + c0 + 4));
#pragma unroll
        for (int j = 0; j < 4; j++) {
            int r = rowi[e0 + j], cc = coli[e0 + j];
            const float* pr = g_P + (long)r  * 256 + c0;
            const float* pc = g_P + (long)cc * 256 + 128 + c0;
            float4 p0 = __ldg(reinterpret_cast<const float4*>(pr));
            float4 p1 = __ldg(reinterpret_cast<const float4*>(pr + 4));
            float4 q0 = __ldg(reinterpret_cast<const float4*>(pc));
            float4 q1 = __ldg(reinterpret_cast<const float4*>(pc + 4));
            acc[j*4+0] = pk2(b0.x + p0.x + q0.x, b0.y + p0.y + q0.y);
            acc[j*4+1] = pk2(b0.z + p0.z + q0.z, b0.w + p0.w + q0.w);
            acc[j*4+2] = pk2(b1.x + p1.x + q1.x, b1.y + p1.y + q1.y);
            acc[j*4+3] = pk2(b1.z + p1.z + q1.z, b1.w + p1.w + q1.w);
        }
    }

    // ------- GEMM1 (K=17): [rad|eattr] @ e_w1[256:273] -> SiLU -> YsT ----
    gemm_smem_t<17>(XeT, e_w1 + 256 * 128, Wbuf, tid, e0, c0, acc);
    epilogue_silu_T(acc, YsT, e0, c0);

    // ------- GEMM2 (K=128): @ e_w2 + e_b2 -> SiLU = edge_feat ----------
    init_acc_bias(e_b2, c0, acc);
    gemm_smem_t<128>(YsT, e_w2, Wbuf, tid, e0, c0, acc);
    // all warps past final sync -> done reading YsT; safe to overwrite
    {
        float z[4][8];
#pragma unroll
        for (int j = 0; j < 4; j++)
#pragma unroll
            for (int p = 0; p < 4; p++) {
                float2 f = up2(acc[j*4+p]);
                z[j][2*p] = silu_f(f.x); z[j][2*p+1] = silu_f(f.y);
            }
#pragma unroll
        for (int p = 0; p < 8; p++) {
            *reinterpret_cast<float4*>(YsT + (c0 + p) * 128 + e0) =
                make_float4(z[0][p], z[1][p], z[2][p], z[3][p]);
        }
#pragma unroll
        for (int j = 0; j < 4; j++) {
            int eg = e_base + e0 + j;
            if (eg < E) {
                float* dst = g_agg + (long)rowi[e0 + j] * 128 + c0;
                atomicAdd(reinterpret_cast<float4*>(dst),
                          make_float4(z[j][0], z[j][1], z[j][2], z[j][3]));
                atomicAdd(reinterpret_cast<float4*>(dst + 4),
                          make_float4(z[j][4], z[j][5], z[j][6], z[j][7]));
            }
        }
    }
    if (tid < 128) sES[tid] = 0.0f;

    // ------- GEMM3: edge_feat @ ae_w1[0:128] + aeb1 -> SiLU -> dot ae_w2 -
    init_acc_bias(g_aeb1, c0, acc);
    gemm_smem_t<128>(YsT, ae_w1, Wbuf, tid, e0, c0, acc);
    {
        float4 w0 = __ldg(reinterpret_cast<const float4*>(ae_w2 + c0));
        float4 w1 = __ldg(reinterpret_cast<const float4*>(ae_w2 + c0 + 4));
        float wv[8] = { w0.x, w0.y, w0.z, w0.w, w1.x, w1.y, w1.z, w1.w };
#pragma unroll
        for (int j = 0; j < 4; j++) {
            float p = 0.0f;
#pragma unroll
            for (int q = 0; q < 4; q++) {
                float2 f = up2(acc[j*4+q]);
                p += silu_f(f.x) * wv[2*q];
                p += silu_f(f.y) * wv[2*q+1];
            }
            p += __shfl_xor_sync(0xffffffffu, p, 1);
            p += __shfl_xor_sync(0xffffffffu, p, 2);
            if ((lane & 3) == 0) atomicAdd(&sES[e0 + j], p);
        }
    }
    __syncthreads();
    if (tid < 128) {
        int eg = e_base + tid;
        if (eg < E) {
            float s = sES[tid];
            float4 c = cd[tid];
            float f = s * c.w;
            float* dst = g_aggc + (long)rowi[tid] * 3;
            atomicAdd(dst + 0, c.x * f);
            atomicAdd(dst + 1, c.y * f);
            atomicAdd(dst + 2, c.z * f);
        }
    }
}

// ---------------- fused node kernel ----------------
// 128 nodes per CTA, 512 threads.
// smem: XnT[256][128]=32768 | YnT[128][128]=16384 | Wbuf 4096 | sES 128
#define NODE_SMEM ((256*128 + 128*128 + 4096 + 128) * 4)

__global__ void __launch_bounds__(512, 1) node_kernel(
    const float* __restrict__ h, const float* __restrict__ coordg,
    const float* __restrict__ n_w1, const float* __restrict__ n_w2,
    const float* __restrict__ n_b2,
    const float* __restrict__ ap_w1, const float* __restrict__ ap_w2,
    float* __restrict__ out, int N)
{
    extern __shared__ float sm[];
    float* XnT  = sm;
    float* YnT  = XnT + 256 * 128;
    float* Wbuf = YnT + 128 * 128;
    float* sES  = Wbuf + 4096;

    const int tid = threadIdx.x;
    const int nb = blockIdx.x * 128;

    // ------- stage XnT: rows 0..127 = h^T, rows 128..255 = agg^T -------
    {
        const int el = tid & 127, part = tid >> 7;
        int n = nb + el;
        bool v = n < N;
        long nn = v ? (long)n : 0;
        const float4* srcp = (part < 2)
            ? reinterpret_cast<const float4*>(h) + nn * 32 + (part & 1) * 16
            : reinterpret_cast<const float4*>(g_agg) + nn * 32 + (part & 1) * 16;
        int k0 = (part & 1) * 64 + ((part >= 2) ? 128 : 0);
#pragma unroll
        for (int i = 0; i < 16; i++) {
            float4 a = v ? __ldg(srcp + i) : make_float4(0.f, 0.f, 0.f, 0.f);
            int k = k0 + 4 * i;
            XnT[(k+0)*128 + el] = a.x; XnT[(k+1)*128 + el] = a.y;
            XnT[(k+2)*128 + el] = a.z; XnT[(k+3)*128 + el] = a.w;
        }
    }

    const int warp = tid >> 5, lane = tid & 31;
    const int e0 = (warp >> 2) * 32 + (lane >> 2) * 4;
    const int c0 = (warp & 3) * 32 + (lane & 3) * 8;

    UL acc[16];

    // ------- node GEMM1 (K=256): [h|agg] @ n_w1 + nb1 -> SiLU -> YnT ----
    init_acc_bias(g_nb1, c0, acc);
    gemm_smem_t<256>(XnT, n_w1, Wbuf, tid, e0, c0, acc);
    epilogue_silu_T(acc, YnT, e0, c0);

    // ------- node GEMM2: @ n_w2 + n_b2 -> SiLU -> h_out = h + . --------
    init_acc_bias(n_b2, c0, acc);
    gemm_smem_t<128>(YnT, n_w2, Wbuf, tid, e0, c0, acc);
    {
        float ho[4][8];
#pragma unroll
        for (int p = 0; p < 4; p++) {
            float2 f0 = up2(acc[0*4+p]), f1 = up2(acc[1*4+p]);
            float2 f2 = up2(acc[2*4+p]), f3 = up2(acc[3*4+p]);
            float4 hA = *reinterpret_cast<const float4*>(XnT + (c0 + 2*p) * 128 + e0);
            float4 hB = *reinterpret_cast<const float4*>(XnT + (c0 + 2*p + 1) * 128 + e0);
            ho[0][2*p] = silu_f(f0.x) + hA.x; ho[1][2*p] = silu_f(f1.x) + hA.y;
            ho[2][2*p] = silu_f(f2.x) + hA.z; ho[3][2*p] = silu_f(f3.x) + hA.w;
            ho[0][2*p+1] = silu_f(f0.y) + hB.x; ho[1][2*p+1] = silu_f(f1.y) + hB.y;
            ho[2][2*p+1] = silu_f(f2.y) + hB.z; ho[3][2*p+1] = silu_f(f3.y) + hB.w;
        }
#pragma unroll
        for (int p = 0; p < 8; p++) {
            *reinterpret_cast<float4*>(YnT + (c0 + p) * 128 + e0) =
                make_float4(ho[0][p], ho[1][p], ho[2][p], ho[3][p]);
        }
#pragma unroll
        for (int j = 0; j < 4; j++) {
            int n = nb + e0 + j;
            if (n < N) {
                float* o = out + (long)n * 128 + c0;
                *reinterpret_cast<float4*>(o) =
                    make_float4(ho[j][0], ho[j][1], ho[j][2], ho[j][3]);
                *reinterpret_cast<float4*>(o + 4) =
                    make_float4(ho[j][4], ho[j][5], ho[j][6], ho[j][7]);
            }
        }
    }
    if (tid < 128) sES[tid] = 0.0f;

    // ------- acc-point MLP: h_out @ ap_w1 + apb1 -> SiLU -> dot ap_w2 ---
    init_acc_bias(g_apb1, c0, acc);
    gemm_smem_t<128>(YnT, ap_w1, Wbuf, tid, e0, c0, acc);
    {
        float4 w0 = __ldg(reinterpret_cast<const float4*>(ap_w2 + c0));
        float4 w1 = __ldg(reinterpret_cast<const float4*>(ap_w2 + c0 + 4));
        float wv[8] = { w0.x, w0.y, w0.z, w0.w, w1.x, w1.y, w1.z, w1.w };
#pragma unroll
        for (int j = 0; j < 4; j++) {
            float p = 0.0f;
#pragma unroll
            for (int q = 0; q < 4; q++) {
                float2 f = up2(acc[j*4+q]);
                p += silu_f(f.x) * wv[2*q];
                p += silu_f(f.y) * wv[2*q+1];
            }
            p += __shfl_xor_sync(0xffffffffu, p, 1);
            p += __shfl_xor_sync(0xffffffffu, p, 2);
            if ((lane & 3) == 0) atomicAdd(&sES[e0 + j], p);
        }
    }
    __syncthreads();
    if (tid < 128) {
        int n = nb + tid;
        if (n < N) {
            float s = sES[tid];
            long base_c = (long)N * 128;
            long base_a = (long)N * 131;
            out[base_c + (long)n*3 + 0] = coordg[n*3+0];
            out[base_c + (long)n*3 + 1] = coordg[n*3+1];
            out[base_c + (long)n*3 + 2] = coordg[n*3+2];
            out[base_a + (long)n*3 + 0] = g_aggc[n*3+0] * s;
            out[base_a + (long)n*3 + 1] = g_aggc[n*3+1] * s;
            out[base_a + (long)n*3 + 2] = g_aggc[n*3+2] * s;
        }
    }
}

// ---------------- launch ----------------
extern "C" void kernel_launch(void* const* d_in, const int* in_sizes, int n_in,
                              void* d_out, int out_size)
{
    const float* h      = (const float*)d_in[0];
    const int*   ei     = (const int*)  d_in[1];
    const float* coord  = (const float*)d_in[2];
    const float* eattr  = (const float*)d_in[3];
    const float* prompt = (const float*)d_in[4];
    const float* e_w1   = (const float*)d_in[5];
    const float* e_b1   = (const float*)d_in[6];
    const float* e_w2   = (const float*)d_in[7];
    const float* e_b2   = (const float*)d_in[8];
    const float* n_w1   = (const float*)d_in[9];
    const float* n_b1   = (const float*)d_in[10];
    const float* n_w2   = (const float*)d_in[11];
    const float* n_b2   = (const float*)d_in[12];
    const float* ae_w1  = (const float*)d_in[13];
    const float* ae_b1  = (const float*)d_in[14];
    const float* ae_w2  = (const float*)d_in[15];
    const float* ap_w1  = (const float*)d_in[16];
    const float* ap_b1  = (const float*)d_in[17];
    const float* ap_w2  = (const float*)d_in[18];
    float* out = (float*)d_out;

    int N = in_sizes[0] / 128;
    int E = in_sizes[1] / 2;

    cudaFuncSetAttribute(proj_kernel, cudaFuncAttributeMaxDynamicSharedMemorySize, PROJ_SMEM);
    cudaFuncSetAttribute(edge_kernel, cudaFuncAttributeMaxDynamicSharedMemorySize, EDGE_SMEM);
    cudaFuncSetAttribute(node_kernel, cudaFuncAttributeMaxDynamicSharedMemorySize, NODE_SMEM);

    prep_kernel<<<4, 128>>>(prompt, e_w1, e_b1, n_w1, n_b1, ae_w1, ae_b1, ap_w1, ap_b1);
    zero_kernel<<<264, 256>>>(N);
    proj_kernel<<<(N + 127) / 128, 512, PROJ_SMEM>>>(h, e_w1, N);
    edge_kernel<<<(E + 127) / 128, 512, EDGE_SMEM>>>(ei, coord, eattr,
                                                     e_w1, e_w2, e_b2, ae_w1, ae_w2, E);
    node_kernel<<<(N + 127) / 128, 512, NODE_SMEM>>>(h, coord, n_w1, n_w2, n_b2,
                                                     ap_w1, ap_w2, out, N);
}

// round 10
// speedup vs baseline: 2.4848x; 1.1224x over previous
#include <cuda_runtime.h>

typedef unsigned long long UL;

// ---------------- device scratch (no allocations allowed) ----------------
__device__ float g_agg [50000 * 128];   // segment-sum of edge_feat per node
__device__ float g_aggc[50000 * 3];     // segment-sum of trans per node
__device__ float g_P   [50048 * 256];   // per-node projections [P1 | P2]
__device__ float g_eb1 [128];           // e_b1  + prompt @ e_w1[273:401]
__device__ float g_nb1 [128];           // n_b1  + prompt @ n_w1[256:384]
__device__ float g_aeb1[128];           // ae_b1 + prompt @ ae_w1[128:256]
__device__ float g_apb1[128];           // ap_b1 + prompt @ ap_w1[128:256]

// ---------------- small helpers ----------------
__device__ __forceinline__ UL bc2(float x) {
    UL r; asm("mov.b64 %0,{%1,%1};" : "=l"(r) : "f"(x)); return r;
}
__device__ __forceinline__ UL pk2(float x, float y) {
    UL r; asm("mov.b64 %0,{%1,%2};" : "=l"(r) : "f"(x), "f"(y)); return r;
}
__device__ __forceinline__ float2 up2(UL v) {
    float2 f; asm("mov.b64 {%0,%1},%2;" : "=f"(f.x), "=f"(f.y) : "l"(v)); return f;
}
__device__ __forceinline__ void fma2(UL &d, UL a, UL b) {
    asm("fma.rn.f32x2 %0,%1,%2,%0;" : "+l"(d) : "l"(a), "l"(b));
}
__device__ __forceinline__ float silu_f(float x) {
    return __fdividef(x, 1.0f + __expf(-x));
}
__device__ __forceinline__ void cpa16(unsigned dst, const float* src) {
    asm volatile("cp.async.cg.shared.global [%0], [%1], 16;" :: "r"(dst), "l"(src));
}
#define CPA_COMMIT() asm volatile("cp.async.commit_group;" ::: "memory")

// 16 packed FMAs for one k-row: 4 rows x 4 col-pairs
#define FMAROW(WA, WB, S0, S1, S2, S3)                            \
    do {                                                          \
        fma2(acc[0],  S0, WA.x); fma2(acc[1],  S0, WA.y);         \
        fma2(acc[2],  S0, WB.x); fma2(acc[3],  S0, WB.y);         \
        fma2(acc[4],  S1, WA.x); fma2(acc[5],  S1, WA.y);         \
        fma2(acc[6],  S1, WB.x); fma2(acc[7],  S1, WB.y);         \
        fma2(acc[8],  S2, WA.x); fma2(acc[9],  S2, WA.y);         \
        fma2(acc[10], S2, WB.x); fma2(acc[11], S2, WB.y);         \
        fma2(acc[12], S3, WA.x); fma2(acc[13], S3, WA.y);         \
        fma2(acc[14], S3, WB.x); fma2(acc[15], S3, WB.y);         \
    } while (0)

__device__ __forceinline__ void init_acc_bias(const float* biasg, int c0, UL* acc)
{
    float4 b0 = __ldg(reinterpret_cast<const float4*>(biasg + c0));
    float4 b1 = __ldg(reinterpret_cast<const float4*>(biasg + c0 + 4));
    UL bp0 = pk2(b0.x, b0.y), bp1 = pk2(b0.z, b0.w);
    UL bp2 = pk2(b1.x, b1.y), bp3 = pk2(b1.z, b1.w);
#pragma unroll
    for (int j = 0; j < 4; j++) {
        acc[j*4+0] = bp0; acc[j*4+1] = bp1; acc[j*4+2] = bp2; acc[j*4+3] = bp3;
    }
}
__device__ __forceinline__ void init_acc_zero(UL* acc)
{
    UL z = pk2(0.0f, 0.0f);
#pragma unroll
    for (int j = 0; j < 16; j++) acc[j] = z;
}

// ------- GEMM on TRANSPOSED X tile (64-wide), cp.async smem weights -----
// XsT: [K][64] smem (k-row reads contiguous -> LDS.128, conflict-free).
// Wg: global row-major [>=ceil16(K)][128]. Weights staged through
// Wbuf[2][16*128] in 16-row chunks (two cp.async.16 per thread, 256 thr).
// Thread owns 4 rows x 8 cols; caller pre-initializes acc[16].
template<int K>
__device__ __forceinline__ void gemm64(
    const float* XsT, const float* __restrict__ Wg,
    float* Wbuf, int tid, int e0, int c0, UL* acc)
{
    constexpr int CH = (K + 15) / 16;

    // per-thread staging: 32B (8 floats) at linear offset tid*8
    const float* src = Wg + tid * 8;
    unsigned dstb = (unsigned)__cvta_generic_to_shared(Wbuf) + tid * 32;

    cpa16(dstb, src);
    cpa16(dstb + 16, src + 4);
    CPA_COMMIT();

    const float* xb = XsT + e0;

    for (int c = 0; c < CH; c++) {
        if (c + 1 < CH) {
            unsigned d2 = dstb + ((c + 1) & 1) * 8192;
            const float* s2 = src + (c + 1) * 2048;
            cpa16(d2, s2);
            cpa16(d2 + 16, s2 + 4);
            CPA_COMMIT();
            asm volatile("cp.async.wait_group 1;" ::: "memory");
        } else {
            asm volatile("cp.async.wait_group 0;" ::: "memory");
        }
        __syncthreads();

        const float* wb = Wbuf + (c & 1) * 2048 + c0;
        const int kb = c * 16;
        if (kb + 16 <= K) {
#pragma unroll
            for (int kk = 0; kk < 16; kk++) {
                float4 xv = *reinterpret_cast<const float4*>(xb + (kb + kk) * 64);
                ulonglong2 a = *reinterpret_cast<const ulonglong2*>(wb + kk * 128);
                ulonglong2 b = *reinterpret_cast<const ulonglong2*>(wb + kk * 128 + 4);
                UL s0 = bc2(xv.x), s1 = bc2(xv.y), s2 = bc2(xv.z), s3 = bc2(xv.w);
                FMAROW(a, b, s0, s1, s2, s3);
            }
        } else {
            for (int kk = 0; kk < K - kb; kk++) {
                float4 xv = *reinterpret_cast<const float4*>(xb + (kb + kk) * 64);
                ulonglong2 a = *reinterpret_cast<const ulonglong2*>(wb + kk * 128);
                ulonglong2 b = *reinterpret_cast<const ulonglong2*>(wb + kk * 128 + 4);
                UL s0 = bc2(xv.x), s1 = bc2(xv.y), s2 = bc2(xv.z), s3 = bc2(xv.w);
                FMAROW(a, b, s0, s1, s2, s3);
            }
        }
        __syncthreads();
    }
}

// write 8 cols x 4 rows of silu(acc) into transposed tile T[col][row64]
__device__ __forceinline__ void epilogue_silu_T(
    UL* acc, float* T, int e0, int c0)
{
#pragma unroll
    for (int p = 0; p < 4; p++) {
        float2 f0 = up2(acc[0*4+p]), f1 = up2(acc[1*4+p]);
        float2 f2 = up2(acc[2*4+p]), f3 = up2(acc[3*4+p]);
        *reinterpret_cast<float4*>(T + (c0 + 2*p) * 64 + e0) =
            make_float4(silu_f(f0.x), silu_f(f1.x), silu_f(f2.x), silu_f(f3.x));
        *reinterpret_cast<float4*>(T + (c0 + 2*p + 1) * 64 + e0) =
            make_float4(silu_f(f0.y), silu_f(f1.y), silu_f(f2.y), silu_f(f3.y));
    }
}

// ---------------- prompt-bias precompute (4 blocks, one per bias) -------
__global__ void prep_kernel(
    const float* __restrict__ prompt,
    const float* __restrict__ e_w1,  const float* __restrict__ e_b1,
    const float* __restrict__ n_w1,  const float* __restrict__ n_b1,
    const float* __restrict__ ae_w1, const float* __restrict__ ae_b1,
    const float* __restrict__ ap_w1, const float* __restrict__ ap_b1)
{
    int n = threadIdx.x;
    int b = blockIdx.x;
    const float* w; const float* bias; float* dst; int off;
    if (b == 0)      { w = e_w1;  bias = e_b1;  dst = g_eb1;  off = 273; }
    else if (b == 1) { w = n_w1;  bias = n_b1;  dst = g_nb1;  off = 256; }
    else if (b == 2) { w = ae_w1; bias = ae_b1; dst = g_aeb1; off = 128; }
    else             { w = ap_w1; bias = ap_b1; dst = g_apb1; off = 128; }
    float s = bias[n];
    for (int j = 0; j < 128; j++)
        s = fmaf(prompt[j], w[(off + j) * 128 + n], s);
    dst[n] = s;
}

// ---------------- zero scratch ----------------
__global__ void zero_kernel(int N)
{
    long stride = (long)gridDim.x * blockDim.x;
    long t1 = (long)N * 128;
    for (long i = blockIdx.x * (long)blockDim.x + threadIdx.x; i < t1; i += stride)
        g_agg[i] = 0.0f;
    long t2 = (long)N * 3;
    for (long i = blockIdx.x * (long)blockDim.x + threadIdx.x; i < t2; i += stride)
        g_aggc[i] = 0.0f;
}

// ---------------- node projection kernel: g_P = h @ [W1a | W1b] ---------
// 64 nodes per CTA, 256 threads, 2 CTAs/SM.  smem: hT[128][64] | Wbuf
#define PROJ_SMEM ((128*64 + 4096) * 4)

__global__ void __launch_bounds__(256, 2) proj_kernel(
    const float* __restrict__ h, const float* __restrict__ e_w1, int N)
{
    extern __shared__ float sm[];
    float* hT   = sm;
    float* Wbuf = hT + 128 * 64;

    const int tid = threadIdx.x;
    const int nb = blockIdx.x * 64;
    {
        const int el = tid & 63, part = tid >> 6;   // part covers 32 k
        int n = nb + el;
        bool v = n < N;
        long nn = v ? (long)n : 0;
        const float4* hr = reinterpret_cast<const float4*>(h) + nn * 32 + part * 8;
#pragma unroll
        for (int i = 0; i < 8; i++) {
            float4 a = v ? __ldg(hr + i) : make_float4(0.f, 0.f, 0.f, 0.f);
            int k = part * 32 + 4 * i;
            hT[(k+0)*64 + el] = a.x; hT[(k+1)*64 + el] = a.y;
            hT[(k+2)*64 + el] = a.z; hT[(k+3)*64 + el] = a.w;
        }
    }
    const int warp = tid >> 5, lane = tid & 31;
    const int e0 = (warp >> 2) * 32 + (lane >> 2) * 4;
    const int c0 = (warp & 3) * 32 + (lane & 3) * 8;

    UL acc[16];

    // P1 = h @ e_w1[0:128]
    init_acc_zero(acc);
    gemm64<128>(hT, e_w1, Wbuf, tid, e0, c0, acc);
#pragma unroll
    for (int j = 0; j < 4; j++) {
        int n = nb + e0 + j;
        if (n < N) {
            float2 f0 = up2(acc[j*4+0]), f1 = up2(acc[j*4+1]);
            float2 f2 = up2(acc[j*4+2]), f3 = up2(acc[j*4+3]);
            float* o = g_P + (long)n * 256 + c0;
            *reinterpret_cast<float4*>(o)     = make_float4(f0.x, f0.y, f1.x, f1.y);
            *reinterpret_cast<float4*>(o + 4) = make_float4(f2.x, f2.y, f3.x, f3.y);
        }
    }

    // P2 = h @ e_w1[128:256]
    init_acc_zero(acc);
    gemm64<128>(hT, e_w1 + 128 * 128, Wbuf, tid, e0, c0, acc);
#pragma unroll
    for (int j = 0; j < 4; j++) {
        int n = nb + e0 + j;
        if (n < N) {
            float2 f0 = up2(acc[j*4+0]), f1 = up2(acc[j*4+1]);
            float2 f2 = up2(acc[j*4+2]), f3 = up2(acc[j*4+3]);
            float* o = g_P + (long)n * 256 + 128 + c0;
            *reinterpret_cast<float4*>(o)     = make_float4(f0.x, f0.y, f1.x, f1.y);
            *reinterpret_cast<float4*>(o + 4) = make_float4(f2.x, f2.y, f3.x, f3.y);
        }
    }
}

// ---------------- fused edge kernel ----------------
// 64 edges per CTA, 256 threads, 2 CTAs/SM.
// smem (floats): XeT[20][64]=1280 | YsT[128][64]=8192 | Wbuf 4096
//              | cd 256 | sES 64 | rowi 64 | coli 64  -> 56064 B
#define EDGE_SMEM ((20*64 + 128*64 + 4096 + 256 + 64 + 64 + 64) * 4)

__global__ void __launch_bounds__(256, 2) edge_kernel(
    const int* __restrict__ ei,
    const float* __restrict__ coord, const float* __restrict__ eattr,
    const float* __restrict__ e_w1, const float* __restrict__ e_w2,
    const float* __restrict__ e_b2,
    const float* __restrict__ ae_w1, const float* __restrict__ ae_w2,
    int E)
{
    extern __shared__ float sm[];
    float*  XeT  = sm;                                   // 1280
    float*  YsT  = XeT + 20 * 64;                        // 8192
    float*  Wbuf = YsT + 128 * 64;                       // 4096
    float4* cd   = reinterpret_cast<float4*>(Wbuf + 4096);   // 64 float4
    float*  sES  = reinterpret_cast<float*>(cd + 64);        // 64
    int*    rowi = reinterpret_cast<int*>(sES + 64);         // 64
    int*    coli = rowi + 64;                                // 64

    const int tid = threadIdx.x;
    const int e_base = blockIdx.x * 64;
    const int* rowg = ei;
    const int* colg = ei + E;

    // ------- stage small XeT: row0 = radial, rows 1..16 = eattr^T -------
    {
        const int el = tid & 63, part = tid >> 6;
        int e = e_base + el;
        bool v = e < E;
        if (part == 0) {
            long r = v ? (long)rowg[e] : 0;
            long c = v ? (long)colg[e] : 0;
            rowi[el] = (int)r;
            coli[el] = (int)c;
            float dx = 0.f, dy = 0.f, dz = 0.f;
            if (v) {
                dx = coord[r*3+0] - coord[c*3+0];
                dy = coord[r*3+1] - coord[c*3+1];
                dz = coord[r*3+2] - coord[c*3+2];
            }
            float rad = dx*dx + dy*dy + dz*dz;
            XeT[el] = rad;                       // k = 0
            float inv = 1.0f / fmaxf(sqrtf(rad), 1e-12f);
            cd[el] = make_float4(dx, dy, dz, inv);
        } else if (part == 1) {
            const float4* ea = reinterpret_cast<const float4*>(eattr) + (long)e * 4;
#pragma unroll
            for (int i = 0; i < 4; i++) {
                float4 a = v ? __ldg(ea + i) : make_float4(0.f, 0.f, 0.f, 0.f);
                int k = 1 + 4 * i;
                XeT[(k+0)*64 + el] = a.x; XeT[(k+1)*64 + el] = a.y;
                XeT[(k+2)*64 + el] = a.z; XeT[(k+3)*64 + el] = a.w;
            }
        }
    }
    __syncthreads();

    const int warp = tid >> 5, lane = tid & 31;
    const int e0 = (warp >> 2) * 32 + (lane >> 2) * 4;
    const int c0 = (warp & 3) * 32 + (lane & 3) * 8;

    UL acc[16];

    // ------- acc init: eb1_eff + P1[row] + P2[col]  (the K=256 part) ----
    {
        float4 b0 = __ldg(reinterpret_cast<const float4*>(g_eb1 + c0));
        float4 b1 = __ldg(reinterpret_cast<const float4*>(g_eb1 + c0 + 4));
#pragma unroll
        for (int j = 0; j < 4; j++) {
            int r = rowi[e0 + j], cc = coli[e0 + j];
            const float* pr = g_P + (long)r  * 256 + c0;
            const float* pc = g_P + (long)cc * 256 + 128 + c0;
            float4 p0 = __ldg(reinterpret_cast<const float4*>(pr));
            float4 p1 = __ldg(reinterpret_cast<const float4*>(pr + 4));
            float4 q0 = __ldg(reinterpret_cast<const float4*>(pc));
            float4 q1 = __ldg(reinterpret_cast<const float4*>(pc + 4));
            acc[j*4+0] = pk2(b0.x + p0.x + q0.x, b0.y + p0.y + q0.y);
            acc[j*4+1] = pk2(b0.z + p0.z + q0.z, b0.w + p0.w + q0.w);
            acc[j*4+2] = pk2(b1.x + p1.x + q1.x, b1.y + p1.y + q1.y);
            acc[j*4+3] = pk2(b1.z + p1.z + q1.z, b1.w + p1.w + q1.w);
        }
    }

    // ------- GEMM1 (K=17): [rad|eattr] @ e_w1[256:273] -> SiLU -> YsT ----
    gemm64<17>(XeT, e_w1 + 256 * 128, Wbuf, tid, e0, c0, acc);
    epilogue_silu_T(acc, YsT, e0, c0);

    // ------- GEMM2 (K=128): @ e_w2 + e_b2 -> SiLU = edge_feat ----------
    init_acc_bias(e_b2, c0, acc);
    gemm64<128>(YsT, e_w2, Wbuf, tid, e0, c0, acc);
    // all warps past final sync -> done reading YsT; safe to overwrite
    {
        float z[4][8];
#pragma unroll
        for (int j = 0; j < 4; j++)
#pragma unroll
            for (int p = 0; p < 4; p++) {
                float2 f = up2(acc[j*4+p]);
                z[j][2*p] = silu_f(f.x); z[j][2*p+1] = silu_f(f.y);
            }
#pragma unroll
        for (int p = 0; p < 8; p++) {
            *reinterpret_cast<float4*>(YsT + (c0 + p) * 64 + e0) =
                make_float4(z[0][p], z[1][p], z[2][p], z[3][p]);
        }
#pragma unroll
        for (int j = 0; j < 4; j++) {
            int eg = e_base + e0 + j;
            if (eg < E) {
                float* dst = g_agg + (long)rowi[e0 + j] * 128 + c0;
                atomicAdd(reinterpret_cast<float4*>(dst),
                          make_float4(z[j][0], z[j][1], z[j][2], z[j][3]));
                atomicAdd(reinterpret_cast<float4*>(dst + 4),
                          make_float4(z[j][4], z[j][5], z[j][6], z[j][7]));
            }
        }
    }
    if (tid < 64) sES[tid] = 0.0f;

    // ------- GEMM3: edge_feat @ ae_w1[0:128] + aeb1 -> SiLU -> dot ae_w2 -
    init_acc_bias(g_aeb1, c0, acc);
    gemm64<128>(YsT, ae_w1, Wbuf, tid, e0, c0, acc);
    {
        float4 w0 = __ldg(reinterpret_cast<const float4*>(ae_w2 + c0));
        float4 w1 = __ldg(reinterpret_cast<const float4*>(ae_w2 + c0 + 4));
        float wv[8] = { w0.x, w0.y, w0.z, w0.w, w1.x, w1.y, w1.z, w1.w };
#pragma unroll
        for (int j = 0; j < 4; j++) {
            float p = 0.0f;
#pragma unroll
            for (int q = 0; q < 4; q++) {
                float2 f = up2(acc[j*4+q]);
                p += silu_f(f.x) * wv[2*q];
                p += silu_f(f.y) * wv[2*q+1];
            }
            p += __shfl_xor_sync(0xffffffffu, p, 1);
            p += __shfl_xor_sync(0xffffffffu, p, 2);
            if ((lane & 3) == 0) atomicAdd(&sES[e0 + j], p);
        }
    }
    __syncthreads();
    if (tid < 64) {
        int eg = e_base + tid;
        if (eg < E) {
            float s = sES[tid];
            float4 c = cd[tid];
            float f = s * c.w;
            float* dst = g_aggc + (long)rowi[tid] * 3;
            atomicAdd(dst + 0, c.x * f);
            atomicAdd(dst + 1, c.y * f);
            atomicAdd(dst + 2, c.z * f);
        }
    }
}

// ---------------- fused node kernel ----------------
// 64 nodes per CTA, 256 threads, 2 CTAs/SM.
// smem: XnT[256][64]=16384 | YnT[128][64]=8192 | Wbuf 4096 | sES 64
#define NODE_SMEM ((256*64 + 128*64 + 4096 + 64) * 4)

__global__ void __launch_bounds__(256, 2) node_kernel(
    const float* __restrict__ h, const float* __restrict__ coordg,
    const float* __restrict__ n_w1, const float* __restrict__ n_w2,
    const float* __restrict__ n_b2,
    const float* __restrict__ ap_w1, const float* __restrict__ ap_w2,
    float* __restrict__ out, int N)
{
    extern __shared__ float sm[];
    float* XnT  = sm;
    float* YnT  = XnT + 256 * 64;
    float* Wbuf = YnT + 128 * 64;
    float* sES  = Wbuf + 4096;

    const int tid = threadIdx.x;
    const int nb = blockIdx.x * 64;

    // ------- stage XnT: rows 0..127 = h^T, rows 128..255 = agg^T -------
    {
        const int el = tid & 63, part = tid >> 6;   // 4 parts of 64 k
        int n = nb + el;
        bool v = n < N;
        long nn = v ? (long)n : 0;
        const float4* srcp = (part < 2)
            ? reinterpret_cast<const float4*>(h) + nn * 32 + (part & 1) * 16
            : reinterpret_cast<const float4*>(g_agg) + nn * 32 + (part & 1) * 16;
        int k0 = (part & 1) * 64 + ((part >= 2) ? 128 : 0);
#pragma unroll
        for (int i = 0; i < 16; i++) {
            float4 a = v ? __ldg(srcp + i) : make_float4(0.f, 0.f, 0.f, 0.f);
            int k = k0 + 4 * i;
            XnT[(k+0)*64 + el] = a.x; XnT[(k+1)*64 + el] = a.y;
            XnT[(k+2)*64 + el] = a.z; XnT[(k+3)*64 + el] = a.w;
        }
    }

    const int warp = tid >> 5, lane = tid & 31;
    const int e0 = (warp >> 2) * 32 + (lane >> 2) * 4;
    const int c0 = (warp & 3) * 32 + (lane & 3) * 8;

    UL acc[16];

    // ------- node GEMM1 (K=256): [h|agg] @ n_w1 + nb1 -> SiLU -> YnT ----
    init_acc_bias(g_nb1, c0, acc);
    gemm64<256>(XnT, n_w1, Wbuf, tid, e0, c0, acc);
    epilogue_silu_T(acc, YnT, e0, c0);

    // ------- node GEMM2: @ n_w2 + n_b2 -> SiLU -> h_out = h + . --------
    init_acc_bias(n_b2, c0, acc);
    gemm64<128>(YnT, n_w2, Wbuf, tid, e0, c0, acc);
    {
        float ho[4][8];
#pragma unroll
        for (int p = 0; p < 4; p++) {
            float2 f0 = up2(acc[0*4+p]), f1 = up2(acc[1*4+p]);
            float2 f2 = up2(acc[2*4+p]), f3 = up2(acc[3*4+p]);
            float4 hA = *reinterpret_cast<const float4*>(XnT + (c0 + 2*p) * 64 + e0);
            float4 hB = *reinterpret_cast<const float4*>(XnT + (c0 + 2*p + 1) * 64 + e0);
            ho[0][2*p] = silu_f(f0.x) + hA.x; ho[1][2*p] = silu_f(f1.x) + hA.y;
            ho[2][2*p] = silu_f(f2.x) + hA.z; ho[3][2*p] = silu_f(f3.x) + hA.w;
            ho[0][2*p+1] = silu_f(f0.y) + hB.x; ho[1][2*p+1] = silu_f(f1.y) + hB.y;
            ho[2][2*p+1] = silu_f(f2.y) + hB.z; ho[3][2*p+1] = silu_f(f3.y) + hB.w;
        }
#pragma unroll
        for (int p = 0; p < 8; p++) {
            *reinterpret_cast<float4*>(YnT + (c0 + p) * 64 + e0) =
                make_float4(ho[0][p], ho[1][p], ho[2][p], ho[3][p]);
        }
#pragma unroll
        for (int j = 0; j < 4; j++) {
            int n = nb + e0 + j;
            if (n < N) {
                float* o = out + (long)n * 128 + c0;
                *reinterpret_cast<float4*>(o) =
                    make_float4(ho[j][0], ho[j][1], ho[j][2], ho[j][3]);
                *reinterpret_cast<float4*>(o + 4) =
                    make_float4(ho[j][4], ho[j][5], ho[j][6], ho[j][7]);
            }
        }
    }
    if (tid < 64) sES[tid] = 0.0f;

    // ------- acc-point MLP: h_out @ ap_w1 + apb1 -> SiLU -> dot ap_w2 ---
    init_acc_bias(g_apb1, c0, acc);
    gemm64<128>(YnT, ap_w1, Wbuf, tid, e0, c0, acc);
    {
        float4 w0 = __ldg(reinterpret_cast<const float4*>(ap_w2 + c0));
        float4 w1 = __ldg(reinterpret_cast<const float4*>(ap_w2 + c0 + 4));
        float wv[8] = { w0.x, w0.y, w0.z, w0.w, w1.x, w1.y, w1.z, w1.w };
#pragma unroll
        for (int j = 0; j < 4; j++) {
            float p = 0.0f;
#pragma unroll
            for (int q = 0; q < 4; q++) {
                float2 f = up2(acc[j*4+q]);
                p += silu_f(f.x) * wv[2*q];
                p += silu_f(f.y) * wv[2*q+1];
            }
            p += __shfl_xor_sync(0xffffffffu, p, 1);
            p += __shfl_xor_sync(0xffffffffu, p, 2);
            if ((lane & 3) == 0) atomicAdd(&sES[e0 + j], p);
        }
    }
    __syncthreads();
    if (tid < 64) {
        int n = nb + tid;
        if (n < N) {
            float s = sES[tid];
            long base_c = (long)N * 128;
            long base_a = (long)N * 131;
            out[base_c + (long)n*3 + 0] = coordg[n*3+0];
            out[base_c + (long)n*3 + 1] = coordg[n*3+1];
            out[base_c + (long)n*3 + 2] = coordg[n*3+2];
            out[base_a + (long)n*3 + 0] = g_aggc[n*3+0] * s;
            out[base_a + (long)n*3 + 1] = g_aggc[n*3+1] * s;
            out[base_a + (long)n*3 + 2] = g_aggc[n*3+2] * s;
        }
    }
}

// ---------------- launch ----------------
extern "C" void kernel_launch(void* const* d_in, const int* in_sizes, int n_in,
                              void* d_out, int out_size)
{
    const float* h      = (const float*)d_in[0];
    const int*   ei     = (const int*)  d_in[1];
    const float* coord  = (const float*)d_in[2];
    const float* eattr  = (const float*)d_in[3];
    const float* prompt = (const float*)d_in[4];
    const float* e_w1   = (const float*)d_in[5];
    const float* e_b1   = (const float*)d_in[6];
    const float* e_w2   = (const float*)d_in[7];
    const float* e_b2   = (const float*)d_in[8];
    const float* n_w1   = (const float*)d_in[9];
    const float* n_b1   = (const float*)d_in[10];
    const float* n_w2   = (const float*)d_in[11];
    const float* n_b2   = (const float*)d_in[12];
    const float* ae_w1  = (const float*)d_in[13];
    const float* ae_b1  = (const float*)d_in[14];
    const float* ae_w2  = (const float*)d_in[15];
    const float* ap_w1  = (const float*)d_in[16];
    const float* ap_b1  = (const float*)d_in[17];
    const float* ap_w2  = (const float*)d_in[18];
    float* out = (float*)d_out;

    int N = in_sizes[0] / 128;
    int E = in_sizes[1] / 2;

    cudaFuncSetAttribute(proj_kernel, cudaFuncAttributeMaxDynamicSharedMemorySize, PROJ_SMEM);
    cudaFuncSetAttribute(edge_kernel, cudaFuncAttributeMaxDynamicSharedMemorySize, EDGE_SMEM);
    cudaFuncSetAttribute(node_kernel, cudaFuncAttributeMaxDynamicSharedMemorySize, NODE_SMEM);

    prep_kernel<<<4, 128>>>(prompt, e_w1, e_b1, n_w1, n_b1, ae_w1, ae_b1, ap_w1, ap_b1);
    zero_kernel<<<264, 256>>>(N);
    proj_kernel<<<(N + 63) / 64, 256, PROJ_SMEM>>>(h, e_w1, N);
    edge_kernel<<<(E + 63) / 64, 256, EDGE_SMEM>>>(ei, coord, eattr,
                                                   e_w1, e_w2, e_b2, ae_w1, ae_w2, E);
    node_kernel<<<(N + 63) / 64, 256, NODE_SMEM>>>(h, coord, n_w1, n_w2, n_b2,
                                                   ap_w1, ap_w2, out, N);
}

// round 11
// speedup vs baseline: 2.5333x; 1.0195x over previous
#include <cuda_runtime.h>

typedef unsigned long long UL;

// ---------------- device scratch (no allocations allowed) ----------------
__device__ float g_agg [50000 * 128];   // segment-sum of edge_feat per node
__device__ float g_aggc[50000 * 3];     // segment-sum of trans per node
__device__ float g_P   [50048 * 256];   // per-node projections [P1 | P2]
__device__ float g_eb1 [128];           // e_b1  + prompt @ e_w1[273:401]
__device__ float g_nb1 [128];           // n_b1  + prompt @ n_w1[256:384]
__device__ float g_aeb1[128];           // ae_b1 + prompt @ ae_w1[128:256]
__device__ float g_apb1[128];           // ap_b1 + prompt @ ap_w1[128:256]

// ---------------- small helpers ----------------
__device__ __forceinline__ UL bc2(float x) {
    UL r; asm("mov.b64 %0,{%1,%1};" : "=l"(r) : "f"(x)); return r;
}
__device__ __forceinline__ UL pk2(float x, float y) {
    UL r; asm("mov.b64 %0,{%1,%2};" : "=l"(r) : "f"(x), "f"(y)); return r;
}
__device__ __forceinline__ float2 up2(UL v) {
    float2 f; asm("mov.b64 {%0,%1},%2;" : "=f"(f.x), "=f"(f.y) : "l"(v)); return f;
}
__device__ __forceinline__ void fma2(UL &d, UL a, UL b) {
    asm("fma.rn.f32x2 %0,%1,%2,%0;" : "+l"(d) : "l"(a), "l"(b));
}
__device__ __forceinline__ float silu_f(float x) {
    return __fdividef(x, 1.0f + __expf(-x));
}
__device__ __forceinline__ void cpa16(unsigned dst, const float* src) {
    asm volatile("cp.async.cg.shared.global [%0], [%1], 16;" :: "r"(dst), "l"(src));
}
#define CPA_COMMIT() asm volatile("cp.async.commit_group;" ::: "memory")

// 16 packed FMAs for one k-row: 4 rows x 4 col-pairs
#define FMAROW(WA, WB, S0, S1, S2, S3)                            \
    do {                                                          \
        fma2(acc[0],  S0, WA.x); fma2(acc[1],  S0, WA.y);         \
        fma2(acc[2],  S0, WB.x); fma2(acc[3],  S0, WB.y);         \
        fma2(acc[4],  S1, WA.x); fma2(acc[5],  S1, WA.y);         \
        fma2(acc[6],  S1, WB.x); fma2(acc[7],  S1, WB.y);         \
        fma2(acc[8],  S2, WA.x); fma2(acc[9],  S2, WA.y);         \
        fma2(acc[10], S2, WB.x); fma2(acc[11], S2, WB.y);         \
        fma2(acc[12], S3, WA.x); fma2(acc[13], S3, WA.y);         \
        fma2(acc[14], S3, WB.x); fma2(acc[15], S3, WB.y);         \
    } while (0)

__device__ __forceinline__ void init_acc_bias(const float* biasg, int c0, UL* acc)
{
    float4 b0 = __ldg(reinterpret_cast<const float4*>(biasg + c0));
    float4 b1 = __ldg(reinterpret_cast<const float4*>(biasg + c0 + 4));
    UL bp0 = pk2(b0.x, b0.y), bp1 = pk2(b0.z, b0.w);
    UL bp2 = pk2(b1.x, b1.y), bp3 = pk2(b1.z, b1.w);
#pragma unroll
    for (int j = 0; j < 4; j++) {
        acc[j*4+0] = bp0; acc[j*4+1] = bp1; acc[j*4+2] = bp2; acc[j*4+3] = bp3;
    }
}
__device__ __forceinline__ void init_acc_zero(UL* acc)
{
    UL z = pk2(0.0f, 0.0f);
#pragma unroll
    for (int j = 0; j < 16; j++) acc[j] = z;
}

// ------- GEMM on TRANSPOSED X tile (64-wide), cp.async ring pipeline ----
// XsT: [K][64] smem (k-row reads contiguous -> LDS.128, conflict-free).
// Wg: global row-major [>=ceil16(K)][128]. Weights flow through a
// DEPTH-slot ring (16 k-rows = 8192B per slot), ONE __syncthreads per
// chunk: wait -> sync (visibility + consume-before-overwrite) -> issue
// chunk c+DEPTH-1 -> consume chunk c.  Uniform group accounting via
// always-commit (empty groups near the tail).
// Thread owns 4 rows x 8 cols; caller pre-initializes acc[16].
template<int K, int DEPTH>
__device__ __forceinline__ void gemm64(
    const float* XsT, const float* __restrict__ Wg,
    float* Wbuf, int tid, int e0, int c0, UL* acc)
{
    constexpr int CH = (K + 15) / 16;

    // per-thread staging: 32B (8 floats) at linear offset tid*8
    const float* src = Wg + tid * 8;
    unsigned dstb = (unsigned)__cvta_generic_to_shared(Wbuf) + tid * 32;

#pragma unroll
    for (int p = 0; p < DEPTH - 1; p++) {
        if (p < CH) {
            unsigned d = dstb + p * 8192;
            const float* s = src + p * 2048;
            cpa16(d, s);
            cpa16(d + 16, s + 4);
        }
        CPA_COMMIT();
    }

    const float* xb = XsT + e0;
    int cons = 0;
    int nxt = (DEPTH - 1) % DEPTH;

    for (int c = 0; c < CH; c++) {
        asm volatile("cp.async.wait_group %0;" :: "n"(DEPTH - 2) : "memory");
        __syncthreads();
        if (c + DEPTH - 1 < CH) {
            unsigned d = dstb + nxt * 8192;
            const float* s = src + (c + DEPTH - 1) * 2048;
            cpa16(d, s);
            cpa16(d + 16, s + 4);
        }
        CPA_COMMIT();

        const float* wb = Wbuf + cons * 2048 + c0;
        const int kb = c * 16;
        const float* xk = xb + kb * 64;
        if (kb + 16 <= K) {
#pragma unroll
            for (int kk = 0; kk < 16; kk++) {
                float4 xv = *reinterpret_cast<const float4*>(xk + kk * 64);
                ulonglong2 a = *reinterpret_cast<const ulonglong2*>(wb + kk * 128);
                ulonglong2 b = *reinterpret_cast<const ulonglong2*>(wb + kk * 128 + 4);
                UL s0 = bc2(xv.x), s1 = bc2(xv.y), s2 = bc2(xv.z), s3 = bc2(xv.w);
                FMAROW(a, b, s0, s1, s2, s3);
            }
        } else {
            for (int kk = 0; kk < K - kb; kk++) {
                float4 xv = *reinterpret_cast<const float4*>(xk + kk * 64);
                ulonglong2 a = *reinterpret_cast<const ulonglong2*>(wb + kk * 128);
                ulonglong2 b = *reinterpret_cast<const ulonglong2*>(wb + kk * 128 + 4);
                UL s0 = bc2(xv.x), s1 = bc2(xv.y), s2 = bc2(xv.z), s3 = bc2(xv.w);
                FMAROW(a, b, s0, s1, s2, s3);
            }
        }
        cons++; if (cons == DEPTH) cons = 0;
        nxt++;  if (nxt == DEPTH)  nxt = 0;
    }
    // drain (remaining groups are empty) + protect Wbuf/tiles for the caller
    asm volatile("cp.async.wait_group 0;" ::: "memory");
    __syncthreads();
}

// write 8 cols x 4 rows of silu(acc) into transposed tile T[col][row64]
__device__ __forceinline__ void epilogue_silu_T(
    UL* acc, float* T, int e0, int c0)
{
#pragma unroll
    for (int p = 0; p < 4; p++) {
        float2 f0 = up2(acc[0*4+p]), f1 = up2(acc[1*4+p]);
        float2 f2 = up2(acc[2*4+p]), f3 = up2(acc[3*4+p]);
        *reinterpret_cast<float4*>(T + (c0 + 2*p) * 64 + e0) =
            make_float4(silu_f(f0.x), silu_f(f1.x), silu_f(f2.x), silu_f(f3.x));
        *reinterpret_cast<float4*>(T + (c0 + 2*p + 1) * 64 + e0) =
            make_float4(silu_f(f0.y), silu_f(f1.y), silu_f(f2.y), silu_f(f3.y));
    }
}

// ---------------- prompt-bias precompute (4 blocks, one per bias) -------
__global__ void prep_kernel(
    const float* __restrict__ prompt,
    const float* __restrict__ e_w1,  const float* __restrict__ e_b1,
    const float* __restrict__ n_w1,  const float* __restrict__ n_b1,
    const float* __restrict__ ae_w1, const float* __restrict__ ae_b1,
    const float* __restrict__ ap_w1, const float* __restrict__ ap_b1)
{
    int n = threadIdx.x;
    int b = blockIdx.x;
    const float* w; const float* bias; float* dst; int off;
    if (b == 0)      { w = e_w1;  bias = e_b1;  dst = g_eb1;  off = 273; }
    else if (b == 1) { w = n_w1;  bias = n_b1;  dst = g_nb1;  off = 256; }
    else if (b == 2) { w = ae_w1; bias = ae_b1; dst = g_aeb1; off = 128; }
    else             { w = ap_w1; bias = ap_b1; dst = g_apb1; off = 128; }
    float s = bias[n];
    for (int j = 0; j < 128; j++)
        s = fmaf(prompt[j], w[(off + j) * 128 + n], s);
    dst[n] = s;
}

// ---------------- node projection kernel: g_P = h @ [W1a | W1b] ---------
// Also zeros g_agg / g_aggc for its 64 nodes (replaces zero_kernel).
// 64 nodes per CTA, 256 threads, 2 CTAs/SM.  smem: hT[128][64] | Wbuf[4]
#define PROJ_SMEM ((128*64 + 4*2048) * 4)

__global__ void __launch_bounds__(256, 2) proj_kernel(
    const float* __restrict__ h, const float* __restrict__ e_w1, int N)
{
    extern __shared__ float sm[];
    float* hT   = sm;
    float* Wbuf = hT + 128 * 64;

    const int tid = threadIdx.x;
    const int nb = blockIdx.x * 64;

    // zero scratch for this CTA's nodes
    {
        const int el = tid & 63, part = tid >> 6;
        int n = nb + el;
        if (n < N) {
            float4 z4 = make_float4(0.f, 0.f, 0.f, 0.f);
            float4* ga = reinterpret_cast<float4*>(g_agg + (long)n * 128) + part * 8;
#pragma unroll
            for (int i = 0; i < 8; i++) ga[i] = z4;
            if (part == 0) {
                g_aggc[(long)n*3+0] = 0.f;
                g_aggc[(long)n*3+1] = 0.f;
                g_aggc[(long)n*3+2] = 0.f;
            }
        }
    }

    {
        const int el = tid & 63, part = tid >> 6;   // part covers 32 k
        int n = nb + el;
        bool v = n < N;
        long nn = v ? (long)n : 0;
        const float4* hr = reinterpret_cast<const float4*>(h) + nn * 32 + part * 8;
#pragma unroll
        for (int i = 0; i < 8; i++) {
            float4 a = v ? __ldg(hr + i) : make_float4(0.f, 0.f, 0.f, 0.f);
            int k = part * 32 + 4 * i;
            hT[(k+0)*64 + el] = a.x; hT[(k+1)*64 + el] = a.y;
            hT[(k+2)*64 + el] = a.z; hT[(k+3)*64 + el] = a.w;
        }
    }
    const int warp = tid >> 5, lane = tid & 31;
    const int e0 = (warp >> 2) * 32 + (lane >> 2) * 4;
    const int c0 = (warp & 3) * 32 + (lane & 3) * 8;

    UL acc[16];

    // P1 = h @ e_w1[0:128]
    init_acc_zero(acc);
    gemm64<128, 4>(hT, e_w1, Wbuf, tid, e0, c0, acc);
#pragma unroll
    for (int j = 0; j < 4; j++) {
        int n = nb + e0 + j;
        if (n < N) {
            float2 f0 = up2(acc[j*4+0]), f1 = up2(acc[j*4+1]);
            float2 f2 = up2(acc[j*4+2]), f3 = up2(acc[j*4+3]);
            float* o = g_P + (long)n * 256 + c0;
            *reinterpret_cast<float4*>(o)     = make_float4(f0.x, f0.y, f1.x, f1.y);
            *reinterpret_cast<float4*>(o + 4) = make_float4(f2.x, f2.y, f3.x, f3.y);
        }
    }

    // P2 = h @ e_w1[128:256]
    init_acc_zero(acc);
    gemm64<128, 4>(hT, e_w1 + 128 * 128, Wbuf, tid, e0, c0, acc);
#pragma unroll
    for (int j = 0; j < 4; j++) {
        int n = nb + e0 + j;
        if (n < N) {
            float2 f0 = up2(acc[j*4+0]), f1 = up2(acc[j*4+1]);
            float2 f2 = up2(acc[j*4+2]), f3 = up2(acc[j*4+3]);
            float* o = g_P + (long)n * 256 + 128 + c0;
            *reinterpret_cast<float4*>(o)     = make_float4(f0.x, f0.y, f1.x, f1.y);
            *reinterpret_cast<float4*>(o + 4) = make_float4(f2.x, f2.y, f3.x, f3.y);
        }
    }
}

// ---------------- fused edge kernel ----------------
// 64 edges per CTA, 256 threads, 2 CTAs/SM.
// smem (floats): XeT[20][64]=1280 | YsT[128][64]=8192 | Wbuf[3*2048]=6144
//              | cd 256 | sES 64 | rowi 64 | coli 64  -> 64256 B
#define EDGE_SMEM ((20*64 + 128*64 + 3*2048 + 256 + 64 + 64 + 64) * 4)

__global__ void __launch_bounds__(256, 2) edge_kernel(
    const int* __restrict__ ei,
    const float* __restrict__ coord, const float* __restrict__ eattr,
    const float* __restrict__ e_w1, const float* __restrict__ e_w2,
    const float* __restrict__ e_b2,
    const float* __restrict__ ae_w1, const float* __restrict__ ae_w2,
    int E)
{
    extern __shared__ float sm[];
    float*  XeT  = sm;                                   // 1280
    float*  YsT  = XeT + 20 * 64;                        // 8192
    float*  Wbuf = YsT + 128 * 64;                       // 6144
    float4* cd   = reinterpret_cast<float4*>(Wbuf + 3 * 2048);   // 64 float4
    float*  sES  = reinterpret_cast<float*>(cd + 64);        // 64
    int*    rowi = reinterpret_cast<int*>(sES + 64);         // 64
    int*    coli = rowi + 64;                                // 64

    const int tid = threadIdx.x;
    const int e_base = blockIdx.x * 64;
    const int* rowg = ei;
    const int* colg = ei + E;

    // ------- stage small XeT: row0 = radial, rows 1..16 = eattr^T -------
    {
        const int el = tid & 63, part = tid >> 6;
        int e = e_base + el;
        bool v = e < E;
        if (part == 0) {
            long r = v ? (long)rowg[e] : 0;
            long c = v ? (long)colg[e] : 0;
            rowi[el] = (int)r;
            coli[el] = (int)c;
            float dx = 0.f, dy = 0.f, dz = 0.f;
            if (v) {
                dx = coord[r*3+0] - coord[c*3+0];
                dy = coord[r*3+1] - coord[c*3+1];
                dz = coord[r*3+2] - coord[c*3+2];
            }
            float rad = dx*dx + dy*dy + dz*dz;
            XeT[el] = rad;                       // k = 0
            float inv = 1.0f / fmaxf(sqrtf(rad), 1e-12f);
            cd[el] = make_float4(dx, dy, dz, inv);
        } else if (part == 1) {
            const float4* ea = reinterpret_cast<const float4*>(eattr) + (long)e * 4;
#pragma unroll
            for (int i = 0; i < 4; i++) {
                float4 a = v ? __ldg(ea + i) : make_float4(0.f, 0.f, 0.f, 0.f);
                int k = 1 + 4 * i;
                XeT[(k+0)*64 + el] = a.x; XeT[(k+1)*64 + el] = a.y;
                XeT[(k+2)*64 + el] = a.z; XeT[(k+3)*64 + el] = a.w;
            }
        }
    }
    __syncthreads();

    const int warp = tid >> 5, lane = tid & 31;
    const int e0 = (warp >> 2) * 32 + (lane >> 2) * 4;
    const int c0 = (warp & 3) * 32 + (lane & 3) * 8;

    UL acc[16];

    // ------- acc init: eb1_eff + P1[row] + P2[col]  (the K=256 part) ----
    {
        float4 b0 = __ldg(reinterpret_cast<const float4*>(g_eb1 + c0));
        float4 b1 = __ldg(reinterpret_cast<const float4*>(g_eb1 + c0 + 4));
#pragma unroll
        for (int j = 0; j < 4; j++) {
            int r = rowi[e0 + j], cc = coli[e0 + j];
            const float* pr = g_P + (long)r  * 256 + c0;
            const float* pc = g_P + (long)cc * 256 + 128 + c0;
            float4 p0 = __ldg(reinterpret_cast<const float4*>(pr));
            float4 p1 = __ldg(reinterpret_cast<const float4*>(pr + 4));
            float4 q0 = __ldg(reinterpret_cast<const float4*>(pc));
            float4 q1 = __ldg(reinterpret_cast<const float4*>(pc + 4));
            acc[j*4+0] = pk2(b0.x + p0.x + q0.x, b0.y + p0.y + q0.y);
            acc[j*4+1] = pk2(b0.z + p0.z + q0.z, b0.w + p0.w + q0.w);
            acc[j*4+2] = pk2(b1.x + p1.x + q1.x, b1.y + p1.y + q1.y);
            acc[j*4+3] = pk2(b1.z + p1.z + q1.z, b1.w + p1.w + q1.w);
        }
    }

    // ------- GEMM1 (K=17): [rad|eattr] @ e_w1[256:273] -> SiLU -> YsT ----
    gemm64<17, 3>(XeT, e_w1 + 256 * 128, Wbuf, tid, e0, c0, acc);
    epilogue_silu_T(acc, YsT, e0, c0);

    // ------- GEMM2 (K=128): @ e_w2 + e_b2 -> SiLU = edge_feat ----------
    init_acc_bias(e_b2, c0, acc);
    gemm64<128, 3>(YsT, e_w2, Wbuf, tid, e0, c0, acc);
    // trailing sync of gemm64 ordered every warp's reads; safe to overwrite
    {
        float z[4][8];
#pragma unroll
        for (int j = 0; j < 4; j++)
#pragma unroll
            for (int p = 0; p < 4; p++) {
                float2 f = up2(acc[j*4+p]);
                z[j][2*p] = silu_f(f.x); z[j][2*p+1] = silu_f(f.y);
            }
#pragma unroll
        for (int p = 0; p < 8; p++) {
            *reinterpret_cast<float4*>(YsT + (c0 + p) * 64 + e0) =
                make_float4(z[0][p], z[1][p], z[2][p], z[3][p]);
        }
#pragma unroll
        for (int j = 0; j < 4; j++) {
            int eg = e_base + e0 + j;
            if (eg < E) {
                float* dst = g_agg + (long)rowi[e0 + j] * 128 + c0;
                atomicAdd(reinterpret_cast<float4*>(dst),
                          make_float4(z[j][0], z[j][1], z[j][2], z[j][3]));
                atomicAdd(reinterpret_cast<float4*>(dst + 4),
                          make_float4(z[j][4], z[j][5], z[j][6], z[j][7]));
            }
        }
    }
    if (tid < 64) sES[tid] = 0.0f;

    // ------- GEMM3: edge_feat @ ae_w1[0:128] + aeb1 -> SiLU -> dot ae_w2 -
    init_acc_bias(g_aeb1, c0, acc);
    gemm64<128, 3>(YsT, ae_w1, Wbuf, tid, e0, c0, acc);
    {
        float4 w0 = __ldg(reinterpret_cast<const float4*>(ae_w2 + c0));
        float4 w1 = __ldg(reinterpret_cast<const float4*>(ae_w2 + c0 + 4));
        float wv[8] = { w0.x, w0.y, w0.z, w0.w, w1.x, w1.y, w1.z, w1.w };
#pragma unroll
        for (int j = 0; j < 4; j++) {
            float p = 0.0f;
#pragma unroll
            for (int q = 0; q < 4; q++) {
                float2 f = up2(acc[j*4+q]);
                p += silu_f(f.x) * wv[2*q];
                p += silu_f(f.y) * wv[2*q+1];
            }
            p += __shfl_xor_sync(0xffffffffu, p, 1);
            p += __shfl_xor_sync(0xffffffffu, p, 2);
            if ((lane & 3) == 0) atomicAdd(&sES[e0 + j], p);
        }
    }
    __syncthreads();
    if (tid < 64) {
        int eg = e_base + tid;
        if (eg < E) {
            float s = sES[tid];
            float4 c = cd[tid];
            float f = s * c.w;
            float* dst = g_aggc + (long)rowi[tid] * 3;
            atomicAdd(dst + 0, c.x * f);
            atomicAdd(dst + 1, c.y * f);
            atomicAdd(dst + 2, c.z * f);
        }
    }
}

// ---------------- fused node kernel ----------------
// 64 nodes per CTA, 256 threads, 2 CTAs/SM.
// smem: XnT[256][64]=16384 | YnT[128][64]=8192 | Wbuf[2*2048]=4096 | sES 64
#define NODE_SMEM ((256*64 + 128*64 + 2*2048 + 64) * 4)

__global__ void __launch_bounds__(256, 2) node_kernel(
    const float* __restrict__ h, const float* __restrict__ coordg,
    const float* __restrict__ n_w1, const float* __restrict__ n_w2,
    const float* __restrict__ n_b2,
    const float* __restrict__ ap_w1, const float* __restrict__ ap_w2,
    float* __restrict__ out, int N)
{
    extern __shared__ float sm[];
    float* XnT  = sm;
    float* YnT  = XnT + 256 * 64;
    float* Wbuf = YnT + 128 * 64;
    float* sES  = Wbuf + 2 * 2048;

    const int tid = threadIdx.x;
    const int nb = blockIdx.x * 64;

    // ------- stage XnT: rows 0..127 = h^T, rows 128..255 = agg^T -------
    {
        const int el = tid & 63, part = tid >> 6;   // 4 parts of 64 k
        int n = nb + el;
        bool v = n < N;
        long nn = v ? (long)n : 0;
        const float4* srcp = (part < 2)
            ? reinterpret_cast<const float4*>(h) + nn * 32 + (part & 1) * 16
            : reinterpret_cast<const float4*>(g_agg) + nn * 32 + (part & 1) * 16;
        int k0 = (part & 1) * 64 + ((part >= 2) ? 128 : 0);
#pragma unroll
        for (int i = 0; i < 16; i++) {
            float4 a = v ? __ldg(srcp + i) : make_float4(0.f, 0.f, 0.f, 0.f);
            int k = k0 + 4 * i;
            XnT[(k+0)*64 + el] = a.x; XnT[(k+1)*64 + el] = a.y;
            XnT[(k+2)*64 + el] = a.z; XnT[(k+3)*64 + el] = a.w;
        }
    }

    const int warp = tid >> 5, lane = tid & 31;
    const int e0 = (warp >> 2) * 32 + (lane >> 2) * 4;
    const int c0 = (warp & 3) * 32 + (lane & 3) * 8;

    UL acc[16];

    // ------- node GEMM1 (K=256): [h|agg] @ n_w1 + nb1 -> SiLU -> YnT ----
    init_acc_bias(g_nb1, c0, acc);
    gemm64<256, 2>(XnT, n_w1, Wbuf, tid, e0, c0, acc);
    epilogue_silu_T(acc, YnT, e0, c0);

    // ------- node GEMM2: @ n_w2 + n_b2 -> SiLU -> h_out = h + . --------
    init_acc_bias(n_b2, c0, acc);
    gemm64<128, 2>(YnT, n_w2, Wbuf, tid, e0, c0, acc);
    {
        float ho[4][8];
#pragma unroll
        for (int p = 0; p < 4; p++) {
            float2 f0 = up2(acc[0*4+p]), f1 = up2(acc[1*4+p]);
            float2 f2 = up2(acc[2*4+p]), f3 = up2(acc[3*4+p]);
            float4 hA = *reinterpret_cast<const float4*>(XnT + (c0 + 2*p) * 64 + e0);
            float4 hB = *reinterpret_cast<const float4*>(XnT + (c0 + 2*p + 1) * 64 + e0);
            ho[0][2*p] = silu_f(f0.x) + hA.x; ho[1][2*p] = silu_f(f1.x) + hA.y;
            ho[2][2*p] = silu_f(f2.x) + hA.z; ho[3][2*p] = silu_f(f3.x) + hA.w;
            ho[0][2*p+1] = silu_f(f0.y) + hB.x; ho[1][2*p+1] = silu_f(f1.y) + hB.y;
            ho[2][2*p+1] = silu_f(f2.y) + hB.z; ho[3][2*p+1] = silu_f(f3.y) + hB.w;
        }
#pragma unroll
        for (int p = 0; p < 8; p++) {
            *reinterpret_cast<float4*>(YnT + (c0 + p) * 64 + e0) =
                make_float4(ho[0][p], ho[1][p], ho[2][p], ho[3][p]);
        }
#pragma unroll
        for (int j = 0; j < 4; j++) {
            int n = nb + e0 + j;
            if (n < N) {
                float* o = out + (long)n * 128 + c0;
                *reinterpret_cast<float4*>(o) =
                    make_float4(ho[j][0], ho[j][1], ho[j][2], ho[j][3]);
                *reinterpret_cast<float4*>(o + 4) =
                    make_float4(ho[j][4], ho[j][5], ho[j][6], ho[j][7]);
            }
        }
    }
    if (tid < 64) sES[tid] = 0.0f;

    // ------- acc-point MLP: h_out @ ap_w1 + apb1 -> SiLU -> dot ap_w2 ---
    init_acc_bias(g_apb1, c0, acc);
    gemm64<128, 2>(YnT, ap_w1, Wbuf, tid, e0, c0, acc);
    {
        float4 w0 = __ldg(reinterpret_cast<const float4*>(ap_w2 + c0));
        float4 w1 = __ldg(reinterpret_cast<const float4*>(ap_w2 + c0 + 4));
        float wv[8] = { w0.x, w0.y, w0.z, w0.w, w1.x, w1.y, w1.z, w1.w };
#pragma unroll
        for (int j = 0; j < 4; j++) {
            float p = 0.0f;
#pragma unroll
            for (int q = 0; q < 4; q++) {
                float2 f = up2(acc[j*4+q]);
                p += silu_f(f.x) * wv[2*q];
                p += silu_f(f.y) * wv[2*q+1];
            }
            p += __shfl_xor_sync(0xffffffffu, p, 1);
            p += __shfl_xor_sync(0xffffffffu, p, 2);
            if ((lane & 3) == 0) atomicAdd(&sES[e0 + j], p);
        }
    }
    __syncthreads();
    if (tid < 64) {
        int n = nb + tid;
        if (n < N) {
            float s = sES[tid];
            long base_c = (long)N * 128;
            long base_a = (long)N * 131;
            out[base_c + (long)n*3 + 0] = coordg[n*3+0];
            out[base_c + (long)n*3 + 1] = coordg[n*3+1];
            out[base_c + (long)n*3 + 2] = coordg[n*3+2];
            out[base_a + (long)n*3 + 0] = g_aggc[n*3+0] * s;
            out[base_a + (long)n*3 + 1] = g_aggc[n*3+1] * s;
            out[base_a + (long)n*3 + 2] = g_aggc[n*3+2] * s;
        }
    }
}

// ---------------- launch ----------------
extern "C" void kernel_launch(void* const* d_in, const int* in_sizes, int n_in,
                              void* d_out, int out_size)
{
    const float* h      = (const float*)d_in[0];
    const int*   ei     = (const int*)  d_in[1];
    const float* coord  = (const float*)d_in[2];
    const float* eattr  = (const float*)d_in[3];
    const float* prompt = (const float*)d_in[4];
    const float* e_w1   = (const float*)d_in[5];
    const float* e_b1   = (const float*)d_in[6];
    const float* e_w2   = (const float*)d_in[7];
    const float* e_b2   = (const float*)d_in[8];
    const float* n_w1   = (const float*)d_in[9];
    const float* n_b1   = (const float*)d_in[10];
    const float* n_w2   = (const float*)d_in[11];
    const float* n_b2   = (const float*)d_in[12];
    const float* ae_w1  = (const float*)d_in[13];
    const float* ae_b1  = (const float*)d_in[14];
    const float* ae_w2  = (const float*)d_in[15];
    const float* ap_w1  = (const float*)d_in[16];
    const float* ap_b1  = (const float*)d_in[17];
    const float* ap_w2  = (const float*)d_in[18];
    float* out = (float*)d_out;

    int N = in_sizes[0] / 128;
    int E = in_sizes[1] / 2;

    cudaFuncSetAttribute(proj_kernel, cudaFuncAttributeMaxDynamicSharedMemorySize, PROJ_SMEM);
    cudaFuncSetAttribute(edge_kernel, cudaFuncAttributeMaxDynamicSharedMemorySize, EDGE_SMEM);
    cudaFuncSetAttribute(node_kernel, cudaFuncAttributeMaxDynamicSharedMemorySize, NODE_SMEM);

    prep_kernel<<<4, 128>>>(prompt, e_w1, e_b1, n_w1, n_b1, ae_w1, ae_b1, ap_w1, ap_b1);
    proj_kernel<<<(N + 63) / 64, 256, PROJ_SMEM>>>(h, e_w1, N);
    edge_kernel<<<(E + 63) / 64, 256, EDGE_SMEM>>>(ei, coord, eattr,
                                                   e_w1, e_w2, e_b2, ae_w1, ae_w2, E);
    node_kernel<<<(N + 63) / 64, 256, NODE_SMEM>>>(h, coord, n_w1, n_w2, n_b2,
                                                   ap_w1, ap_w2, out, N);
}

// round 13
// speedup vs baseline: 3.1639x; 1.2489x over previous
#include <cuda_runtime.h>
#include <cuda_bf16.h>

typedef unsigned long long UL;

// ---------------- device scratch (no allocations allowed) ----------------
__device__ float g_agg [50000 * 128];   // segment-sum of edge_feat per node
__device__ float g_aggc[50000 * 3];     // segment-sum of trans per node
__device__ float g_P   [50048 * 256];   // per-node projections [P1 | P2]
__device__ float g_eb1 [128];           // e_b1  + prompt @ e_w1[273:401]
__device__ float g_nb1 [128];           // n_b1  + prompt @ n_w1[256:384]
__device__ float g_aeb1[128];           // ae_b1 + prompt @ ae_w1[128:256]
__device__ float g_apb1[128];           // ap_b1 + prompt @ ap_w1[128:256]
// bf16 hi/lo weight tiles, BT[n][k] with 8-way XOR swizzle, 32KB each
__device__ uint4 g_Bw2h[2048];
__device__ uint4 g_Bw2l[2048];
__device__ uint4 g_Baeh[2048];
__device__ uint4 g_Bael[2048];

// ---------------- small helpers ----------------
__device__ __forceinline__ UL bc2(float x) {
    UL r; asm("mov.b64 %0,{%1,%1};" : "=l"(r) : "f"(x)); return r;
}
__device__ __forceinline__ UL pk2(float x, float y) {
    UL r; asm("mov.b64 %0,{%1,%2};" : "=l"(r) : "f"(x), "f"(y)); return r;
}
__device__ __forceinline__ float2 up2(UL v) {
    float2 f; asm("mov.b64 {%0,%1},%2;" : "=f"(f.x), "=f"(f.y) : "l"(v)); return f;
}
__device__ __forceinline__ void fma2(UL &d, UL a, UL b) {
    asm("fma.rn.f32x2 %0,%1,%2,%0;" : "+l"(d) : "l"(a), "l"(b));
}
__device__ __forceinline__ float silu_f(float x) {
    return __fdividef(x, 1.0f + __expf(-x));
}
__device__ __forceinline__ void cpa16(unsigned dst, const float* src) {
    asm volatile("cp.async.cg.shared.global [%0], [%1], 16;" :: "r"(dst), "l"(src));
}
#define CPA_COMMIT() asm volatile("cp.async.commit_group;" ::: "memory")

// row-major [row][128] bf16, 256B row stride, 8-way XOR swizzle on 16B chunks
__device__ __forceinline__ unsigned aoff(int row, int col) {
    return (unsigned)(row * 256 + ((((col >> 3) ^ (row & 7)) << 4) | ((col & 7) * 2)));
}

__device__ __forceinline__ void ldm4(unsigned* r, unsigned addr) {
    asm volatile("ldmatrix.sync.aligned.m8n8.x4.shared.b16 {%0,%1,%2,%3}, [%4];"
        : "=r"(r[0]), "=r"(r[1]), "=r"(r[2]), "=r"(r[3]) : "r"(addr));
}
__device__ __forceinline__ void mma16816(float* c, const unsigned* a,
                                         unsigned b0, unsigned b1) {
    asm volatile(
        "mma.sync.aligned.m16n8k16.row.col.f32.bf16.bf16.f32 "
        "{%0,%1,%2,%3}, {%4,%5,%6,%7}, {%8,%9}, {%0,%1,%2,%3};"
        : "+f"(c[0]), "+f"(c[1]), "+f"(c[2]), "+f"(c[3])
        : "r"(a[0]), "r"(a[1]), "r"(a[2]), "r"(a[3]), "r"(b0), "r"(b1));
}

// 16 packed FMAs for one k-row: 4 rows x 4 col-pairs
#define FMAROW(WA, WB, S0, S1, S2, S3)                            \
    do {                                                          \
        fma2(acc[0],  S0, WA.x); fma2(acc[1],  S0, WA.y);         \
        fma2(acc[2],  S0, WB.x); fma2(acc[3],  S0, WB.y);         \
        fma2(acc[4],  S1, WA.x); fma2(acc[5],  S1, WA.y);         \
        fma2(acc[6],  S1, WB.x); fma2(acc[7],  S1, WB.y);         \
        fma2(acc[8],  S2, WA.x); fma2(acc[9],  S2, WA.y);         \
        fma2(acc[10], S2, WB.x); fma2(acc[11], S2, WB.y);         \
        fma2(acc[12], S3, WA.x); fma2(acc[13], S3, WA.y);         \
        fma2(acc[14], S3, WB.x); fma2(acc[15], S3, WB.y);         \
    } while (0)

__device__ __forceinline__ void init_acc_bias(const float* biasg, int c0, UL* acc)
{
    float4 b0 = __ldg(reinterpret_cast<const float4*>(biasg + c0));
    float4 b1 = __ldg(reinterpret_cast<const float4*>(biasg + c0 + 4));
    UL bp0 = pk2(b0.x, b0.y), bp1 = pk2(b0.z, b0.w);
    UL bp2 = pk2(b1.x, b1.y), bp3 = pk2(b1.z, b1.w);
#pragma unroll
    for (int j = 0; j < 4; j++) {
        acc[j*4+0] = bp0; acc[j*4+1] = bp1; acc[j*4+2] = bp2; acc[j*4+3] = bp3;
    }
}
__device__ __forceinline__ void init_acc_zero(UL* acc)
{
    UL z = pk2(0.0f, 0.0f);
#pragma unroll
    for (int j = 0; j < 16; j++) acc[j] = z;
}

// ------- f32x2 GEMM, transposed X tile, cp.async ring (NT threads) ------
template<int K, int DEPTH, int NT, int XSTR>
__device__ __forceinline__ void gemm_t(
    const float* XsT, const float* __restrict__ Wg,
    float* Wbuf, int tid, int e0, int c0, UL* acc)
{
    constexpr int CH = (K + 15) / 16;
    constexpr int PF = 2048 / NT;   // floats staged per thread per chunk

    const float* src = Wg + tid * PF;
    unsigned dstb = (unsigned)__cvta_generic_to_shared(Wbuf) + tid * PF * 4;

#pragma unroll
    for (int p = 0; p < DEPTH - 1; p++) {
        if (p < CH) {
            unsigned d = dstb + p * 8192;
            const float* s = src + p * 2048;
            cpa16(d, s);
            if (PF == 8) cpa16(d + 16, s + 4);
        }
        CPA_COMMIT();
    }

    const float* xb = XsT + e0;
    int cons = 0, nxt = (DEPTH - 1) % DEPTH;

    for (int c = 0; c < CH; c++) {
        asm volatile("cp.async.wait_group %0;" :: "n"(DEPTH - 2) : "memory");
        __syncthreads();
        if (c + DEPTH - 1 < CH) {
            unsigned d = dstb + nxt * 8192;
            const float* s = src + (c + DEPTH - 1) * 2048;
            cpa16(d, s);
            if (PF == 8) cpa16(d + 16, s + 4);
        }
        CPA_COMMIT();

        const float* wb = Wbuf + cons * 2048 + c0;
        const int kb = c * 16;
        const float* xk = xb + kb * XSTR;
        if (kb + 16 <= K) {
#pragma unroll
            for (int kk = 0; kk < 16; kk++) {
                float4 xv = *reinterpret_cast<const float4*>(xk + kk * XSTR);
                ulonglong2 a = *reinterpret_cast<const ulonglong2*>(wb + kk * 128);
                ulonglong2 b = *reinterpret_cast<const ulonglong2*>(wb + kk * 128 + 4);
                UL s0 = bc2(xv.x), s1 = bc2(xv.y), s2 = bc2(xv.z), s3 = bc2(xv.w);
                FMAROW(a, b, s0, s1, s2, s3);
            }
        } else {
            for (int kk = 0; kk < K - kb; kk++) {
                float4 xv = *reinterpret_cast<const float4*>(xk + kk * XSTR);
                ulonglong2 a = *reinterpret_cast<const ulonglong2*>(wb + kk * 128);
                ulonglong2 b = *reinterpret_cast<const ulonglong2*>(wb + kk * 128 + 4);
                UL s0 = bc2(xv.x), s1 = bc2(xv.y), s2 = bc2(xv.z), s3 = bc2(xv.w);
                FMAROW(a, b, s0, s1, s2, s3);
            }
        }
        cons++; if (cons == DEPTH) cons = 0;
        nxt++;  if (nxt == DEPTH)  nxt = 0;
    }
    asm volatile("cp.async.wait_group 0;" ::: "memory");
    __syncthreads();
}

// write 8 cols x 4 rows of silu(acc) into transposed tile T[col][row64]
__device__ __forceinline__ void epilogue_silu_T(UL* acc, float* T, int e0, int c0)
{
#pragma unroll
    for (int p = 0; p < 4; p++) {
        float2 f0 = up2(acc[0*4+p]), f1 = up2(acc[1*4+p]);
        float2 f2 = up2(acc[2*4+p]), f3 = up2(acc[3*4+p]);
        *reinterpret_cast<float4*>(T + (c0 + 2*p) * 64 + e0) =
            make_float4(silu_f(f0.x), silu_f(f1.x), silu_f(f2.x), silu_f(f3.x));
        *reinterpret_cast<float4*>(T + (c0 + 2*p + 1) * 64 + e0) =
            make_float4(silu_f(f0.y), silu_f(f1.y), silu_f(f2.y), silu_f(f3.y));
    }
}

// bf16 hi/lo split store of a col-pair (col even) into A tiles
__device__ __forceinline__ void store_bf16_pair(
    char* AhB, char* AlB, int row, int col, float z0, float z1)
{
    __nv_bfloat16 h0 = __float2bfloat16(z0);
    __nv_bfloat16 h1 = __float2bfloat16(z1);
    __nv_bfloat16 l0 = __float2bfloat16(z0 - __bfloat162float(h0));
    __nv_bfloat16 l1 = __float2bfloat16(z1 - __bfloat162float(h1));
    unsigned uh = (unsigned)*reinterpret_cast<unsigned short*>(&h0)
                | ((unsigned)*reinterpret_cast<unsigned short*>(&h1) << 16);
    unsigned ul = (unsigned)*reinterpret_cast<unsigned short*>(&l0)
                | ((unsigned)*reinterpret_cast<unsigned short*>(&l1) << 16);
    unsigned off = aoff(row, col);
    *reinterpret_cast<unsigned*>(AhB + off) = uh;
    *reinterpret_cast<unsigned*>(AlB + off) = ul;
}

// 3-term bf16-split 32x32 warp-tile GEMM over K=128 (mma.sync m16n8k16)
__device__ __forceinline__ void mma_gemm(
    unsigned AhU, unsigned AlU, unsigned BhU, unsigned BlU,
    int m0, int n0, int lane, float c[2][4][4])
{
#pragma unroll
    for (int i = 0; i < 2; i++)
#pragma unroll
        for (int j = 0; j < 4; j++)
#pragma unroll
            for (int q = 0; q < 4; q++) c[i][j][q] = 0.0f;

    const int mi = lane >> 3;
    const int rAoff = ((mi & 1) << 3) + (lane & 7);   // A: mi bit0 = m-half
    const int kHalfA = mi >> 1;                       //    mi bit1 = k-half
    const int nOff = ((mi >> 1) << 3) + (lane & 7);   // B: mi bit1 = n-half
    const int kHalfB = mi & 1;                        //    mi bit0 = k-half

#pragma unroll
    for (int k0 = 0; k0 < 128; k0 += 16) {
        unsigned ah[2][4], al[2][4], bh[2][4], bl[2][4];
        const int kcA = (k0 >> 3) + kHalfA;
        const int kcB = (k0 >> 3) + kHalfB;
#pragma unroll
        for (int i = 0; i < 2; i++) {
            int row = m0 + 16 * i + rAoff;
            unsigned off = (unsigned)(row * 256 + ((kcA ^ (row & 7)) << 4));
            ldm4(ah[i], AhU + off);
            ldm4(al[i], AlU + off);
        }
#pragma unroll
        for (int j2 = 0; j2 < 2; j2++) {
            int nrow = n0 + 16 * j2 + nOff;
            unsigned off = (unsigned)(nrow * 256 + ((kcB ^ (nrow & 7)) << 4));
            ldm4(bh[j2], BhU + off);
            ldm4(bl[j2], BlU + off);
        }
#pragma unroll
        for (int i = 0; i < 2; i++) {
#pragma unroll
            for (int jt = 0; jt < 4; jt++) {
                int j2 = jt >> 1, s = jt & 1;
                mma16816(c[i][jt], ah[i], bh[j2][2*s], bh[j2][2*s+1]);
                mma16816(c[i][jt], ah[i], bl[j2][2*s], bl[j2][2*s+1]);
                mma16816(c[i][jt], al[i], bh[j2][2*s], bh[j2][2*s+1]);
            }
        }
    }
}

// ---------------- prep: prompt-biases + bf16-split BT weight tiles -------
__global__ void prep_kernel(
    const float* __restrict__ prompt,
    const float* __restrict__ e_w1,  const float* __restrict__ e_b1,
    const float* __restrict__ n_w1,  const float* __restrict__ n_b1,
    const float* __restrict__ ae_w1, const float* __restrict__ ae_b1,
    const float* __restrict__ ap_w1, const float* __restrict__ ap_b1,
    const float* __restrict__ e_w2)
{
    int n = threadIdx.x;
    int b = blockIdx.x;
    if (b < 4) {
        const float* w; const float* bias; float* dst; int off;
        if (b == 0)      { w = e_w1;  bias = e_b1;  dst = g_eb1;  off = 273; }
        else if (b == 1) { w = n_w1;  bias = n_b1;  dst = g_nb1;  off = 256; }
        else if (b == 2) { w = ae_w1; bias = ae_b1; dst = g_aeb1; off = 128; }
        else             { w = ap_w1; bias = ap_b1; dst = g_apb1; off = 128; }
        float s = bias[n];
        for (int j = 0; j < 128; j++)
            s = fmaf(prompt[j], w[(off + j) * 128 + n], s);
        dst[n] = s;
    } else {
        const float* W; char* BH; char* BL;
        if (b == 4) { W = e_w2;  BH = (char*)g_Bw2h; BL = (char*)g_Bw2l; }
        else        { W = ae_w1; BH = (char*)g_Baeh; BL = (char*)g_Bael; }
        for (int i = n; i < 16384; i += 128) {
            int nn = i >> 7, k = i & 127;
            float v = W[k * 128 + nn];             // BT[nn][k] = W[k][nn]
            __nv_bfloat16 h = __float2bfloat16(v);
            __nv_bfloat16 l = __float2bfloat16(v - __bfloat162float(h));
            unsigned off = aoff(nn, k);
            *reinterpret_cast<unsigned short*>(BH + off) =
                *reinterpret_cast<unsigned short*>(&h);
            *reinterpret_cast<unsigned short*>(BL + off) =
                *reinterpret_cast<unsigned short*>(&l);
        }
    }
}

// ---------------- node projection kernel: g_P = h @ [W1a | W1b] ---------
#define PROJ_SMEM ((128*64 + 4*2048) * 4)

__global__ void __launch_bounds__(256, 2) proj_kernel(
    const float* __restrict__ h, const float* __restrict__ e_w1, int N)
{
    extern __shared__ float sm[];
    float* hT   = sm;
    float* Wbuf = hT + 128 * 64;

    const int tid = threadIdx.x;
    const int nb = blockIdx.x * 64;

    {
        const int el = tid & 63, part = tid >> 6;
        int n = nb + el;
        if (n < N) {
            float4 z4 = make_float4(0.f, 0.f, 0.f, 0.f);
            float4* ga = reinterpret_cast<float4*>(g_agg + (long)n * 128) + part * 8;
#pragma unroll
            for (int i = 0; i < 8; i++) ga[i] = z4;
            if (part == 0) {
                g_aggc[(long)n*3+0] = 0.f;
                g_aggc[(long)n*3+1] = 0.f;
                g_aggc[(long)n*3+2] = 0.f;
            }
        }
    }
    {
        const int el = tid & 63, part = tid >> 6;
        int n = nb + el;
        bool v = n < N;
        long nn = v ? (long)n : 0;
        const float4* hr = reinterpret_cast<const float4*>(h) + nn * 32 + part * 8;
#pragma unroll
        for (int i = 0; i < 8; i++) {
            float4 a = v ? __ldg(hr + i) : make_float4(0.f, 0.f, 0.f, 0.f);
            int k = part * 32 + 4 * i;
            hT[(k+0)*64 + el] = a.x; hT[(k+1)*64 + el] = a.y;
            hT[(k+2)*64 + el] = a.z; hT[(k+3)*64 + el] = a.w;
        }
    }
    const int warp = tid >> 5, lane = tid & 31;
    const int e0 = (warp >> 2) * 32 + (lane >> 2) * 4;
    const int c0 = (warp & 3) * 32 + (lane & 3) * 8;

    UL acc[16];

    init_acc_zero(acc);
    gemm_t<128, 4, 256, 64>(hT, e_w1, Wbuf, tid, e0, c0, acc);
#pragma unroll
    for (int j = 0; j < 4; j++) {
        int n = nb + e0 + j;
        if (n < N) {
            float2 f0 = up2(acc[j*4+0]), f1 = up2(acc[j*4+1]);
            float2 f2 = up2(acc[j*4+2]), f3 = up2(acc[j*4+3]);
            float* o = g_P + (long)n * 256 + c0;
            *reinterpret_cast<float4*>(o)     = make_float4(f0.x, f0.y, f1.x, f1.y);
            *reinterpret_cast<float4*>(o + 4) = make_float4(f2.x, f2.y, f3.x, f3.y);
        }
    }

    init_acc_zero(acc);
    gemm_t<128, 4, 256, 64>(hT, e_w1 + 128 * 128, Wbuf, tid, e0, c0, acc);
#pragma unroll
    for (int j = 0; j < 4; j++) {
        int n = nb + e0 + j;
        if (n < N) {
            float2 f0 = up2(acc[j*4+0]), f1 = up2(acc[j*4+1]);
            float2 f2 = up2(acc[j*4+2]), f3 = up2(acc[j*4+3]);
            float* o = g_P + (long)n * 256 + 128 + c0;
            *reinterpret_cast<float4*>(o)     = make_float4(f0.x, f0.y, f1.x, f1.y);
            *reinterpret_cast<float4*>(o + 4) = make_float4(f2.x, f2.y, f3.x, f3.y);
        }
    }
}

// ---------------- fused edge kernel (mma.sync bf16 split) ----------------
// 128 edges per CTA, 512 threads, 1 CTA/SM.
// byte map: Ah 0 | Al 32768 | B2h 65536 | B2l 98304 | B3h 131072 | B3l 163840
//   XeT 196608 (8704) | Wbuf 205312 (16384) | cd 221696 (2048)
//   sES 223744 (512) | rowi 224256 (512) | coli 224768 (512)
#define EDGE_SMEM 225280

__global__ void __launch_bounds__(512, 1) edge_kernel(
    const int* __restrict__ ei,
    const float* __restrict__ coord, const float* __restrict__ eattr,
    const float* __restrict__ e_w1, const float* __restrict__ e_b2,
    const float* __restrict__ ae_w2, int E)
{
    extern __shared__ float sm[];
    char* base = reinterpret_cast<char*>(sm);
    char* AhB = base;
    char* AlB = base + 32768;
    float* XeT  = reinterpret_cast<float*>(base + 196608);
    float* Wbuf = reinterpret_cast<float*>(base + 205312);
    float4* cd  = reinterpret_cast<float4*>(base + 221696);
    float*  sES = reinterpret_cast<float*>(base + 223744);
    int*   rowi = reinterpret_cast<int*>(base + 224256);
    int*   coli = reinterpret_cast<int*>(base + 224768);
    unsigned smem_u = (unsigned)__cvta_generic_to_shared(base);

    const int tid = threadIdx.x;
    const int wid = tid >> 5, lane = tid & 31;
    const int e_base = blockIdx.x * 128;
    const int* rowg = ei;
    const int* colg = ei + E;

    // stream all 4 weight tiles (pre-swizzled, layout-preserving blob copy)
    {
        const float* s0 = reinterpret_cast<const float*>(g_Bw2h) + tid * 16;
        const float* s1 = reinterpret_cast<const float*>(g_Bw2l) + tid * 16;
        const float* s2 = reinterpret_cast<const float*>(g_Baeh) + tid * 16;
        const float* s3 = reinterpret_cast<const float*>(g_Bael) + tid * 16;
        unsigned d0 = smem_u + 65536  + tid * 64;
        unsigned d1 = smem_u + 98304  + tid * 64;
        unsigned d2 = smem_u + 131072 + tid * 64;
        unsigned d3 = smem_u + 163840 + tid * 64;
#pragma unroll
        for (int i = 0; i < 4; i++) {
            cpa16(d0 + i * 16, s0 + i * 4);
            cpa16(d1 + i * 16, s1 + i * 4);
            cpa16(d2 + i * 16, s2 + i * 4);
            cpa16(d3 + i * 16, s3 + i * 4);
        }
        CPA_COMMIT();
    }

    // ------- stage XeT: row0 = radial, rows 1..16 = eattr^T; indices -----
    {
        const int el = tid & 127, part = tid >> 7;
        int e = e_base + el;
        bool v = e < E;
        if (part == 0) {
            long r = v ? (long)rowg[e] : 0;
            long c = v ? (long)colg[e] : 0;
            rowi[el] = (int)r;
            coli[el] = (int)c;
            float dx = 0.f, dy = 0.f, dz = 0.f;
            if (v) {
                dx = coord[r*3+0] - coord[c*3+0];
                dy = coord[r*3+1] - coord[c*3+1];
                dz = coord[r*3+2] - coord[c*3+2];
            }
            float rad = dx*dx + dy*dy + dz*dz;
            XeT[el] = rad;
            float inv = 1.0f / fmaxf(sqrtf(rad), 1e-12f);
            cd[el] = make_float4(dx, dy, dz, inv);
        } else if (part == 1) {
            const float4* ea = reinterpret_cast<const float4*>(eattr) + (long)e * 4;
#pragma unroll
            for (int i = 0; i < 4; i++) {
                float4 a = v ? __ldg(ea + i) : make_float4(0.f, 0.f, 0.f, 0.f);
                int k = 1 + 4 * i;
                XeT[(k+0)*128 + el] = a.x; XeT[(k+1)*128 + el] = a.y;
                XeT[(k+2)*128 + el] = a.z; XeT[(k+3)*128 + el] = a.w;
            }
        }
    }
    __syncthreads();

    const int e0 = (wid >> 2) * 32 + (lane >> 2) * 4;
    const int c0 = (wid & 3) * 32 + (lane & 3) * 8;

    UL acc[16];

    // ------- acc init: eb1_eff + P1[row] + P2[col] -----------------------
    {
        float4 b0 = __ldg(reinterpret_cast<const float4*>(g_eb1 + c0));
        float4 b1 = __ldg(reinterpret_cast<const float4*>(g_eb1 + c0 + 4));
#pragma unroll
        for (int j = 0; j < 4; j++) {
            int r = rowi[e0 + j], cc = coli[e0 + j];
            const float* pr = g_P + (long)r  * 256 + c0;
            const float* pc = g_P + (long)cc * 256 + 128 + c0;
            float4 p0 = __ldg(reinterpret_cast<const float4*>(pr));
            float4 p1 = __ldg(reinterpret_cast<const float4*>(pr + 4));
            float4 q0 = __ldg(reinterpret_cast<const float4*>(pc));
            float4 q1 = __ldg(reinterpret_cast<const float4*>(pc + 4));
            acc[j*4+0] = pk2(b0.x + p0.x + q0.x, b0.y + p0.y + q0.y);
            acc[j*4+1] = pk2(b0.z + p0.z + q0.z, b0.w + p0.w + q0.w);
            acc[j*4+2] = pk2(b1.x + p1.x + q1.x, b1.y + p1.y + q1.y);
            acc[j*4+3] = pk2(b1.z + p1.z + q1.z, b1.w + p1.w + q1.w);
        }
    }

    // ------- GEMM1 (K=17, f32x2): -> silu -> bf16 hi/lo A tiles ---------
    // (gemm_t's final wait_group 0 also drains the B-tile copies)
    gemm_t<17, 2, 512, 128>(XeT, e_w1 + 256 * 128, Wbuf, tid, e0, c0, acc);
#pragma unroll
    for (int j = 0; j < 4; j++) {
        int r = e0 + j;
#pragma unroll
        for (int p = 0; p < 4; p++) {
            float2 f = up2(acc[j*4+p]);
            store_bf16_pair(AhB, AlB, r, c0 + 2*p, silu_f(f.x), silu_f(f.y));
        }
    }
    if (tid < 128) sES[tid] = 0.0f;
    __syncthreads();

    const int m0 = (wid >> 2) * 32;
    const int n0 = (wid & 3) * 32;
    const int g  = lane >> 2;
    const int q  = lane & 3;

    float c[2][4][4];

    // ------- GEMM2: edge hidden @ e_w2  (tensor cores) -------------------
    mma_gemm(smem_u + 0, smem_u + 32768, smem_u + 65536, smem_u + 98304,
             m0, n0, lane, c);
    __syncthreads();   // all warps done reading A before overwrite

    // epilogue: bias+silu, store edge_feat to A tiles, g_agg atomics
#pragma unroll
    for (int i = 0; i < 2; i++) {
        int r0 = m0 + 16 * i + g;
#pragma unroll
        for (int jt = 0; jt < 4; jt++) {
            int col = n0 + 8 * jt + q * 2;
            float bx = __ldg(e_b2 + col), by = __ldg(e_b2 + col + 1);
            float z0 = silu_f(c[i][jt][0] + bx);
            float z1 = silu_f(c[i][jt][1] + by);
            float z2 = silu_f(c[i][jt][2] + bx);
            float z3 = silu_f(c[i][jt][3] + by);
            store_bf16_pair(AhB, AlB, r0,     col, z0, z1);
            store_bf16_pair(AhB, AlB, r0 + 8, col, z2, z3);
            if (e_base + r0 < E)
                atomicAdd(reinterpret_cast<float2*>(
                    g_agg + (long)rowi[r0] * 128 + col), make_float2(z0, z1));
            if (e_base + r0 + 8 < E)
                atomicAdd(reinterpret_cast<float2*>(
                    g_agg + (long)rowi[r0 + 8] * 128 + col), make_float2(z2, z3));
        }
    }
    __syncthreads();   // edge_feat visible to all warps

    // ------- GEMM3: edge_feat @ ae_w1  (tensor cores) --------------------
    mma_gemm(smem_u + 0, smem_u + 32768, smem_u + 131072, smem_u + 163840,
             m0, n0, lane, c);

    // epilogue: silu(c + aeb1) dot ae_w2 -> per-row sums in sES
    {
        float s[4] = {0.f, 0.f, 0.f, 0.f};   // rows m0+g, +8, +16, +24
#pragma unroll
        for (int i = 0; i < 2; i++) {
#pragma unroll
            for (int jt = 0; jt < 4; jt++) {
                int col = n0 + 8 * jt + q * 2;
                float bx = __ldg(g_aeb1 + col), by = __ldg(g_aeb1 + col + 1);
                float wx = __ldg(ae_w2 + col),  wy = __ldg(ae_w2 + col + 1);
                s[2*i]   += silu_f(c[i][jt][0] + bx) * wx
                          + silu_f(c[i][jt][1] + by) * wy;
                s[2*i+1] += silu_f(c[i][jt][2] + bx) * wx
                          + silu_f(c[i][jt][3] + by) * wy;
            }
        }
#pragma unroll
        for (int t = 0; t < 4; t++) {
            s[t] += __shfl_xor_sync(0xffffffffu, s[t], 1);
            s[t] += __shfl_xor_sync(0xffffffffu, s[t], 2);
        }
        if (q == 0) {
            atomicAdd(&sES[m0 + g],      s[0]);
            atomicAdd(&sES[m0 + 8 + g],  s[1]);
            atomicAdd(&sES[m0 + 16 + g], s[2]);
            atomicAdd(&sES[m0 + 24 + g], s[3]);
        }
    }
    __syncthreads();

    if (tid < 128) {
        int eg = e_base + tid;
        if (eg < E) {
            float sv = sES[tid];
            float4 cdl = cd[tid];
            float f = sv * cdl.w;
            float* dst = g_aggc + (long)rowi[tid] * 3;
            atomicAdd(dst + 0, cdl.x * f);
            atomicAdd(dst + 1, cdl.y * f);
            atomicAdd(dst + 2, cdl.z * f);
        }
    }
}

// ---------------- fused node kernel (f32x2, unchanged) -------------------
#define NODE_SMEM ((256*64 + 128*64 + 2*2048 + 64) * 4)

__global__ void __launch_bounds__(256, 2) node_kernel(
    const float* __restrict__ h, const float* __restrict__ coordg,
    const float* __restrict__ n_w1, const float* __restrict__ n_w2,
    const float* __restrict__ n_b2,
    const float* __restrict__ ap_w1, const float* __restrict__ ap_w2,
    float* __restrict__ out, int N)
{
    extern __shared__ float sm[];
    float* XnT  = sm;
    float* YnT  = XnT + 256 * 64;
    float* Wbuf = YnT + 128 * 64;
    float* sES  = Wbuf + 2 * 2048;

    const int tid = threadIdx.x;
    const int nb = blockIdx.x * 64;

    {
        const int el = tid & 63, part = tid >> 6;
        int n = nb + el;
        bool v = n < N;
        long nn = v ? (long)n : 0;
        const float4* srcp = (part < 2)
            ? reinterpret_cast<const float4*>(h) + nn * 32 + (part & 1) * 16
            : reinterpret_cast<const float4*>(g_agg) + nn * 32 + (part & 1) * 16;
        int k0 = (part & 1) * 64 + ((part >= 2) ? 128 : 0);
#pragma unroll
        for (int i = 0; i < 16; i++) {
            float4 a = v ? __ldg(srcp + i) : make_float4(0.f, 0.f, 0.f, 0.f);
            int k = k0 + 4 * i;
            XnT[(k+0)*64 + el] = a.x; XnT[(k+1)*64 + el] = a.y;
            XnT[(k+2)*64 + el] = a.z; XnT[(k+3)*64 + el] = a.w;
        }
    }

    const int warp = tid >> 5, lane = tid & 31;
    const int e0 = (warp >> 2) * 32 + (lane >> 2) * 4;
    const int c0 = (warp & 3) * 32 + (lane & 3) * 8;

    UL acc[16];

    init_acc_bias(g_nb1, c0, acc);
    gemm_t<256, 2, 256, 64>(XnT, n_w1, Wbuf, tid, e0, c0, acc);
    epilogue_silu_T(acc, YnT, e0, c0);

    init_acc_bias(n_b2, c0, acc);
    gemm_t<128, 2, 256, 64>(YnT, n_w2, Wbuf, tid, e0, c0, acc);
    {
        float ho[4][8];
#pragma unroll
        for (int p = 0; p < 4; p++) {
            float2 f0 = up2(acc[0*4+p]), f1 = up2(acc[1*4+p]);
            float2 f2 = up2(acc[2*4+p]), f3 = up2(acc[3*4+p]);
            float4 hA = *reinterpret_cast<const float4*>(XnT + (c0 + 2*p) * 64 + e0);
            float4 hB = *reinterpret_cast<const float4*>(XnT + (c0 + 2*p + 1) * 64 + e0);
            ho[0][2*p] = silu_f(f0.x) + hA.x; ho[1][2*p] = silu_f(f1.x) + hA.y;
            ho[2][2*p] = silu_f(f2.x) + hA.z; ho[3][2*p] = silu_f(f3.x) + hA.w;
            ho[0][2*p+1] = silu_f(f0.y) + hB.x; ho[1][2*p+1] = silu_f(f1.y) + hB.y;
            ho[2][2*p+1] = silu_f(f2.y) + hB.z; ho[3][2*p+1] = silu_f(f3.y) + hB.w;
        }
#pragma unroll
        for (int p = 0; p < 8; p++) {
            *reinterpret_cast<float4*>(YnT + (c0 + p) * 64 + e0) =
                make_float4(ho[0][p], ho[1][p], ho[2][p], ho[3][p]);
        }
#pragma unroll
        for (int j = 0; j < 4; j++) {
            int n = nb + e0 + j;
            if (n < N) {
                float* o = out + (long)n * 128 + c0;
                *reinterpret_cast<float4*>(o) =
                    make_float4(ho[j][0], ho[j][1], ho[j][2], ho[j][3]);
                *reinterpret_cast<float4*>(o + 4) =
                    make_float4(ho[j][4], ho[j][5], ho[j][6], ho[j][7]);
            }
        }
    }
    if (tid < 64) sES[tid] = 0.0f;

    init_acc_bias(g_apb1, c0, acc);
    gemm_t<128, 2, 256, 64>(YnT, ap_w1, Wbuf, tid, e0, c0, acc);
    {
        float4 w0 = __ldg(reinterpret_cast<const float4*>(ap_w2 + c0));
        float4 w1 = __ldg(reinterpret_cast<const float4*>(ap_w2 + c0 + 4));
        float wv[8] = { w0.x, w0.y, w0.z, w0.w, w1.x, w1.y, w1.z, w1.w };
#pragma unroll
        for (int j = 0; j < 4; j++) {
            float p = 0.0f;
#pragma unroll
            for (int qq = 0; qq < 4; qq++) {
                float2 f = up2(acc[j*4+qq]);
                p += silu_f(f.x) * wv[2*qq];
                p += silu_f(f.y) * wv[2*qq+1];
            }
            p += __shfl_xor_sync(0xffffffffu, p, 1);
            p += __shfl_xor_sync(0xffffffffu, p, 2);
            if ((lane & 3) == 0) atomicAdd(&sES[e0 + j], p);
        }
    }
    __syncthreads();
    if (tid < 64) {
        int n = nb + tid;
        if (n < N) {
            float s = sES[tid];
            long base_c = (long)N * 128;
            long base_a = (long)N * 131;
            out[base_c + (long)n*3 + 0] = coordg[n*3+0];
            out[base_c + (long)n*3 + 1] = coordg[n*3+1];
            out[base_c + (long)n*3 + 2] = coordg[n*3+2];
            out[base_a + (long)n*3 + 0] = g_aggc[n*3+0] * s;
            out[base_a + (long)n*3 + 1] = g_aggc[n*3+1] * s;
            out[base_a + (long)n*3 + 2] = g_aggc[n*3+2] * s;
        }
    }
}

// ---------------- launch ----------------
extern "C" void kernel_launch(void* const* d_in, const int* in_sizes, int n_in,
                              void* d_out, int out_size)
{
    const float* h      = (const float*)d_in[0];
    const int*   ei     = (const int*)  d_in[1];
    const float* coord  = (const float*)d_in[2];
    const float* eattr  = (const float*)d_in[3];
    const float* prompt = (const float*)d_in[4];
    const float* e_w1   = (const float*)d_in[5];
    const float* e_b1   = (const float*)d_in[6];
    const float* e_w2   = (const float*)d_in[7];
    const float* e_b2   = (const float*)d_in[8];
    const float* n_w1   = (const float*)d_in[9];
    const float* n_b1   = (const float*)d_in[10];
    const float* n_w2   = (const float*)d_in[11];
    const float* n_b2   = (const float*)d_in[12];
    const float* ae_w1  = (const float*)d_in[13];
    const float* ae_b1  = (const float*)d_in[14];
    const float* ae_w2  = (const float*)d_in[15];
    const float* ap_w1  = (const float*)d_in[16];
    const float* ap_b1  = (const float*)d_in[17];
    const float* ap_w2  = (const float*)d_in[18];
    float* out = (float*)d_out;

    int N = in_sizes[0] / 128;
    int E = in_sizes[1] / 2;

    cudaFuncSetAttribute(proj_kernel, cudaFuncAttributeMaxDynamicSharedMemorySize, PROJ_SMEM);
    cudaFuncSetAttribute(edge_kernel, cudaFuncAttributeMaxDynamicSharedMemorySize, EDGE_SMEM);
    cudaFuncSetAttribute(node_kernel, cudaFuncAttributeMaxDynamicSharedMemorySize, NODE_SMEM);

    prep_kernel<<<6, 128>>>(prompt, e_w1, e_b1, n_w1, n_b1,
                            ae_w1, ae_b1, ap_w1, ap_b1, e_w2);
    proj_kernel<<<(N + 63) / 64, 256, PROJ_SMEM>>>(h, e_w1, N);
    edge_kernel<<<(E + 127) / 128, 512, EDGE_SMEM>>>(ei, coord, eattr,
                                                     e_w1, e_b2, ae_w2, E);
    node_kernel<<<(N + 63) / 64, 256, NODE_SMEM>>>(h, coord, n_w1, n_w2, n_b2,
                                                   ap_w1, ap_w2, out, N);
}

// round 14
// speedup vs baseline: 3.2727x; 1.0344x over previous
#include <cuda_runtime.h>
#include <cuda_bf16.h>

typedef unsigned long long UL;

// ---------------- device scratch (no allocations allowed) ----------------
__device__ float g_agg [50000 * 128];   // segment-sum of edge_feat per node
__device__ float g_aggc[50000 * 3];     // segment-sum of trans per node
__device__ float g_P   [50048 * 256];   // per-node projections [P1 | P2]
__device__ float g_eb1 [128];           // e_b1  + prompt @ e_w1[273:401]
__device__ float g_nb1 [128];           // n_b1  + prompt @ n_w1[256:384]
__device__ float g_aeb1[128];           // ae_b1 + prompt @ ae_w1[128:256]
__device__ float g_apb1[128];           // ap_b1 + prompt @ ap_w1[128:256]
// bf16 hi/lo weight tiles, BT[n][k] with 8-way XOR swizzle, 32KB each
__device__ uint4 g_Bw2h[2048];
__device__ uint4 g_Bw2l[2048];
__device__ uint4 g_Baeh[2048];
__device__ uint4 g_Bael[2048];

// ---------------- small helpers ----------------
__device__ __forceinline__ UL bc2(float x) {
    UL r; asm("mov.b64 %0,{%1,%1};" : "=l"(r) : "f"(x)); return r;
}
__device__ __forceinline__ UL pk2(float x, float y) {
    UL r; asm("mov.b64 %0,{%1,%2};" : "=l"(r) : "f"(x), "f"(y)); return r;
}
__device__ __forceinline__ float2 up2(UL v) {
    float2 f; asm("mov.b64 {%0,%1},%2;" : "=f"(f.x), "=f"(f.y) : "l"(v)); return f;
}
__device__ __forceinline__ void fma2(UL &d, UL a, UL b) {
    asm("fma.rn.f32x2 %0,%1,%2,%0;" : "+l"(d) : "l"(a), "l"(b));
}
__device__ __forceinline__ float silu_f(float x) {
    return __fdividef(x, 1.0f + __expf(-x));
}
__device__ __forceinline__ void cpa16(unsigned dst, const float* src) {
    asm volatile("cp.async.cg.shared.global [%0], [%1], 16;" :: "r"(dst), "l"(src));
}
#define CPA_COMMIT() asm volatile("cp.async.commit_group;" ::: "memory")

// row-major [row][128] bf16, 256B row stride, 8-way XOR swizzle on 16B chunks
__device__ __forceinline__ unsigned aoff(int row, int col) {
    return (unsigned)(row * 256 + ((((col >> 3) ^ (row & 7)) << 4) | ((col & 7) * 2)));
}

__device__ __forceinline__ void ldm4(unsigned* r, unsigned addr) {
    asm volatile("ldmatrix.sync.aligned.m8n8.x4.shared.b16 {%0,%1,%2,%3}, [%4];"
        : "=r"(r[0]), "=r"(r[1]), "=r"(r[2]), "=r"(r[3]) : "r"(addr));
}
__device__ __forceinline__ void mma16816(float* c, const unsigned* a,
                                         unsigned b0, unsigned b1) {
    asm volatile(
        "mma.sync.aligned.m16n8k16.row.col.f32.bf16.bf16.f32 "
        "{%0,%1,%2,%3}, {%4,%5,%6,%7}, {%8,%9}, {%0,%1,%2,%3};"
        : "+f"(c[0]), "+f"(c[1]), "+f"(c[2]), "+f"(c[3])
        : "r"(a[0]), "r"(a[1]), "r"(a[2]), "r"(a[3]), "r"(b0), "r"(b1));
}

// 16 packed FMAs for one k-row: 4 rows x 4 col-pairs
#define FMAROW(WA, WB, S0, S1, S2, S3)                            \
    do {                                                          \
        fma2(acc[0],  S0, WA.x); fma2(acc[1],  S0, WA.y);         \
        fma2(acc[2],  S0, WB.x); fma2(acc[3],  S0, WB.y);         \
        fma2(acc[4],  S1, WA.x); fma2(acc[5],  S1, WA.y);         \
        fma2(acc[6],  S1, WB.x); fma2(acc[7],  S1, WB.y);         \
        fma2(acc[8],  S2, WA.x); fma2(acc[9],  S2, WA.y);         \
        fma2(acc[10], S2, WB.x); fma2(acc[11], S2, WB.y);         \
        fma2(acc[12], S3, WA.x); fma2(acc[13], S3, WA.y);         \
        fma2(acc[14], S3, WB.x); fma2(acc[15], S3, WB.y);         \
    } while (0)

__device__ __forceinline__ void init_acc_bias(const float* biasg, int c0, UL* acc)
{
    float4 b0 = __ldg(reinterpret_cast<const float4*>(biasg + c0));
    float4 b1 = __ldg(reinterpret_cast<const float4*>(biasg + c0 + 4));
    UL bp0 = pk2(b0.x, b0.y), bp1 = pk2(b0.z, b0.w);
    UL bp2 = pk2(b1.x, b1.y), bp3 = pk2(b1.z, b1.w);
#pragma unroll
    for (int j = 0; j < 4; j++) {
        acc[j*4+0] = bp0; acc[j*4+1] = bp1; acc[j*4+2] = bp2; acc[j*4+3] = bp3;
    }
}
__device__ __forceinline__ void init_acc_zero(UL* acc)
{
    UL z = pk2(0.0f, 0.0f);
#pragma unroll
    for (int j = 0; j < 16; j++) acc[j] = z;
}

// ------- f32x2 GEMM, transposed X tile, cp.async ring (NT threads) ------
template<int K, int DEPTH, int NT, int XSTR>
__device__ __forceinline__ void gemm_t(
    const float* XsT, const float* __restrict__ Wg,
    float* Wbuf, int tid, int e0, int c0, UL* acc)
{
    constexpr int CH = (K + 15) / 16;
    constexpr int PF = 2048 / NT;   // floats staged per thread per chunk

    const float* src = Wg + tid * PF;
    unsigned dstb = (unsigned)__cvta_generic_to_shared(Wbuf) + tid * PF * 4;

#pragma unroll
    for (int p = 0; p < DEPTH - 1; p++) {
        if (p < CH) {
            unsigned d = dstb + p * 8192;
            const float* s = src + p * 2048;
            cpa16(d, s);
            if (PF == 8) cpa16(d + 16, s + 4);
        }
        CPA_COMMIT();
    }

    const float* xb = XsT + e0;
    int cons = 0, nxt = (DEPTH - 1) % DEPTH;

    for (int c = 0; c < CH; c++) {
        asm volatile("cp.async.wait_group %0;" :: "n"(DEPTH - 2) : "memory");
        __syncthreads();
        if (c + DEPTH - 1 < CH) {
            unsigned d = dstb + nxt * 8192;
            const float* s = src + (c + DEPTH - 1) * 2048;
            cpa16(d, s);
            if (PF == 8) cpa16(d + 16, s + 4);
        }
        CPA_COMMIT();

        const float* wb = Wbuf + cons * 2048 + c0;
        const int kb = c * 16;
        const float* xk = xb + kb * XSTR;
        if (kb + 16 <= K) {
#pragma unroll
            for (int kk = 0; kk < 16; kk++) {
                float4 xv = *reinterpret_cast<const float4*>(xk + kk * XSTR);
                ulonglong2 a = *reinterpret_cast<const ulonglong2*>(wb + kk * 128);
                ulonglong2 b = *reinterpret_cast<const ulonglong2*>(wb + kk * 128 + 4);
                UL s0 = bc2(xv.x), s1 = bc2(xv.y), s2 = bc2(xv.z), s3 = bc2(xv.w);
                FMAROW(a, b, s0, s1, s2, s3);
            }
        } else {
            for (int kk = 0; kk < K - kb; kk++) {
                float4 xv = *reinterpret_cast<const float4*>(xk + kk * XSTR);
                ulonglong2 a = *reinterpret_cast<const ulonglong2*>(wb + kk * 128);
                ulonglong2 b = *reinterpret_cast<const ulonglong2*>(wb + kk * 128 + 4);
                UL s0 = bc2(xv.x), s1 = bc2(xv.y), s2 = bc2(xv.z), s3 = bc2(xv.w);
                FMAROW(a, b, s0, s1, s2, s3);
            }
        }
        cons++; if (cons == DEPTH) cons = 0;
        nxt++;  if (nxt == DEPTH)  nxt = 0;
    }
    asm volatile("cp.async.wait_group 0;" ::: "memory");
    __syncthreads();
}

// write 8 cols x 4 rows of silu(acc) into transposed tile T[col][row64]
__device__ __forceinline__ void epilogue_silu_T(UL* acc, float* T, int e0, int c0)
{
#pragma unroll
    for (int p = 0; p < 4; p++) {
        float2 f0 = up2(acc[0*4+p]), f1 = up2(acc[1*4+p]);
        float2 f2 = up2(acc[2*4+p]), f3 = up2(acc[3*4+p]);
        *reinterpret_cast<float4*>(T + (c0 + 2*p) * 64 + e0) =
            make_float4(silu_f(f0.x), silu_f(f1.x), silu_f(f2.x), silu_f(f3.x));
        *reinterpret_cast<float4*>(T + (c0 + 2*p + 1) * 64 + e0) =
            make_float4(silu_f(f0.y), silu_f(f1.y), silu_f(f2.y), silu_f(f3.y));
    }
}

// bf16 hi/lo split store of a col-pair (col even) into A tiles
__device__ __forceinline__ void store_bf16_pair(
    char* AhB, char* AlB, int row, int col, float z0, float z1)
{
    __nv_bfloat16 h0 = __float2bfloat16(z0);
    __nv_bfloat16 h1 = __float2bfloat16(z1);
    __nv_bfloat16 l0 = __float2bfloat16(z0 - __bfloat162float(h0));
    __nv_bfloat16 l1 = __float2bfloat16(z1 - __bfloat162float(h1));
    unsigned uh = (unsigned)*reinterpret_cast<unsigned short*>(&h0)
                | ((unsigned)*reinterpret_cast<unsigned short*>(&h1) << 16);
    unsigned ul = (unsigned)*reinterpret_cast<unsigned short*>(&l0)
                | ((unsigned)*reinterpret_cast<unsigned short*>(&l1) << 16);
    unsigned off = aoff(row, col);
    *reinterpret_cast<unsigned*>(AhB + off) = uh;
    *reinterpret_cast<unsigned*>(AlB + off) = ul;
}

// 3-term bf16-split 32x32 warp-tile GEMM over K=128 (mma.sync m16n8k16)
__device__ __forceinline__ void mma_gemm(
    unsigned AhU, unsigned AlU, unsigned BhU, unsigned BlU,
    int m0, int n0, int lane, float c[2][4][4])
{
#pragma unroll
    for (int i = 0; i < 2; i++)
#pragma unroll
        for (int j = 0; j < 4; j++)
#pragma unroll
            for (int q = 0; q < 4; q++) c[i][j][q] = 0.0f;

    const int mi = lane >> 3;
    const int rAoff = ((mi & 1) << 3) + (lane & 7);   // A: mi bit0 = m-half
    const int kHalfA = mi >> 1;                       //    mi bit1 = k-half
    const int nOff = ((mi >> 1) << 3) + (lane & 7);   // B: mi bit1 = n-half
    const int kHalfB = mi & 1;                        //    mi bit0 = k-half

#pragma unroll
    for (int k0 = 0; k0 < 128; k0 += 16) {
        unsigned ah[2][4], al[2][4], bh[2][4], bl[2][4];
        const int kcA = (k0 >> 3) + kHalfA;
        const int kcB = (k0 >> 3) + kHalfB;
#pragma unroll
        for (int i = 0; i < 2; i++) {
            int row = m0 + 16 * i + rAoff;
            unsigned off = (unsigned)(row * 256 + ((kcA ^ (row & 7)) << 4));
            ldm4(ah[i], AhU + off);
            ldm4(al[i], AlU + off);
        }
#pragma unroll
        for (int j2 = 0; j2 < 2; j2++) {
            int nrow = n0 + 16 * j2 + nOff;
            unsigned off = (unsigned)(nrow * 256 + ((kcB ^ (nrow & 7)) << 4));
            ldm4(bh[j2], BhU + off);
            ldm4(bl[j2], BlU + off);
        }
#pragma unroll
        for (int i = 0; i < 2; i++) {
#pragma unroll
            for (int jt = 0; jt < 4; jt++) {
                int j2 = jt >> 1, s = jt & 1;
                mma16816(c[i][jt], ah[i], bh[j2][2*s], bh[j2][2*s+1]);
                mma16816(c[i][jt], ah[i], bl[j2][2*s], bl[j2][2*s+1]);
                mma16816(c[i][jt], al[i], bh[j2][2*s], bh[j2][2*s+1]);
            }
        }
    }
}

// ---------------- prep: prompt-biases + bf16-split BT weight tiles -------
__global__ void prep_kernel(
    const float* __restrict__ prompt,
    const float* __restrict__ e_w1,  const float* __restrict__ e_b1,
    const float* __restrict__ n_w1,  const float* __restrict__ n_b1,
    const float* __restrict__ ae_w1, const float* __restrict__ ae_b1,
    const float* __restrict__ ap_w1, const float* __restrict__ ap_b1,
    const float* __restrict__ e_w2)
{
    int n = threadIdx.x;
    int b = blockIdx.x;
    if (b < 4) {
        const float* w; const float* bias; float* dst; int off;
        if (b == 0)      { w = e_w1;  bias = e_b1;  dst = g_eb1;  off = 273; }
        else if (b == 1) { w = n_w1;  bias = n_b1;  dst = g_nb1;  off = 256; }
        else if (b == 2) { w = ae_w1; bias = ae_b1; dst = g_aeb1; off = 128; }
        else             { w = ap_w1; bias = ap_b1; dst = g_apb1; off = 128; }
        float s = bias[n];
        for (int j = 0; j < 128; j++)
            s = fmaf(prompt[j], w[(off + j) * 128 + n], s);
        dst[n] = s;
    } else {
        const float* W; char* BH; char* BL;
        if (b == 4) { W = e_w2;  BH = (char*)g_Bw2h; BL = (char*)g_Bw2l; }
        else        { W = ae_w1; BH = (char*)g_Baeh; BL = (char*)g_Bael; }
        for (int i = n; i < 16384; i += 128) {
            int nn = i >> 7, k = i & 127;
            float v = W[k * 128 + nn];             // BT[nn][k] = W[k][nn]
            __nv_bfloat16 h = __float2bfloat16(v);
            __nv_bfloat16 l = __float2bfloat16(v - __bfloat162float(h));
            unsigned off = aoff(nn, k);
            *reinterpret_cast<unsigned short*>(BH + off) =
                *reinterpret_cast<unsigned short*>(&h);
            *reinterpret_cast<unsigned short*>(BL + off) =
                *reinterpret_cast<unsigned short*>(&l);
        }
    }
}

// ---------------- node projection kernel: g_P = h @ [W1a | W1b] ---------
#define PROJ_SMEM ((128*64 + 4*2048) * 4)

__global__ void __launch_bounds__(256, 2) proj_kernel(
    const float* __restrict__ h, const float* __restrict__ e_w1, int N)
{
    extern __shared__ float sm[];
    float* hT   = sm;
    float* Wbuf = hT + 128 * 64;

    const int tid = threadIdx.x;
    const int nb = blockIdx.x * 64;

    {
        const int el = tid & 63, part = tid >> 6;
        int n = nb + el;
        if (n < N) {
            float4 z4 = make_float4(0.f, 0.f, 0.f, 0.f);
            float4* ga = reinterpret_cast<float4*>(g_agg + (long)n * 128) + part * 8;
#pragma unroll
            for (int i = 0; i < 8; i++) ga[i] = z4;
            if (part == 0) {
                g_aggc[(long)n*3+0] = 0.f;
                g_aggc[(long)n*3+1] = 0.f;
                g_aggc[(long)n*3+2] = 0.f;
            }
        }
    }
    {
        const int el = tid & 63, part = tid >> 6;
        int n = nb + el;
        bool v = n < N;
        long nn = v ? (long)n : 0;
        const float4* hr = reinterpret_cast<const float4*>(h) + nn * 32 + part * 8;
#pragma unroll
        for (int i = 0; i < 8; i++) {
            float4 a = v ? __ldg(hr + i) : make_float4(0.f, 0.f, 0.f, 0.f);
            int k = part * 32 + 4 * i;
            hT[(k+0)*64 + el] = a.x; hT[(k+1)*64 + el] = a.y;
            hT[(k+2)*64 + el] = a.z; hT[(k+3)*64 + el] = a.w;
        }
    }
    const int warp = tid >> 5, lane = tid & 31;
    const int e0 = (warp >> 2) * 32 + (lane >> 2) * 4;
    const int c0 = (warp & 3) * 32 + (lane & 3) * 8;

    UL acc[16];

    init_acc_zero(acc);
    gemm_t<128, 4, 256, 64>(hT, e_w1, Wbuf, tid, e0, c0, acc);
#pragma unroll
    for (int j = 0; j < 4; j++) {
        int n = nb + e0 + j;
        if (n < N) {
            float2 f0 = up2(acc[j*4+0]), f1 = up2(acc[j*4+1]);
            float2 f2 = up2(acc[j*4+2]), f3 = up2(acc[j*4+3]);
            float* o = g_P + (long)n * 256 + c0;
            *reinterpret_cast<float4*>(o)     = make_float4(f0.x, f0.y, f1.x, f1.y);
            *reinterpret_cast<float4*>(o + 4) = make_float4(f2.x, f2.y, f3.x, f3.y);
        }
    }

    init_acc_zero(acc);
    gemm_t<128, 4, 256, 64>(hT, e_w1 + 128 * 128, Wbuf, tid, e0, c0, acc);
#pragma unroll
    for (int j = 0; j < 4; j++) {
        int n = nb + e0 + j;
        if (n < N) {
            float2 f0 = up2(acc[j*4+0]), f1 = up2(acc[j*4+1]);
            float2 f2 = up2(acc[j*4+2]), f3 = up2(acc[j*4+3]);
            float* o = g_P + (long)n * 256 + 128 + c0;
            *reinterpret_cast<float4*>(o)     = make_float4(f0.x, f0.y, f1.x, f1.y);
            *reinterpret_cast<float4*>(o + 4) = make_float4(f2.x, f2.y, f3.x, f3.y);
        }
    }
}

// ---------------- fused edge kernel (mma.sync, 64 edges, 2 CTAs/SM) ------
// byte map: Ah 0 (16384) | Al 16384 | Bh 32768 (32768) | Bl 65536
//   W1s 98304 (8704) | XeT 107008 (4352) | cd 111360 (1024)
//   sES 112384 (256) | rowi 112640 (256) | coli 112896 (256)
#define OFF_AL  16384
#define OFF_BH  32768
#define OFF_BL  65536
#define OFF_W1  98304
#define OFF_XE  107008
#define OFF_CD  111360
#define OFF_SES 112384
#define OFF_ROW 112640
#define OFF_COL 112896
#define EDGE_SMEM 113152

__global__ void __launch_bounds__(256, 2) edge_kernel(
    const int* __restrict__ ei,
    const float* __restrict__ coord, const float* __restrict__ eattr,
    const float* __restrict__ e_w1, const float* __restrict__ e_b2,
    const float* __restrict__ ae_w2, int E)
{
    extern __shared__ float sm[];
    char* base = reinterpret_cast<char*>(sm);
    char* AhB = base;
    char* AlB = base + OFF_AL;
    float* W1s  = reinterpret_cast<float*>(base + OFF_W1);
    float* XeT  = reinterpret_cast<float*>(base + OFF_XE);
    float4* cd  = reinterpret_cast<float4*>(base + OFF_CD);
    float*  sES = reinterpret_cast<float*>(base + OFF_SES);
    int*   rowi = reinterpret_cast<int*>(base + OFF_ROW);
    int*   coli = reinterpret_cast<int*>(base + OFF_COL);
    unsigned smem_u = (unsigned)__cvta_generic_to_shared(base);

    const int tid = threadIdx.x;
    const int wid = tid >> 5, lane = tid & 31;
    const int e_base = blockIdx.x * 64;
    const int* rowg = ei;
    const int* colg = ei + E;

    // group 0: e_w2 hi/lo B tiles (128B per thread per tile)
    {
        const float* s0 = reinterpret_cast<const float*>(g_Bw2h) + tid * 32;
        const float* s1 = reinterpret_cast<const float*>(g_Bw2l) + tid * 32;
        unsigned d0 = smem_u + OFF_BH + tid * 128;
        unsigned d1 = smem_u + OFF_BL + tid * 128;
#pragma unroll
        for (int i = 0; i < 8; i++) {
            cpa16(d0 + i * 16, s0 + i * 4);
            cpa16(d1 + i * 16, s1 + i * 4);
        }
        CPA_COMMIT();
    }
    // group 1: W1c (17x128 fp32 = 544 float4)
    {
        const float* wsrc = e_w1 + 256 * 128;
        for (int i = tid; i < 544; i += 256)
            cpa16(smem_u + OFF_W1 + i * 16, wsrc + i * 4);
        CPA_COMMIT();
    }

    // ------- stage XeT: row0 = radial, rows 1..16 = eattr^T; indices -----
    {
        const int el = tid & 63, part = tid >> 6;
        int e = e_base + el;
        bool v = e < E;
        if (part == 0) {
            long r = v ? (long)rowg[e] : 0;
            long c = v ? (long)colg[e] : 0;
            rowi[el] = (int)r;
            coli[el] = (int)c;
            float dx = 0.f, dy = 0.f, dz = 0.f;
            if (v) {
                dx = coord[r*3+0] - coord[c*3+0];
                dy = coord[r*3+1] - coord[c*3+1];
                dz = coord[r*3+2] - coord[c*3+2];
            }
            float rad = dx*dx + dy*dy + dz*dz;
            XeT[el] = rad;
            float inv = 1.0f / fmaxf(sqrtf(rad), 1e-12f);
            cd[el] = make_float4(dx, dy, dz, inv);
        } else if (part == 1) {
            const float4* ea = reinterpret_cast<const float4*>(eattr) + (long)e * 4;
#pragma unroll
            for (int i = 0; i < 4; i++) {
                float4 a = v ? __ldg(ea + i) : make_float4(0.f, 0.f, 0.f, 0.f);
                int k = 1 + 4 * i;
                XeT[(k+0)*64 + el] = a.x; XeT[(k+1)*64 + el] = a.y;
                XeT[(k+2)*64 + el] = a.z; XeT[(k+3)*64 + el] = a.w;
            }
        }
    }
    asm volatile("cp.async.wait_group 0;" ::: "memory");
    __syncthreads();

    const int e0 = (wid >> 2) * 32 + (lane >> 2) * 4;
    const int c0 = (wid & 3) * 32 + (lane & 3) * 8;

    UL acc[16];

    // ------- acc init: eb1_eff + P1[row] + P2[col] -----------------------
    {
        float4 b0 = __ldg(reinterpret_cast<const float4*>(g_eb1 + c0));
        float4 b1 = __ldg(reinterpret_cast<const float4*>(g_eb1 + c0 + 4));
#pragma unroll
        for (int j = 0; j < 4; j++) {
            int r = rowi[e0 + j], cc = coli[e0 + j];
            const float* pr = g_P + (long)r  * 256 + c0;
            const float* pc = g_P + (long)cc * 256 + 128 + c0;
            float4 p0 = __ldg(reinterpret_cast<const float4*>(pr));
            float4 p1 = __ldg(reinterpret_cast<const float4*>(pr + 4));
            float4 q0 = __ldg(reinterpret_cast<const float4*>(pc));
            float4 q1 = __ldg(reinterpret_cast<const float4*>(pc + 4));
            acc[j*4+0] = pk2(b0.x + p0.x + q0.x, b0.y + p0.y + q0.y);
            acc[j*4+1] = pk2(b0.z + p0.z + q0.z, b0.w + p0.w + q0.w);
            acc[j*4+2] = pk2(b1.x + p1.x + q1.x, b1.y + p1.y + q1.y);
            acc[j*4+3] = pk2(b1.z + p1.z + q1.z, b1.w + p1.w + q1.w);
        }
    }

    // ------- GEMM1 (K=17, f32x2) from staged W1s/XeT ---------------------
#pragma unroll
    for (int k = 0; k < 17; k++) {
        float4 xv = *reinterpret_cast<const float4*>(XeT + k * 64 + e0);
        const float* wb = W1s + k * 128 + c0;
        ulonglong2 a = *reinterpret_cast<const ulonglong2*>(wb);
        ulonglong2 b = *reinterpret_cast<const ulonglong2*>(wb + 4);
        UL s0 = bc2(xv.x), s1 = bc2(xv.y), s2 = bc2(xv.z), s3 = bc2(xv.w);
        FMAROW(a, b, s0, s1, s2, s3);
    }
#pragma unroll
    for (int j = 0; j < 4; j++) {
        int r = e0 + j;
#pragma unroll
        for (int p = 0; p < 4; p++) {
            float2 f = up2(acc[j*4+p]);
            store_bf16_pair(AhB, AlB, r, c0 + 2*p, silu_f(f.x), silu_f(f.y));
        }
    }
    if (tid < 64) sES[tid] = 0.0f;
    __syncthreads();

    const int m0 = (wid >> 2) * 32;
    const int n0 = (wid & 3) * 32;
    const int g  = lane >> 2;
    const int q  = lane & 3;

    float c[2][4][4];

    // ------- GEMM2: edge hidden @ e_w2  (tensor cores) -------------------
    mma_gemm(smem_u + 0, smem_u + OFF_AL, smem_u + OFF_BH, smem_u + OFF_BL,
             m0, n0, lane, c);
    __syncthreads();   // all warps done reading A and B before overwrite

    // stream ae_w1 hi/lo into the B buffers (overlaps epilogue below)
    {
        const float* s0 = reinterpret_cast<const float*>(g_Baeh) + tid * 32;
        const float* s1 = reinterpret_cast<const float*>(g_Bael) + tid * 32;
        unsigned d0 = smem_u + OFF_BH + tid * 128;
        unsigned d1 = smem_u + OFF_BL + tid * 128;
#pragma unroll
        for (int i = 0; i < 8; i++) {
            cpa16(d0 + i * 16, s0 + i * 4);
            cpa16(d1 + i * 16, s1 + i * 4);
        }
        CPA_COMMIT();
    }

    // epilogue: bias+silu, store edge_feat to A tiles, g_agg atomics
#pragma unroll
    for (int i = 0; i < 2; i++) {
        int r0 = m0 + 16 * i + g;
#pragma unroll
        for (int jt = 0; jt < 4; jt++) {
            int col = n0 + 8 * jt + q * 2;
            float bx = __ldg(e_b2 + col), by = __ldg(e_b2 + col + 1);
            float z0 = silu_f(c[i][jt][0] + bx);
            float z1 = silu_f(c[i][jt][1] + by);
            float z2 = silu_f(c[i][jt][2] + bx);
            float z3 = silu_f(c[i][jt][3] + by);
            store_bf16_pair(AhB, AlB, r0,     col, z0, z1);
            store_bf16_pair(AhB, AlB, r0 + 8, col, z2, z3);
            if (e_base + r0 < E)
                atomicAdd(reinterpret_cast<float2*>(
                    g_agg + (long)rowi[r0] * 128 + col), make_float2(z0, z1));
            if (e_base + r0 + 8 < E)
                atomicAdd(reinterpret_cast<float2*>(
                    g_agg + (long)rowi[r0 + 8] * 128 + col), make_float2(z2, z3));
        }
    }
    asm volatile("cp.async.wait_group 0;" ::: "memory");
    __syncthreads();   // edge_feat + ae tiles visible to all warps

    // ------- GEMM3: edge_feat @ ae_w1  (tensor cores) --------------------
    mma_gemm(smem_u + 0, smem_u + OFF_AL, smem_u + OFF_BH, smem_u + OFF_BL,
             m0, n0, lane, c);

    // epilogue: silu(c + aeb1) dot ae_w2 -> per-row sums in sES
    {
        float s[4] = {0.f, 0.f, 0.f, 0.f};   // rows m0+g, +8, +16, +24
#pragma unroll
        for (int i = 0; i < 2; i++) {
#pragma unroll
            for (int jt = 0; jt < 4; jt++) {
                int col = n0 + 8 * jt + q * 2;
                float bx = __ldg(g_aeb1 + col), by = __ldg(g_aeb1 + col + 1);
                float wx = __ldg(ae_w2 + col),  wy = __ldg(ae_w2 + col + 1);
                s[2*i]   += silu_f(c[i][jt][0] + bx) * wx
                          + silu_f(c[i][jt][1] + by) * wy;
                s[2*i+1] += silu_f(c[i][jt][2] + bx) * wx
                          + silu_f(c[i][jt][3] + by) * wy;
            }
        }
#pragma unroll
        for (int t = 0; t < 4; t++) {
            s[t] += __shfl_xor_sync(0xffffffffu, s[t], 1);
            s[t] += __shfl_xor_sync(0xffffffffu, s[t], 2);
        }
        if (q == 0) {
            atomicAdd(&sES[m0 + g],      s[0]);
            atomicAdd(&sES[m0 + 8 + g],  s[1]);
            atomicAdd(&sES[m0 + 16 + g], s[2]);
            atomicAdd(&sES[m0 + 24 + g], s[3]);
        }
    }
    __syncthreads();

    if (tid < 64) {
        int eg = e_base + tid;
        if (eg < E) {
            float sv = sES[tid];
            float4 cdl = cd[tid];
            float f = sv * cdl.w;
            float* dst = g_aggc + (long)rowi[tid] * 3;
            atomicAdd(dst + 0, cdl.x * f);
            atomicAdd(dst + 1, cdl.y * f);
            atomicAdd(dst + 2, cdl.z * f);
        }
    }
}

// ---------------- fused node kernel (f32x2, unchanged) -------------------
#define NODE_SMEM ((256*64 + 128*64 + 2*2048 + 64) * 4)

__global__ void __launch_bounds__(256, 2) node_kernel(
    const float* __restrict__ h, const float* __restrict__ coordg,
    const float* __restrict__ n_w1, const float* __restrict__ n_w2,
    const float* __restrict__ n_b2,
    const float* __restrict__ ap_w1, const float* __restrict__ ap_w2,
    float* __restrict__ out, int N)
{
    extern __shared__ float sm[];
    float* XnT  = sm;
    float* YnT  = XnT + 256 * 64;
    float* Wbuf = YnT + 128 * 64;
    float* sES  = Wbuf + 2 * 2048;

    const int tid = threadIdx.x;
    const int nb = blockIdx.x * 64;

    {
        const int el = tid & 63, part = tid >> 6;
        int n = nb + el;
        bool v = n < N;
        long nn = v ? (long)n : 0;
        const float4* srcp = (part < 2)
            ? reinterpret_cast<const float4*>(h) + nn * 32 + (part & 1) * 16
            : reinterpret_cast<const float4*>(g_agg) + nn * 32 + (part & 1) * 16;
        int k0 = (part & 1) * 64 + ((part >= 2) ? 128 : 0);
#pragma unroll
        for (int i = 0; i < 16; i++) {
            float4 a = v ? __ldg(srcp + i) : make_float4(0.f, 0.f, 0.f, 0.f);
            int k = k0 + 4 * i;
            XnT[(k+0)*64 + el] = a.x; XnT[(k+1)*64 + el] = a.y;
            XnT[(k+2)*64 + el] = a.z; XnT[(k+3)*64 + el] = a.w;
        }
    }

    const int warp = tid >> 5, lane = tid & 31;
    const int e0 = (warp >> 2) * 32 + (lane >> 2) * 4;
    const int c0 = (warp & 3) * 32 + (lane & 3) * 8;

    UL acc[16];

    init_acc_bias(g_nb1, c0, acc);
    gemm_t<256, 2, 256, 64>(XnT, n_w1, Wbuf, tid, e0, c0, acc);
    epilogue_silu_T(acc, YnT, e0, c0);

    init_acc_bias(n_b2, c0, acc);
    gemm_t<128, 2, 256, 64>(YnT, n_w2, Wbuf, tid, e0, c0, acc);
    {
        float ho[4][8];
#pragma unroll
        for (int p = 0; p < 4; p++) {
            float2 f0 = up2(acc[0*4+p]), f1 = up2(acc[1*4+p]);
            float2 f2 = up2(acc[2*4+p]), f3 = up2(acc[3*4+p]);
            float4 hA = *reinterpret_cast<const float4*>(XnT + (c0 + 2*p) * 64 + e0);
            float4 hB = *reinterpret_cast<const float4*>(XnT + (c0 + 2*p + 1) * 64 + e0);
            ho[0][2*p] = silu_f(f0.x) + hA.x; ho[1][2*p] = silu_f(f1.x) + hA.y;
            ho[2][2*p] = silu_f(f2.x) + hA.z; ho[3][2*p] = silu_f(f3.x) + hA.w;
            ho[0][2*p+1] = silu_f(f0.y) + hB.x; ho[1][2*p+1] = silu_f(f1.y) + hB.y;
            ho[2][2*p+1] = silu_f(f2.y) + hB.z; ho[3][2*p+1] = silu_f(f3.y) + hB.w;
        }
#pragma unroll
        for (int p = 0; p < 8; p++) {
            *reinterpret_cast<float4*>(YnT + (c0 + p) * 64 + e0) =
                make_float4(ho[0][p], ho[1][p], ho[2][p], ho[3][p]);
        }
#pragma unroll
        for (int j = 0; j < 4; j++) {
            int n = nb + e0 + j;
            if (n < N) {
                float* o = out + (long)n * 128 + c0;
                *reinterpret_cast<float4*>(o) =
                    make_float4(ho[j][0], ho[j][1], ho[j][2], ho[j][3]);
                *reinterpret_cast<float4*>(o + 4) =
                    make_float4(ho[j][4], ho[j][5], ho[j][6], ho[j][7]);
            }
        }
    }
    if (tid < 64) sES[tid] = 0.0f;

    init_acc_bias(g_apb1, c0, acc);
    gemm_t<128, 2, 256, 64>(YnT, ap_w1, Wbuf, tid, e0, c0, acc);
    {
        float4 w0 = __ldg(reinterpret_cast<const float4*>(ap_w2 + c0));
        float4 w1 = __ldg(reinterpret_cast<const float4*>(ap_w2 + c0 + 4));
        float wv[8] = { w0.x, w0.y, w0.z, w0.w, w1.x, w1.y, w1.z, w1.w };
#pragma unroll
        for (int j = 0; j < 4; j++) {
            float p = 0.0f;
#pragma unroll
            for (int qq = 0; qq < 4; qq++) {
                float2 f = up2(acc[j*4+qq]);
                p += silu_f(f.x) * wv[2*qq];
                p += silu_f(f.y) * wv[2*qq+1];
            }
            p += __shfl_xor_sync(0xffffffffu, p, 1);
            p += __shfl_xor_sync(0xffffffffu, p, 2);
            if ((lane & 3) == 0) atomicAdd(&sES[e0 + j], p);
        }
    }
    __syncthreads();
    if (tid < 64) {
        int n = nb + tid;
        if (n < N) {
            float s = sES[tid];
            long base_c = (long)N * 128;
            long base_a = (long)N * 131;
            out[base_c + (long)n*3 + 0] = coordg[n*3+0];
            out[base_c + (long)n*3 + 1] = coordg[n*3+1];
            out[base_c + (long)n*3 + 2] = coordg[n*3+2];
            out[base_a + (long)n*3 + 0] = g_aggc[n*3+0] * s;
            out[base_a + (long)n*3 + 1] = g_aggc[n*3+1] * s;
            out[base_a + (long)n*3 + 2] = g_aggc[n*3+2] * s;
        }
    }
}

// ---------------- launch ----------------
extern "C" void kernel_launch(void* const* d_in, const int* in_sizes, int n_in,
                              void* d_out, int out_size)
{
    const float* h      = (const float*)d_in[0];
    const int*   ei     = (const int*)  d_in[1];
    const float* coord  = (const float*)d_in[2];
    const float* eattr  = (const float*)d_in[3];
    const float* prompt = (const float*)d_in[4];
    const float* e_w1   = (const float*)d_in[5];
    const float* e_b1   = (const float*)d_in[6];
    const float* e_w2   = (const float*)d_in[7];
    const float* e_b2   = (const float*)d_in[8];
    const float* n_w1   = (const float*)d_in[9];
    const float* n_b1   = (const float*)d_in[10];
    const float* n_w2   = (const float*)d_in[11];
    const float* n_b2   = (const float*)d_in[12];
    const float* ae_w1  = (const float*)d_in[13];
    const float* ae_b1  = (const float*)d_in[14];
    const float* ae_w2  = (const float*)d_in[15];
    const float* ap_w1  = (const float*)d_in[16];
    const float* ap_b1  = (const float*)d_in[17];
    const float* ap_w2  = (const float*)d_in[18];
    float* out = (float*)d_out;

    int N = in_sizes[0] / 128;
    int E = in_sizes[1] / 2;

    cudaFuncSetAttribute(proj_kernel, cudaFuncAttributeMaxDynamicSharedMemorySize, PROJ_SMEM);
    cudaFuncSetAttribute(edge_kernel, cudaFuncAttributeMaxDynamicSharedMemorySize, EDGE_SMEM);
    cudaFuncSetAttribute(node_kernel, cudaFuncAttributeMaxDynamicSharedMemorySize, NODE_SMEM);

    prep_kernel<<<6, 128>>>(prompt, e_w1, e_b1, n_w1, n_b1,
                            ae_w1, ae_b1, ap_w1, ap_b1, e_w2);
    proj_kernel<<<(N + 63) / 64, 256, PROJ_SMEM>>>(h, e_w1, N);
    edge_kernel<<<(E + 63) / 64, 256, EDGE_SMEM>>>(ei, coord, eattr,
                                                   e_w1, e_b2, ae_w2, E);
    node_kernel<<<(N + 63) / 64, 256, NODE_SMEM>>>(h, coord, n_w1, n_w2, n_b2,
                                                   ap_w1, ap_w2, out, N);
}

// round 16
// speedup vs baseline: 3.5479x; 1.0841x over previous
#include <cuda_runtime.h>
#include <cuda_bf16.h>

typedef unsigned long long UL;

// ---------------- device scratch (no allocations allowed) ----------------
__device__ float g_agg [50000 * 128];   // segment-sum of edge_feat per node
__device__ float g_aggc[50000 * 3];     // segment-sum of trans per node
__device__ float g_P   [50048 * 256];   // per-node projections [P1 | P2]
__device__ float g_eb1 [128];           // e_b1  + prompt @ e_w1[273:401]
__device__ float g_nb1 [128];           // n_b1  + prompt @ n_w1[256:384]
__device__ float g_aeb1[128];           // ae_b1 + prompt @ ae_w1[128:256]
__device__ float g_apb1[128];           // ap_b1 + prompt @ ap_w1[128:256]
__device__ float g_apw2c[128];          // copy of ap_w2
// bf16 hi/lo weight tiles, BT[n][k] with 8-way XOR swizzle, 32KB each
__device__ uint4 g_Bw2h [2048];  __device__ uint4 g_Bw2l [2048];   // e_w2
__device__ uint4 g_Baeh [2048];  __device__ uint4 g_Bael [2048];   // ae_w1
__device__ uint4 g_Bn1ah[2048];  __device__ uint4 g_Bn1al[2048];   // n_w1 k0
__device__ uint4 g_Bn1bh[2048];  __device__ uint4 g_Bn1bl[2048];   // n_w1 k1
__device__ uint4 g_Bn2h [2048];  __device__ uint4 g_Bn2l [2048];   // n_w2
__device__ uint4 g_Baph [2048];  __device__ uint4 g_Bapl [2048];   // ap_w1
__device__ uint4 g_Be1ah[2048];  __device__ uint4 g_Be1al[2048];   // e_w1 k0
__device__ uint4 g_Be1bh[2048];  __device__ uint4 g_Be1bl[2048];   // e_w1 k1

// ---------------- small helpers ----------------
__device__ __forceinline__ UL bc2(float x) {
    UL r; asm("mov.b64 %0,{%1,%1};" : "=l"(r) : "f"(x)); return r;
}
__device__ __forceinline__ UL pk2(float x, float y) {
    UL r; asm("mov.b64 %0,{%1,%2};" : "=l"(r) : "f"(x), "f"(y)); return r;
}
__device__ __forceinline__ float2 up2(UL v) {
    float2 f; asm("mov.b64 {%0,%1},%2;" : "=f"(f.x), "=f"(f.y) : "l"(v)); return f;
}
__device__ __forceinline__ void fma2(UL &d, UL a, UL b) {
    asm("fma.rn.f32x2 %0,%1,%2,%0;" : "+l"(d) : "l"(a), "l"(b));
}
__device__ __forceinline__ float silu_f(float x) {
    return __fdividef(x, 1.0f + __expf(-x));
}
__device__ __forceinline__ void cpa16(unsigned dst, const float* src) {
    asm volatile("cp.async.cg.shared.global [%0], [%1], 16;" :: "r"(dst), "l"(src));
}
#define CPA_COMMIT() asm volatile("cp.async.commit_group;" ::: "memory")
#define CPA_WAIT0()  asm volatile("cp.async.wait_group 0;" ::: "memory")

// row-major [row][128] bf16, 256B row stride, 8-way XOR swizzle on 16B chunks
__device__ __forceinline__ unsigned aoff(int row, int col) {
    return (unsigned)(row * 256 + ((((col >> 3) ^ (row & 7)) << 4) | ((col & 7) * 2)));
}

__device__ __forceinline__ void ldm4(unsigned* r, unsigned addr) {
    asm volatile("ldmatrix.sync.aligned.m8n8.x4.shared.b16 {%0,%1,%2,%3}, [%4];"
        : "=r"(r[0]), "=r"(r[1]), "=r"(r[2]), "=r"(r[3]) : "r"(addr));
}
__device__ __forceinline__ void mma16816(float* c, const unsigned* a,
                                         unsigned b0, unsigned b1) {
    asm volatile(
        "mma.sync.aligned.m16n8k16.row.col.f32.bf16.bf16.f32 "
        "{%0,%1,%2,%3}, {%4,%5,%6,%7}, {%8,%9}, {%0,%1,%2,%3};"
        : "+f"(c[0]), "+f"(c[1]), "+f"(c[2]), "+f"(c[3])
        : "r"(a[0]), "r"(a[1]), "r"(a[2]), "r"(a[3]), "r"(b0), "r"(b1));
}

// 16 packed FMAs for one k-row: 4 rows x 4 col-pairs
#define FMAROW(WA, WB, S0, S1, S2, S3)                            \
    do {                                                          \
        fma2(acc[0],  S0, WA.x); fma2(acc[1],  S0, WA.y);         \
        fma2(acc[2],  S0, WB.x); fma2(acc[3],  S0, WB.y);         \
        fma2(acc[4],  S1, WA.x); fma2(acc[5],  S1, WA.y);         \
        fma2(acc[6],  S1, WB.x); fma2(acc[7],  S1, WB.y);         \
        fma2(acc[8],  S2, WA.x); fma2(acc[9],  S2, WA.y);         \
        fma2(acc[10], S2, WB.x); fma2(acc[11], S2, WB.y);         \
        fma2(acc[12], S3, WA.x); fma2(acc[13], S3, WA.y);         \
        fma2(acc[14], S3, WB.x); fma2(acc[15], S3, WB.y);         \
    } while (0)

// bf16 hi/lo split store of a col-pair (col even) into A tiles
__device__ __forceinline__ void store_bf16_pair(
    char* AhB, char* AlB, int row, int col, float z0, float z1)
{
    __nv_bfloat16 h0 = __float2bfloat16(z0);
    __nv_bfloat16 h1 = __float2bfloat16(z1);
    __nv_bfloat16 l0 = __float2bfloat16(z0 - __bfloat162float(h0));
    __nv_bfloat16 l1 = __float2bfloat16(z1 - __bfloat162float(h1));
    unsigned uh = (unsigned)*reinterpret_cast<unsigned short*>(&h0)
                | ((unsigned)*reinterpret_cast<unsigned short*>(&h1) << 16);
    unsigned ul = (unsigned)*reinterpret_cast<unsigned short*>(&l0)
                | ((unsigned)*reinterpret_cast<unsigned short*>(&l1) << 16);
    unsigned off = aoff(row, col);
    *reinterpret_cast<unsigned*>(AhB + off) = uh;
    *reinterpret_cast<unsigned*>(AlB + off) = ul;
}

// 3-term bf16-split 32x32 warp-tile GEMM over K=128 (mma.sync m16n8k16)
__device__ __forceinline__ void mma_gemm(
    unsigned AhU, unsigned AlU, unsigned BhU, unsigned BlU,
    int m0, int n0, int lane, float c[2][4][4], bool zero)
{
    if (zero) {
#pragma unroll
        for (int i = 0; i < 2; i++)
#pragma unroll
            for (int j = 0; j < 4; j++)
#pragma unroll
                for (int q = 0; q < 4; q++) c[i][j][q] = 0.0f;
    }

    const int mi = lane >> 3;
    const int rAoff = ((mi & 1) << 3) + (lane & 7);   // A: mi bit0 = m-half
    const int kHalfA = mi >> 1;                       //    mi bit1 = k-half
    const int nOff = ((mi >> 1) << 3) + (lane & 7);   // B: mi bit1 = n-half
    const int kHalfB = mi & 1;                        //    mi bit0 = k-half

#pragma unroll
    for (int k0 = 0; k0 < 128; k0 += 16) {
        unsigned ah[2][4], al[2][4], bh[2][4], bl[2][4];
        const int kcA = (k0 >> 3) + kHalfA;
        const int kcB = (k0 >> 3) + kHalfB;
#pragma unroll
        for (int i = 0; i < 2; i++) {
            int row = m0 + 16 * i + rAoff;
            unsigned off = (unsigned)(row * 256 + ((kcA ^ (row & 7)) << 4));
            ldm4(ah[i], AhU + off);
            ldm4(al[i], AlU + off);
        }
#pragma unroll
        for (int j2 = 0; j2 < 2; j2++) {
            int nrow = n0 + 16 * j2 + nOff;
            unsigned off = (unsigned)(nrow * 256 + ((kcB ^ (nrow & 7)) << 4));
            ldm4(bh[j2], BhU + off);
            ldm4(bl[j2], BlU + off);
        }
#pragma unroll
        for (int i = 0; i < 2; i++) {
#pragma unroll
            for (int jt = 0; jt < 4; jt++) {
                int j2 = jt >> 1, s = jt & 1;
                mma16816(c[i][jt], ah[i], bh[j2][2*s], bh[j2][2*s+1]);
                mma16816(c[i][jt], ah[i], bl[j2][2*s], bl[j2][2*s+1]);
                mma16816(c[i][jt], al[i], bh[j2][2*s], bh[j2][2*s+1]);
            }
        }
    }
}

// stage a 64x128 fp32 row-major global matrix (row base nb) into bf16 hi/lo
// A tiles; 256 threads, thread t: row = t>>2, cols (t&3)*32..+31
__device__ __forceinline__ void stage_A_split(
    char* AhB, char* AlB, const float* __restrict__ src,
    long nb, int N, int tid)
{
    int row = tid >> 2;
    int cb = (tid & 3) * 32;
    long n = nb + row;
    bool v = n < N;
    const float4* s = reinterpret_cast<const float4*>(src + n * 128 + cb);
#pragma unroll
    for (int i = 0; i < 8; i++) {
        float4 a = v ? __ldg(s + i) : make_float4(0.f, 0.f, 0.f, 0.f);
        store_bf16_pair(AhB, AlB, row, cb + 4*i,     a.x, a.y);
        store_bf16_pair(AhB, AlB, row, cb + 4*i + 2, a.z, a.w);
    }
}

// stage one 32KB pre-split B tile pair into smem (256 threads, 128B each)
__device__ __forceinline__ void stage_B(
    unsigned dBh, unsigned dBl, const uint4* BHg, const uint4* BLg, int tid)
{
    const float* s0 = reinterpret_cast<const float*>(BHg) + tid * 32;
    const float* s1 = reinterpret_cast<const float*>(BLg) + tid * 32;
    unsigned d0 = dBh + tid * 128;
    unsigned d1 = dBl + tid * 128;
#pragma unroll
    for (int i = 0; i < 8; i++) {
        cpa16(d0 + i * 16, s0 + i * 4);
        cpa16(d1 + i * 16, s1 + i * 4);
    }
    CPA_COMMIT();
}

// ---------------- prep: prompt-biases + bf16-split BT weight tiles -------
__global__ void prep_kernel(
    const float* __restrict__ prompt,
    const float* __restrict__ e_w1,  const float* __restrict__ e_b1,
    const float* __restrict__ n_w1,  const float* __restrict__ n_b1,
    const float* __restrict__ ae_w1, const float* __restrict__ ae_b1,
    const float* __restrict__ ap_w1, const float* __restrict__ ap_b1,
    const float* __restrict__ e_w2,  const float* __restrict__ n_w2)
{
    int n = threadIdx.x;
    int b = blockIdx.x;
    if (b < 4) {
        const float* w; const float* bias; float* dst; int off;
        if (b == 0)      { w = e_w1;  bias = e_b1;  dst = g_eb1;  off = 273; }
        else if (b == 1) { w = n_w1;  bias = n_b1;  dst = g_nb1;  off = 256; }
        else if (b == 2) { w = ae_w1; bias = ae_b1; dst = g_aeb1; off = 128; }
        else             { w = ap_w1; bias = ap_b1; dst = g_apb1; off = 128; }
        float s = bias[n];
        for (int j = 0; j < 128; j++)
            s = fmaf(prompt[j], w[(off + j) * 128 + n], s);
        dst[n] = s;
    } else {
        const float* W; char* BH; char* BL;
        switch (b) {
        case 4:  W = e_w2;          BH = (char*)g_Bw2h;  BL = (char*)g_Bw2l;  break;
        case 5:  W = ae_w1;         BH = (char*)g_Baeh;  BL = (char*)g_Bael;  break;
        case 6:  W = n_w1;          BH = (char*)g_Bn1ah; BL = (char*)g_Bn1al; break;
        case 7:  W = n_w1 + 16384;  BH = (char*)g_Bn1bh; BL = (char*)g_Bn1bl; break;
        case 8:  W = n_w2;          BH = (char*)g_Bn2h;  BL = (char*)g_Bn2l;  break;
        case 9:  W = ap_w1;         BH = (char*)g_Baph;  BL = (char*)g_Bapl;  break;
        case 10: W = e_w1;          BH = (char*)g_Be1ah; BL = (char*)g_Be1al; break;
        default: W = e_w1 + 16384;  BH = (char*)g_Be1bh; BL = (char*)g_Be1bl; break;
        }
        for (int i = n; i < 16384; i += 128) {
            int nn = i >> 7, k = i & 127;
            float v = W[k * 128 + nn];             // BT[nn][k] = W[k][nn]
            __nv_bfloat16 h = __float2bfloat16(v);
            __nv_bfloat16 l = __float2bfloat16(v - __bfloat162float(h));
            unsigned off = aoff(nn, k);
            *reinterpret_cast<unsigned short*>(BH + off) =
                *reinterpret_cast<unsigned short*>(&h);
            *reinterpret_cast<unsigned short*>(BL + off) =
                *reinterpret_cast<unsigned short*>(&l);
        }
    }
}

// ap_w2 copied to a device global so node_kernel sig stays small
__global__ void copy_apw2(const float* __restrict__ ap_w2)
{
    g_apw2c[threadIdx.x] = ap_w2[threadIdx.x];
}

// ---------------- node projection kernel (mma): g_P = h @ [W1a | W1b] ----
// 64 nodes/CTA, 256 threads, 2 CTAs/SM.
// smem: Ah 0 (16K) | Al 16384 | Bh 32768 (32K) | Bl 65536  -> 98304 B
#define PROJ_SMEM 98304

__global__ void __launch_bounds__(256, 2) proj_kernel(
    const float* __restrict__ h, int N)
{
    extern __shared__ float sm[];
    char* base = reinterpret_cast<char*>(sm);
    char* AhB = base;
    char* AlB = base + 16384;
    unsigned smem_u = (unsigned)__cvta_generic_to_shared(base);

    const int tid = threadIdx.x;
    const int wid = tid >> 5, lane = tid & 31;
    const long nb = (long)blockIdx.x * 64;

    // zero scratch for this CTA's nodes
    {
        const int el = tid & 63, part = tid >> 6;
        long n = nb + el;
        if (n < N) {
            float4 z4 = make_float4(0.f, 0.f, 0.f, 0.f);
            float4* ga = reinterpret_cast<float4*>(g_agg + n * 128) + part * 8;
#pragma unroll
            for (int i = 0; i < 8; i++) ga[i] = z4;
            if (part == 0) {
                g_aggc[n*3+0] = 0.f; g_aggc[n*3+1] = 0.f; g_aggc[n*3+2] = 0.f;
            }
        }
    }

    stage_B(smem_u + 32768, smem_u + 65536, g_Be1ah, g_Be1al, tid);
    stage_A_split(AhB, AlB, h, nb, N, tid);
    CPA_WAIT0();
    __syncthreads();

    const int m0 = (wid >> 2) * 32;
    const int n0 = (wid & 3) * 32;
    const int g  = lane >> 2;
    const int q  = lane & 3;

    float c[2][4][4];

    // P1 = h @ e_w1[0:128]
    mma_gemm(smem_u, smem_u + 16384, smem_u + 32768, smem_u + 65536,
             m0, n0, lane, c, true);
    __syncthreads();   // B consumed by all warps
    stage_B(smem_u + 32768, smem_u + 65536, g_Be1bh, g_Be1bl, tid);
#pragma unroll
    for (int i = 0; i < 2; i++) {
        int r0 = m0 + 16 * i + g;
        long na = nb + r0, nber = nb + r0 + 8;
#pragma unroll
        for (int jt = 0; jt < 4; jt++) {
            int col = n0 + 8 * jt + q * 2;
            if (na < N)
                *reinterpret_cast<float2*>(g_P + na * 256 + col) =
                    make_float2(c[i][jt][0], c[i][jt][1]);
            if (nber < N)
                *reinterpret_cast<float2*>(g_P + nber * 256 + col) =
                    make_float2(c[i][jt][2], c[i][jt][3]);
        }
    }
    CPA_WAIT0();
    __syncthreads();

    // P2 = h @ e_w1[128:256]
    mma_gemm(smem_u, smem_u + 16384, smem_u + 32768, smem_u + 65536,
             m0, n0, lane, c, true);
#pragma unroll
    for (int i = 0; i < 2; i++) {
        int r0 = m0 + 16 * i + g;
        long na = nb + r0, nber = nb + r0 + 8;
#pragma unroll
        for (int jt = 0; jt < 4; jt++) {
            int col = n0 + 8 * jt + q * 2;
            if (na < N)
                *reinterpret_cast<float2*>(g_P + na * 256 + 128 + col) =
                    make_float2(c[i][jt][0], c[i][jt][1]);
            if (nber < N)
                *reinterpret_cast<float2*>(g_P + nber * 256 + 128 + col) =
                    make_float2(c[i][jt][2], c[i][jt][3]);
        }
    }
}

// ---------------- fused edge kernel (mma.sync, 64 edges, 2 CTAs/SM) ------
// byte map: Ah 0 (16384) | Al 16384 | Bh 32768 (32768) | Bl 65536
//   W1s 98304 (8704) | XeT 107008 (4352) | cd 111360 (1024)
//   sES 112384 (256) | rowi 112640 (256) | coli 112896 (256)
#define OFF_AL  16384
#define OFF_BH  32768
#define OFF_BL  65536
#define OFF_W1  98304
#define OFF_XE  107008
#define OFF_CD  111360
#define OFF_SES 112384
#define OFF_ROW 112640
#define OFF_COL 112896
#define EDGE_SMEM 113152

__global__ void __launch_bounds__(256, 2) edge_kernel(
    const int* __restrict__ ei,
    const float* __restrict__ coord, const float* __restrict__ eattr,
    const float* __restrict__ e_w1, const float* __restrict__ e_b2,
    const float* __restrict__ ae_w2, int E)
{
    extern __shared__ float sm[];
    char* base = reinterpret_cast<char*>(sm);
    char* AhB = base;
    char* AlB = base + OFF_AL;
    float* W1s  = reinterpret_cast<float*>(base + OFF_W1);
    float* XeT  = reinterpret_cast<float*>(base + OFF_XE);
    float4* cd  = reinterpret_cast<float4*>(base + OFF_CD);
    float*  sES = reinterpret_cast<float*>(base + OFF_SES);
    int*   rowi = reinterpret_cast<int*>(base + OFF_ROW);
    int*   coli = reinterpret_cast<int*>(base + OFF_COL);
    unsigned smem_u = (unsigned)__cvta_generic_to_shared(base);

    const int tid = threadIdx.x;
    const int wid = tid >> 5, lane = tid & 31;
    const int e_base = blockIdx.x * 64;
    const int* rowg = ei;
    const int* colg = ei + E;

    // group 0: e_w2 hi/lo B tiles
    stage_B(smem_u + OFF_BH, smem_u + OFF_BL, g_Bw2h, g_Bw2l, tid);
    // group 1: W1c (17x128 fp32 = 544 float4)
    {
        const float* wsrc = e_w1 + 256 * 128;
        for (int i = tid; i < 544; i += 256)
            cpa16(smem_u + OFF_W1 + i * 16, wsrc + i * 4);
        CPA_COMMIT();
    }

    // ------- stage XeT: row0 = radial, rows 1..16 = eattr^T; indices -----
    {
        const int el = tid & 63, part = tid >> 6;
        int e = e_base + el;
        bool v = e < E;
        if (part == 0) {
            long r = v ? (long)rowg[e] : 0;
            long c = v ? (long)colg[e] : 0;
            rowi[el] = (int)r;
            coli[el] = (int)c;
            float dx = 0.f, dy = 0.f, dz = 0.f;
            if (v) {
                dx = coord[r*3+0] - coord[c*3+0];
                dy = coord[r*3+1] - coord[c*3+1];
                dz = coord[r*3+2] - coord[c*3+2];
            }
            float rad = dx*dx + dy*dy + dz*dz;
            XeT[el] = rad;
            float inv = 1.0f / fmaxf(sqrtf(rad), 1e-12f);
            cd[el] = make_float4(dx, dy, dz, inv);
        } else if (part == 1) {
            const float4* ea = reinterpret_cast<const float4*>(eattr) + (long)e * 4;
#pragma unroll
            for (int i = 0; i < 4; i++) {
                float4 a = v ? __ldg(ea + i) : make_float4(0.f, 0.f, 0.f, 0.f);
                int k = 1 + 4 * i;
                XeT[(k+0)*64 + el] = a.x; XeT[(k+1)*64 + el] = a.y;
                XeT[(k+2)*64 + el] = a.z; XeT[(k+3)*64 + el] = a.w;
            }
        }
    }
    CPA_WAIT0();
    __syncthreads();

    const int e0 = (wid >> 2) * 32 + (lane >> 2) * 4;
    const int c0 = (wid & 3) * 32 + (lane & 3) * 8;

    UL acc[16];

    // ------- acc init: eb1_eff + P1[row] + P2[col] -----------------------
    {
        float4 b0 = __ldg(reinterpret_cast<const float4*>(g_eb1 + c0));
        float4 b1 = __ldg(reinterpret_cast<const float4*>(g_eb1 + c0 + 4));
#pragma unroll
        for (int j = 0; j < 4; j++) {
            int r = rowi[e0 + j], cc = coli[e0 + j];
            const float* pr = g_P + (long)r  * 256 + c0;
            const float* pc = g_P + (long)cc * 256 + 128 + c0;
            float4 p0 = __ldg(reinterpret_cast<const float4*>(pr));
            float4 p1 = __ldg(reinterpret_cast<const float4*>(pr + 4));
            float4 q0 = __ldg(reinterpret_cast<const float4*>(pc));
            float4 q1 = __ldg(reinterpret_cast<const float4*>(pc + 4));
            acc[j*4+0] = pk2(b0.x + p0.x + q0.x, b0.y + p0.y + q0.y);
            acc[j*4+1] = pk2(b0.z + p0.z + q0.z, b0.w + p0.w + q0.w);
            acc[j*4+2] = pk2(b1.x + p1.x + q1.x, b1.y + p1.y + q1.y);
            acc[j*4+3] = pk2(b1.z + p1.z + q1.z, b1.w + p1.w + q1.w);
        }
    }

    // ------- GEMM1 (K=17, f32x2) from staged W1s/XeT ---------------------
#pragma unroll
    for (int k = 0; k < 17; k++) {
        float4 xv = *reinterpret_cast<const float4*>(XeT + k * 64 + e0);
        const float* wb = W1s + k * 128 + c0;
        ulonglong2 a = *reinterpret_cast<const ulonglong2*>(wb);
        ulonglong2 b = *reinterpret_cast<const ulonglong2*>(wb + 4);
        UL s0 = bc2(xv.x), s1 = bc2(xv.y), s2 = bc2(xv.z), s3 = bc2(xv.w);
        FMAROW(a, b, s0, s1, s2, s3);
    }
#pragma unroll
    for (int j = 0; j < 4; j++) {
        int r = e0 + j;
#pragma unroll
        for (int p = 0; p < 4; p++) {
            float2 f = up2(acc[j*4+p]);
            store_bf16_pair(AhB, AlB, r, c0 + 2*p, silu_f(f.x), silu_f(f.y));
        }
    }
    if (tid < 64) sES[tid] = 0.0f;
    __syncthreads();

    const int m0 = (wid >> 2) * 32;
    const int n0 = (wid & 3) * 32;
    const int g  = lane >> 2;
    const int q  = lane & 3;

    float c[2][4][4];

    // ------- GEMM2: edge hidden @ e_w2  (tensor cores) -------------------
    mma_gemm(smem_u + 0, smem_u + OFF_AL, smem_u + OFF_BH, smem_u + OFF_BL,
             m0, n0, lane, c, true);
    __syncthreads();   // all warps done reading A and B before overwrite

    // stream ae_w1 hi/lo into the B buffers (overlaps epilogue below)
    stage_B(smem_u + OFF_BH, smem_u + OFF_BL, g_Baeh, g_Bael, tid);

    // epilogue: bias+silu, store edge_feat to A tiles, g_agg atomics
#pragma unroll
    for (int i = 0; i < 2; i++) {
        int r0 = m0 + 16 * i + g;
#pragma unroll
        for (int jt = 0; jt < 4; jt++) {
            int col = n0 + 8 * jt + q * 2;
            float bx = __ldg(e_b2 + col), by = __ldg(e_b2 + col + 1);
            float z0 = silu_f(c[i][jt][0] + bx);
            float z1 = silu_f(c[i][jt][1] + by);
            float z2 = silu_f(c[i][jt][2] + bx);
            float z3 = silu_f(c[i][jt][3] + by);
            store_bf16_pair(AhB, AlB, r0,     col, z0, z1);
            store_bf16_pair(AhB, AlB, r0 + 8, col, z2, z3);
            if (e_base + r0 < E)
                atomicAdd(reinterpret_cast<float2*>(
                    g_agg + (long)rowi[r0] * 128 + col), make_float2(z0, z1));
            if (e_base + r0 + 8 < E)
                atomicAdd(reinterpret_cast<float2*>(
                    g_agg + (long)rowi[r0 + 8] * 128 + col), make_float2(z2, z3));
        }
    }
    CPA_WAIT0();
    __syncthreads();   // edge_feat + ae tiles visible to all warps

    // ------- GEMM3: edge_feat @ ae_w1  (tensor cores) --------------------
    mma_gemm(smem_u + 0, smem_u + OFF_AL, smem_u + OFF_BH, smem_u + OFF_BL,
             m0, n0, lane, c, true);

    // epilogue: silu(c + aeb1) dot ae_w2 -> per-row sums in sES
    {
        float s[4] = {0.f, 0.f, 0.f, 0.f};   // rows m0+g, +8, +16, +24
#pragma unroll
        for (int i = 0; i < 2; i++) {
#pragma unroll
            for (int jt = 0; jt < 4; jt++) {
                int col = n0 + 8 * jt + q * 2;
                float bx = __ldg(g_aeb1 + col), by = __ldg(g_aeb1 + col + 1);
                float wx = __ldg(ae_w2 + col),  wy = __ldg(ae_w2 + col + 1);
                s[2*i]   += silu_f(c[i][jt][0] + bx) * wx
                          + silu_f(c[i][jt][1] + by) * wy;
                s[2*i+1] += silu_f(c[i][jt][2] + bx) * wx
                          + silu_f(c[i][jt][3] + by) * wy;
            }
        }
#pragma unroll
        for (int t = 0; t < 4; t++) {
            s[t] += __shfl_xor_sync(0xffffffffu, s[t], 1);
            s[t] += __shfl_xor_sync(0xffffffffu, s[t], 2);
        }
        if (q == 0) {
            atomicAdd(&sES[m0 + g],      s[0]);
            atomicAdd(&sES[m0 + 8 + g],  s[1]);
            atomicAdd(&sES[m0 + 16 + g], s[2]);
            atomicAdd(&sES[m0 + 24 + g], s[3]);
        }
    }
    __syncthreads();

    if (tid < 64) {
        int eg = e_base + tid;
        if (eg < E) {
            float sv = sES[tid];
            float4 cdl = cd[tid];
            float f = sv * cdl.w;
            float* dst = g_aggc + (long)rowi[tid] * 3;
            atomicAdd(dst + 0, cdl.x * f);
            atomicAdd(dst + 1, cdl.y * f);
            atomicAdd(dst + 2, cdl.z * f);
        }
    }
}

// ---------------- fused node kernel (mma.sync) ---------------------------
// 64 nodes/CTA, 256 threads, 2 CTAs/SM.
// smem: Ah 0 (16K) | Al 16384 | Bh 32768 (32K) | Bl 65536 | sES 98304 (256)
#define NODE_SMEM 98560

__global__ void __launch_bounds__(256, 2) node_kernel(
    const float* __restrict__ h, const float* __restrict__ coordg,
    const float* __restrict__ n_b2, float* __restrict__ out, int N)
{
    extern __shared__ float sm[];
    char* base = reinterpret_cast<char*>(sm);
    char* AhB = base;
    char* AlB = base + 16384;
    float* sES = reinterpret_cast<float*>(base + 98304);
    unsigned smem_u = (unsigned)__cvta_generic_to_shared(base);
    const unsigned uBh = smem_u + 32768, uBl = smem_u + 65536;

    const int tid = threadIdx.x;
    const int wid = tid >> 5, lane = tid & 31;
    const long nb = (long)blockIdx.x * 64;

    if (tid < 64) sES[tid] = 0.0f;

    // stage A = h (bf16 split) and B = n_w1 k-half 0
    stage_B(uBh, uBl, g_Bn1ah, g_Bn1al, tid);
    stage_A_split(AhB, AlB, h, nb, N, tid);
    CPA_WAIT0();
    __syncthreads();

    const int m0 = (wid >> 2) * 32;
    const int n0 = (wid & 3) * 32;
    const int g  = lane >> 2;
    const int q  = lane & 3;

    float c[2][4][4];

    // GEMM1 pass 1: h @ n_w1[0:128]
    mma_gemm(smem_u, smem_u + 16384, uBh, uBl, m0, n0, lane, c, true);
    __syncthreads();   // A and B consumed

    // stage A = agg, B = n_w1 k-half 1
    stage_B(uBh, uBl, g_Bn1bh, g_Bn1bl, tid);
    stage_A_split(AhB, AlB, g_agg, nb, N, tid);
    CPA_WAIT0();
    __syncthreads();

    // GEMM1 pass 2: agg @ n_w1[128:256]  (accumulate)
    mma_gemm(smem_u, smem_u + 16384, uBh, uBl, m0, n0, lane, c, false);
    __syncthreads();   // A, B consumed -> safe to overwrite

    // epilogue 1: Y = silu(c + nb1) -> A tiles;  stage B = n_w2
    stage_B(uBh, uBl, g_Bn2h, g_Bn2l, tid);
#pragma unroll
    for (int i = 0; i < 2; i++) {
        int r0 = m0 + 16 * i + g;
#pragma unroll
        for (int jt = 0; jt < 4; jt++) {
            int col = n0 + 8 * jt + q * 2;
            float bx = __ldg(g_nb1 + col), by = __ldg(g_nb1 + col + 1);
            store_bf16_pair(AhB, AlB, r0, col,
                            silu_f(c[i][jt][0] + bx), silu_f(c[i][jt][1] + by));
            store_bf16_pair(AhB, AlB, r0 + 8, col,
                            silu_f(c[i][jt][2] + bx), silu_f(c[i][jt][3] + by));
        }
    }
    CPA_WAIT0();
    __syncthreads();

    // GEMM2: Y @ n_w2
    mma_gemm(smem_u, smem_u + 16384, uBh, uBl, m0, n0, lane, c, true);
    __syncthreads();   // Y consumed -> safe to overwrite

    // epilogue 2: h_out = h + silu(c + n_b2) -> out + A tiles; stage B = ap_w1
    stage_B(uBh, uBl, g_Baph, g_Bapl, tid);
#pragma unroll
    for (int i = 0; i < 2; i++) {
        int r0 = m0 + 16 * i + g;
        long na = nb + r0, nbr = nb + r0 + 8;
#pragma unroll
        for (int jt = 0; jt < 4; jt++) {
            int col = n0 + 8 * jt + q * 2;
            float bx = __ldg(n_b2 + col), by = __ldg(n_b2 + col + 1);
            float2 hA = (na  < N) ? *reinterpret_cast<const float2*>(h + na  * 128 + col)
                                  : make_float2(0.f, 0.f);
            float2 hBv = (nbr < N) ? *reinterpret_cast<const float2*>(h + nbr * 128 + col)
                                   : make_float2(0.f, 0.f);
            float z0 = silu_f(c[i][jt][0] + bx) + hA.x;
            float z1 = silu_f(c[i][jt][1] + by) + hA.y;
            float z2 = silu_f(c[i][jt][2] + bx) + hBv.x;
            float z3 = silu_f(c[i][jt][3] + by) + hBv.y;
            store_bf16_pair(AhB, AlB, r0,     col, z0, z1);
            store_bf16_pair(AhB, AlB, r0 + 8, col, z2, z3);
            if (na < N)
                *reinterpret_cast<float2*>(out + na * 128 + col) = make_float2(z0, z1);
            if (nbr < N)
                *reinterpret_cast<float2*>(out + nbr * 128 + col) = make_float2(z2, z3);
        }
    }
    CPA_WAIT0();
    __syncthreads();

    // GEMM3: h_out @ ap_w1
    mma_gemm(smem_u, smem_u + 16384, uBh, uBl, m0, n0, lane, c, true);

    // epilogue 3: silu(c + apb1) dot ap_w2 -> sES
    {
        float s[4] = {0.f, 0.f, 0.f, 0.f};
#pragma unroll
        for (int i = 0; i < 2; i++) {
#pragma unroll
            for (int jt = 0; jt < 4; jt++) {
                int col = n0 + 8 * jt + q * 2;
                float bx = __ldg(g_apb1 + col), by = __ldg(g_apb1 + col + 1);
                s[2*i]   += silu_f(c[i][jt][0] + bx) * g_apw2c[col]
                          + silu_f(c[i][jt][1] + by) * g_apw2c[col + 1];
                s[2*i+1] += silu_f(c[i][jt][2] + bx) * g_apw2c[col]
                          + silu_f(c[i][jt][3] + by) * g_apw2c[col + 1];
            }
        }
#pragma unroll
        for (int t = 0; t < 4; t++) {
            s[t] += __shfl_xor_sync(0xffffffffu, s[t], 1);
            s[t] += __shfl_xor_sync(0xffffffffu, s[t], 2);
        }
        if (q == 0) {
            atomicAdd(&sES[m0 + g],      s[0]);
            atomicAdd(&sES[m0 + 8 + g],  s[1]);
            atomicAdd(&sES[m0 + 16 + g], s[2]);
            atomicAdd(&sES[m0 + 24 + g], s[3]);
        }
    }
    __syncthreads();

    if (tid < 64) {
        long n = nb + tid;
        if (n < N) {
            float s = sES[tid];
            long base_c = (long)N * 128;
            long base_a = (long)N * 131;
            out[base_c + n*3 + 0] = coordg[n*3+0];
            out[base_c + n*3 + 1] = coordg[n*3+1];
            out[base_c + n*3 + 2] = coordg[n*3+2];
            out[base_a + n*3 + 0] = g_aggc[n*3+0] * s;
            out[base_a + n*3 + 1] = g_aggc[n*3+1] * s;
            out[base_a + n*3 + 2] = g_aggc[n*3+2] * s;
        }
    }
}

// ---------------- launch ----------------
extern "C" void kernel_launch(void* const* d_in, const int* in_sizes, int n_in,
                              void* d_out, int out_size)
{
    const float* h      = (const float*)d_in[0];
    const int*   ei     = (const int*)  d_in[1];
    const float* coord  = (const float*)d_in[2];
    const float* eattr  = (const float*)d_in[3];
    const float* prompt = (const float*)d_in[4];
    const float* e_w1   = (const float*)d_in[5];
    const float* e_b1   = (const float*)d_in[6];
    const float* e_w2   = (const float*)d_in[7];
    const float* e_b2   = (const float*)d_in[8];
    const float* n_w1   = (const float*)d_in[9];
    const float* n_b1   = (const float*)d_in[10];
    const float* n_w2   = (const float*)d_in[11];
    const float* n_b2   = (const float*)d_in[12];
    const float* ae_w1  = (const float*)d_in[13];
    const float* ae_b1  = (const float*)d_in[14];
    const float* ae_w2  = (const float*)d_in[15];
    const float* ap_w1  = (const float*)d_in[16];
    const float* ap_b1  = (const float*)d_in[17];
    const float* ap_w2  = (const float*)d_in[18];
    float* out = (float*)d_out;

    int N = in_sizes[0] / 128;
    int E = in_sizes[1] / 2;

    cudaFuncSetAttribute(proj_kernel, cudaFuncAttributeMaxDynamicSharedMemorySize, PROJ_SMEM);
    cudaFuncSetAttribute(edge_kernel, cudaFuncAttributeMaxDynamicSharedMemorySize, EDGE_SMEM);
    cudaFuncSetAttribute(node_kernel, cudaFuncAttributeMaxDynamicSharedMemorySize, NODE_SMEM);

    prep_kernel<<<12, 128>>>(prompt, e_w1, e_b1, n_w1, n_b1,
                             ae_w1, ae_b1, ap_w1, ap_b1, e_w2, n_w2);
    copy_apw2<<<1, 128>>>(ap_w2);
    proj_kernel<<<(N + 63) / 64, 256, PROJ_SMEM>>>(h, N);
    edge_kernel<<<(E + 63) / 64, 256, EDGE_SMEM>>>(ei, coord, eattr,
                                                   e_w1, e_b2, ae_w2, E);
    node_kernel<<<(N + 63) / 64, 256, NODE_SMEM>>>(h, coord, n_b2, out, N);
}

// round 17
// speedup vs baseline: 3.5975x; 1.0140x over previous
#include <cuda_runtime.h>
#include <cuda_bf16.h>

typedef unsigned long long UL;

// ---------------- device scratch (no allocations allowed) ----------------
__device__ float g_agg [50000 * 128];   // segment-sum of edge_feat per node
__device__ float g_aggc[50000 * 3];     // segment-sum of trans per node
__device__ float g_P   [50048 * 256];   // per-node projections [P1 | P2]
__device__ float g_eb1 [128];           // e_b1  + prompt @ e_w1[273:401]
__device__ float g_nb1 [128];           // n_b1  + prompt @ n_w1[256:384]
__device__ float g_aeb1[128];           // ae_b1 + prompt @ ae_w1[128:256]
__device__ float g_apb1[128];           // ap_b1 + prompt @ ap_w1[128:256]
__device__ float g_apw2c[128];          // copy of ap_w2
// bf16 hi/lo weight tiles, BT[n][k] with 8-way XOR swizzle, 32KB each
__device__ uint4 g_Bw2h [2048];  __device__ uint4 g_Bw2l [2048];   // e_w2
__device__ uint4 g_Baeh [2048];  __device__ uint4 g_Bael [2048];   // ae_w1
__device__ uint4 g_Bn1ah[2048];  __device__ uint4 g_Bn1al[2048];   // n_w1 k0
__device__ uint4 g_Bn1bh[2048];  __device__ uint4 g_Bn1bl[2048];   // n_w1 k1
__device__ uint4 g_Bn2h [2048];  __device__ uint4 g_Bn2l [2048];   // n_w2
__device__ uint4 g_Baph [2048];  __device__ uint4 g_Bapl [2048];   // ap_w1
__device__ uint4 g_Be1ah[2048];  __device__ uint4 g_Be1al[2048];   // e_w1 k0
__device__ uint4 g_Be1bh[2048];  __device__ uint4 g_Be1bl[2048];   // e_w1 k1

// ---------------- small helpers ----------------
__device__ __forceinline__ UL bc2(float x) {
    UL r; asm("mov.b64 %0,{%1,%1};" : "=l"(r) : "f"(x)); return r;
}
__device__ __forceinline__ UL pk2(float x, float y) {
    UL r; asm("mov.b64 %0,{%1,%2};" : "=l"(r) : "f"(x), "f"(y)); return r;
}
__device__ __forceinline__ float2 up2(UL v) {
    float2 f; asm("mov.b64 {%0,%1},%2;" : "=f"(f.x), "=f"(f.y) : "l"(v)); return f;
}
__device__ __forceinline__ void fma2(UL &d, UL a, UL b) {
    asm("fma.rn.f32x2 %0,%1,%2,%0;" : "+l"(d) : "l"(a), "l"(b));
}
__device__ __forceinline__ float silu_f(float x) {
    return __fdividef(x, 1.0f + __expf(-x));
}
__device__ __forceinline__ void cpa16(unsigned dst, const float* src) {
    asm volatile("cp.async.cg.shared.global [%0], [%1], 16;" :: "r"(dst), "l"(src));
}
#define CPA_COMMIT() asm volatile("cp.async.commit_group;" ::: "memory")
#define CPA_WAIT0()  asm volatile("cp.async.wait_group 0;" ::: "memory")

// row-major [row][128] bf16, 256B row stride, 8-way XOR swizzle on 16B chunks
__device__ __forceinline__ unsigned aoff(int row, int col) {
    return (unsigned)(row * 256 + ((((col >> 3) ^ (row & 7)) << 4) | ((col & 7) * 2)));
}

__device__ __forceinline__ void ldm4(unsigned* r, unsigned addr) {
    asm volatile("ldmatrix.sync.aligned.m8n8.x4.shared.b16 {%0,%1,%2,%3}, [%4];"
        : "=r"(r[0]), "=r"(r[1]), "=r"(r[2]), "=r"(r[3]) : "r"(addr));
}
__device__ __forceinline__ void mma16816(float* c, const unsigned* a,
                                         unsigned b0, unsigned b1) {
    asm volatile(
        "mma.sync.aligned.m16n8k16.row.col.f32.bf16.bf16.f32 "
        "{%0,%1,%2,%3}, {%4,%5,%6,%7}, {%8,%9}, {%0,%1,%2,%3};"
        : "+f"(c[0]), "+f"(c[1]), "+f"(c[2]), "+f"(c[3])
        : "r"(a[0]), "r"(a[1]), "r"(a[2]), "r"(a[3]), "r"(b0), "r"(b1));
}

// 16 packed FMAs for one k-row: 4 rows x 4 col-pairs
#define FMAROW(WA, WB, S0, S1, S2, S3)                            \
    do {                                                          \
        fma2(acc[0],  S0, WA.x); fma2(acc[1],  S0, WA.y);         \
        fma2(acc[2],  S0, WB.x); fma2(acc[3],  S0, WB.y);         \
        fma2(acc[4],  S1, WA.x); fma2(acc[5],  S1, WA.y);         \
        fma2(acc[6],  S1, WB.x); fma2(acc[7],  S1, WB.y);         \
        fma2(acc[8],  S2, WA.x); fma2(acc[9],  S2, WA.y);         \
        fma2(acc[10], S2, WB.x); fma2(acc[11], S2, WB.y);         \
        fma2(acc[12], S3, WA.x); fma2(acc[13], S3, WA.y);         \
        fma2(acc[14], S3, WB.x); fma2(acc[15], S3, WB.y);         \
    } while (0)

// bf16 hi/lo split store of a col-pair (col even) into A tiles
__device__ __forceinline__ void store_bf16_pair(
    char* AhB, char* AlB, int row, int col, float z0, float z1)
{
    __nv_bfloat16 h0 = __float2bfloat16(z0);
    __nv_bfloat16 h1 = __float2bfloat16(z1);
    __nv_bfloat16 l0 = __float2bfloat16(z0 - __bfloat162float(h0));
    __nv_bfloat16 l1 = __float2bfloat16(z1 - __bfloat162float(h1));
    unsigned uh = (unsigned)*reinterpret_cast<unsigned short*>(&h0)
                | ((unsigned)*reinterpret_cast<unsigned short*>(&h1) << 16);
    unsigned ul = (unsigned)*reinterpret_cast<unsigned short*>(&l0)
                | ((unsigned)*reinterpret_cast<unsigned short*>(&l1) << 16);
    unsigned off = aoff(row, col);
    *reinterpret_cast<unsigned*>(AhB + off) = uh;
    *reinterpret_cast<unsigned*>(AlB + off) = ul;
}

// 3-term bf16-split 32x32 warp-tile GEMM over K=128 (both B matrices resident)
__device__ __forceinline__ void mma_gemm(
    unsigned AhU, unsigned AlU, unsigned BhU, unsigned BlU,
    int m0, int n0, int lane, float c[2][4][4], bool zero)
{
    if (zero) {
#pragma unroll
        for (int i = 0; i < 2; i++)
#pragma unroll
            for (int j = 0; j < 4; j++)
#pragma unroll
                for (int q = 0; q < 4; q++) c[i][j][q] = 0.0f;
    }

    const int mi = lane >> 3;
    const int rAoff = ((mi & 1) << 3) + (lane & 7);
    const int kHalfA = mi >> 1;
    const int nOff = ((mi >> 1) << 3) + (lane & 7);
    const int kHalfB = mi & 1;

#pragma unroll
    for (int k0 = 0; k0 < 128; k0 += 16) {
        unsigned ah[2][4], al[2][4], bh[2][4], bl[2][4];
        const int kcA = (k0 >> 3) + kHalfA;
        const int kcB = (k0 >> 3) + kHalfB;
#pragma unroll
        for (int i = 0; i < 2; i++) {
            int row = m0 + 16 * i + rAoff;
            unsigned off = (unsigned)(row * 256 + ((kcA ^ (row & 7)) << 4));
            ldm4(ah[i], AhU + off);
            ldm4(al[i], AlU + off);
        }
#pragma unroll
        for (int j2 = 0; j2 < 2; j2++) {
            int nrow = n0 + 16 * j2 + nOff;
            unsigned off = (unsigned)(nrow * 256 + ((kcB ^ (nrow & 7)) << 4));
            ldm4(bh[j2], BhU + off);
            ldm4(bl[j2], BlU + off);
        }
#pragma unroll
        for (int i = 0; i < 2; i++) {
#pragma unroll
            for (int jt = 0; jt < 4; jt++) {
                int j2 = jt >> 1, s = jt & 1;
                mma16816(c[i][jt], ah[i], bh[j2][2*s], bh[j2][2*s+1]);
                mma16816(c[i][jt], ah[i], bl[j2][2*s], bl[j2][2*s+1]);
                mma16816(c[i][jt], al[i], bh[j2][2*s], bh[j2][2*s+1]);
            }
        }
    }
}

// 2-term pass: c += Ah*B + Al*B  (single B matrix resident)
__device__ __forceinline__ void mma_2t(
    unsigned AhU, unsigned AlU, unsigned BU,
    int m0, int n0, int lane, float c[2][4][4])
{
    const int mi = lane >> 3;
    const int rAoff = ((mi & 1) << 3) + (lane & 7);
    const int kHalfA = mi >> 1;
    const int nOff = ((mi >> 1) << 3) + (lane & 7);
    const int kHalfB = mi & 1;
#pragma unroll
    for (int k0 = 0; k0 < 128; k0 += 16) {
        unsigned ah[2][4], al[2][4], b[2][4];
        const int kcA = (k0 >> 3) + kHalfA;
        const int kcB = (k0 >> 3) + kHalfB;
#pragma unroll
        for (int i = 0; i < 2; i++) {
            int row = m0 + 16 * i + rAoff;
            unsigned off = (unsigned)(row * 256 + ((kcA ^ (row & 7)) << 4));
            ldm4(ah[i], AhU + off);
            ldm4(al[i], AlU + off);
        }
#pragma unroll
        for (int j2 = 0; j2 < 2; j2++) {
            int nrow = n0 + 16 * j2 + nOff;
            unsigned off = (unsigned)(nrow * 256 + ((kcB ^ (nrow & 7)) << 4));
            ldm4(b[j2], BU + off);
        }
#pragma unroll
        for (int i = 0; i < 2; i++) {
#pragma unroll
            for (int jt = 0; jt < 4; jt++) {
                int j2 = jt >> 1, s = jt & 1;
                mma16816(c[i][jt], ah[i], b[j2][2*s], b[j2][2*s+1]);
                mma16816(c[i][jt], al[i], b[j2][2*s], b[j2][2*s+1]);
            }
        }
    }
}

// 1-term pass: c += Ah*B
__device__ __forceinline__ void mma_1t(
    unsigned AhU, unsigned BU,
    int m0, int n0, int lane, float c[2][4][4])
{
    const int mi = lane >> 3;
    const int rAoff = ((mi & 1) << 3) + (lane & 7);
    const int kHalfA = mi >> 1;
    const int nOff = ((mi >> 1) << 3) + (lane & 7);
    const int kHalfB = mi & 1;
#pragma unroll
    for (int k0 = 0; k0 < 128; k0 += 16) {
        unsigned ah[2][4], b[2][4];
        const int kcA = (k0 >> 3) + kHalfA;
        const int kcB = (k0 >> 3) + kHalfB;
#pragma unroll
        for (int i = 0; i < 2; i++) {
            int row = m0 + 16 * i + rAoff;
            unsigned off = (unsigned)(row * 256 + ((kcA ^ (row & 7)) << 4));
            ldm4(ah[i], AhU + off);
        }
#pragma unroll
        for (int j2 = 0; j2 < 2; j2++) {
            int nrow = n0 + 16 * j2 + nOff;
            unsigned off = (unsigned)(nrow * 256 + ((kcB ^ (nrow & 7)) << 4));
            ldm4(b[j2], BU + off);
        }
#pragma unroll
        for (int i = 0; i < 2; i++) {
#pragma unroll
            for (int jt = 0; jt < 4; jt++) {
                int j2 = jt >> 1, s = jt & 1;
                mma16816(c[i][jt], ah[i], b[j2][2*s], b[j2][2*s+1]);
            }
        }
    }
}

// stage a 64x128 fp32 row-major global matrix (row base nb) into bf16 hi/lo
__device__ __forceinline__ void stage_A_split(
    char* AhB, char* AlB, const float* __restrict__ src,
    long nb, int N, int tid)
{
    int row = tid >> 2;
    int cb = (tid & 3) * 32;
    long n = nb + row;
    bool v = n < N;
    const float4* s = reinterpret_cast<const float4*>(src + n * 128 + cb);
#pragma unroll
    for (int i = 0; i < 8; i++) {
        float4 a = v ? __ldg(s + i) : make_float4(0.f, 0.f, 0.f, 0.f);
        store_bf16_pair(AhB, AlB, row, cb + 4*i,     a.x, a.y);
        store_bf16_pair(AhB, AlB, row, cb + 4*i + 2, a.z, a.w);
    }
}

// stage one 32KB pre-split B tile pair (hi+lo) into smem
__device__ __forceinline__ void stage_B(
    unsigned dBh, unsigned dBl, const uint4* BHg, const uint4* BLg, int tid)
{
    const float* s0 = reinterpret_cast<const float*>(BHg) + tid * 32;
    const float* s1 = reinterpret_cast<const float*>(BLg) + tid * 32;
    unsigned d0 = dBh + tid * 128;
    unsigned d1 = dBl + tid * 128;
#pragma unroll
    for (int i = 0; i < 8; i++) {
        cpa16(d0 + i * 16, s0 + i * 4);
        cpa16(d1 + i * 16, s1 + i * 4);
    }
    CPA_COMMIT();
}

// stage ONE 32KB matrix into smem (256 threads x 128B)
__device__ __forceinline__ void stage_B32(
    unsigned dB, const uint4* Bg, int tid)
{
    const float* s0 = reinterpret_cast<const float*>(Bg) + tid * 32;
    unsigned d0 = dB + tid * 128;
#pragma unroll
    for (int i = 0; i < 8; i++) cpa16(d0 + i * 16, s0 + i * 4);
    CPA_COMMIT();
}

// ---------------- prep: prompt-biases + bf16-split BT weight tiles -------
__global__ void prep_kernel(
    const float* __restrict__ prompt,
    const float* __restrict__ e_w1,  const float* __restrict__ e_b1,
    const float* __restrict__ n_w1,  const float* __restrict__ n_b1,
    const float* __restrict__ ae_w1, const float* __restrict__ ae_b1,
    const float* __restrict__ ap_w1, const float* __restrict__ ap_b1,
    const float* __restrict__ e_w2,  const float* __restrict__ n_w2)
{
    int n = threadIdx.x;
    int b = blockIdx.x;
    if (b < 4) {
        const float* w; const float* bias; float* dst; int off;
        if (b == 0)      { w = e_w1;  bias = e_b1;  dst = g_eb1;  off = 273; }
        else if (b == 1) { w = n_w1;  bias = n_b1;  dst = g_nb1;  off = 256; }
        else if (b == 2) { w = ae_w1; bias = ae_b1; dst = g_aeb1; off = 128; }
        else             { w = ap_w1; bias = ap_b1; dst = g_apb1; off = 128; }
        float s = bias[n];
        for (int j = 0; j < 128; j++)
            s = fmaf(prompt[j], w[(off + j) * 128 + n], s);
        dst[n] = s;
    } else {
        const float* W; char* BH; char* BL;
        switch (b) {
        case 4:  W = e_w2;          BH = (char*)g_Bw2h;  BL = (char*)g_Bw2l;  break;
        case 5:  W = ae_w1;         BH = (char*)g_Baeh;  BL = (char*)g_Bael;  break;
        case 6:  W = n_w1;          BH = (char*)g_Bn1ah; BL = (char*)g_Bn1al; break;
        case 7:  W = n_w1 + 16384;  BH = (char*)g_Bn1bh; BL = (char*)g_Bn1bl; break;
        case 8:  W = n_w2;          BH = (char*)g_Bn2h;  BL = (char*)g_Bn2l;  break;
        case 9:  W = ap_w1;         BH = (char*)g_Baph;  BL = (char*)g_Bapl;  break;
        case 10: W = e_w1;          BH = (char*)g_Be1ah; BL = (char*)g_Be1al; break;
        default: W = e_w1 + 16384;  BH = (char*)g_Be1bh; BL = (char*)g_Be1bl; break;
        }
        for (int i = n; i < 16384; i += 128) {
            int nn = i >> 7, k = i & 127;
            float v = W[k * 128 + nn];             // BT[nn][k] = W[k][nn]
            __nv_bfloat16 h = __float2bfloat16(v);
            __nv_bfloat16 l = __float2bfloat16(v - __bfloat162float(h));
            unsigned off = aoff(nn, k);
            *reinterpret_cast<unsigned short*>(BH + off) =
                *reinterpret_cast<unsigned short*>(&h);
            *reinterpret_cast<unsigned short*>(BL + off) =
                *reinterpret_cast<unsigned short*>(&l);
        }
    }
}

// ap_w2 copied to a device global so node_kernel sig stays small
__global__ void copy_apw2(const float* __restrict__ ap_w2)
{
    g_apw2c[threadIdx.x] = ap_w2[threadIdx.x];
}

// ---------------- node projection kernel (mma, unchanged) ----------------
#define PROJ_SMEM 98304

__global__ void __launch_bounds__(256, 2) proj_kernel(
    const float* __restrict__ h, int N)
{
    extern __shared__ float sm[];
    char* base = reinterpret_cast<char*>(sm);
    char* AhB = base;
    char* AlB = base + 16384;
    unsigned smem_u = (unsigned)__cvta_generic_to_shared(base);

    const int tid = threadIdx.x;
    const int wid = tid >> 5, lane = tid & 31;
    const long nb = (long)blockIdx.x * 64;

    {
        const int el = tid & 63, part = tid >> 6;
        long n = nb + el;
        if (n < N) {
            float4 z4 = make_float4(0.f, 0.f, 0.f, 0.f);
            float4* ga = reinterpret_cast<float4*>(g_agg + n * 128) + part * 8;
#pragma unroll
            for (int i = 0; i < 8; i++) ga[i] = z4;
            if (part == 0) {
                g_aggc[n*3+0] = 0.f; g_aggc[n*3+1] = 0.f; g_aggc[n*3+2] = 0.f;
            }
        }
    }

    stage_B(smem_u + 32768, smem_u + 65536, g_Be1ah, g_Be1al, tid);
    stage_A_split(AhB, AlB, h, nb, N, tid);
    CPA_WAIT0();
    __syncthreads();

    const int m0 = (wid >> 2) * 32;
    const int n0 = (wid & 3) * 32;
    const int g  = lane >> 2;
    const int q  = lane & 3;

    float c[2][4][4];

    mma_gemm(smem_u, smem_u + 16384, smem_u + 32768, smem_u + 65536,
             m0, n0, lane, c, true);
    __syncthreads();
    stage_B(smem_u + 32768, smem_u + 65536, g_Be1bh, g_Be1bl, tid);
#pragma unroll
    for (int i = 0; i < 2; i++) {
        int r0 = m0 + 16 * i + g;
        long na = nb + r0, nber = nb + r0 + 8;
#pragma unroll
        for (int jt = 0; jt < 4; jt++) {
            int col = n0 + 8 * jt + q * 2;
            if (na < N)
                *reinterpret_cast<float2*>(g_P + na * 256 + col) =
                    make_float2(c[i][jt][0], c[i][jt][1]);
            if (nber < N)
                *reinterpret_cast<float2*>(g_P + nber * 256 + col) =
                    make_float2(c[i][jt][2], c[i][jt][3]);
        }
    }
    CPA_WAIT0();
    __syncthreads();

    mma_gemm(smem_u, smem_u + 16384, smem_u + 32768, smem_u + 65536,
             m0, n0, lane, c, true);
#pragma unroll
    for (int i = 0; i < 2; i++) {
        int r0 = m0 + 16 * i + g;
        long na = nb + r0, nber = nb + r0 + 8;
#pragma unroll
        for (int jt = 0; jt < 4; jt++) {
            int col = n0 + 8 * jt + q * 2;
            if (na < N)
                *reinterpret_cast<float2*>(g_P + na * 256 + 128 + col) =
                    make_float2(c[i][jt][0], c[i][jt][1]);
            if (nber < N)
                *reinterpret_cast<float2*>(g_P + nber * 256 + 128 + col) =
                    make_float2(c[i][jt][2], c[i][jt][3]);
        }
    }
}

// ---------------- fused edge kernel (mma.sync, 64 edges, 3 CTAs/SM) ------
// byte map: Ah 0 (16K, start holds W1s@0 + XeT@8704) | Al 16384 (16K)
//   B 32768 (32K, one matrix at a time) | cd 65536 (1024)
//   sES 66560 (256) | rowi 66816 (256) | coli 67072 (256)
#define EOFF_AL  16384
#define EOFF_B   32768
#define EOFF_CD  65536
#define EOFF_SES 66560
#define EOFF_ROW 66816
#define EOFF_COL 67072
#define EOFF_XE  8704
#define EDGE_SMEM 67328

__global__ void __launch_bounds__(256, 3) edge_kernel(
    const int* __restrict__ ei,
    const float* __restrict__ coord, const float* __restrict__ eattr,
    const float* __restrict__ e_w1, const float* __restrict__ e_b2,
    const float* __restrict__ ae_w2, int E)
{
    extern __shared__ float sm[];
    char* base = reinterpret_cast<char*>(sm);
    char* AhB = base;
    char* AlB = base + EOFF_AL;
    float* W1s  = reinterpret_cast<float*>(base);            // scratch in Ah
    float* XeT  = reinterpret_cast<float*>(base + EOFF_XE);  // scratch in Ah
    float4* cd  = reinterpret_cast<float4*>(base + EOFF_CD);
    float*  sES = reinterpret_cast<float*>(base + EOFF_SES);
    int*   rowi = reinterpret_cast<int*>(base + EOFF_ROW);
    int*   coli = reinterpret_cast<int*>(base + EOFF_COL);
    unsigned smem_u = (unsigned)__cvta_generic_to_shared(base);
    const unsigned uB = smem_u + EOFF_B;

    const int tid = threadIdx.x;
    const int wid = tid >> 5, lane = tid & 31;
    const int e_base = blockIdx.x * 64;
    const int* rowg = ei;
    const int* colg = ei + E;

    // stage B = e_w2 HI, and W1s (17x128 fp32) into the Ah scratch region
    stage_B32(uB, g_Bw2h, tid);
    {
        const float* wsrc = e_w1 + 256 * 128;
        for (int i = tid; i < 544; i += 256)
            cpa16(smem_u + i * 16, wsrc + i * 4);
        CPA_COMMIT();
    }

    // ------- stage XeT: row0 = radial, rows 1..16 = eattr^T; indices -----
    {
        const int el = tid & 63, part = tid >> 6;
        int e = e_base + el;
        bool v = e < E;
        if (part == 0) {
            long r = v ? (long)rowg[e] : 0;
            long c = v ? (long)colg[e] : 0;
            rowi[el] = (int)r;
            coli[el] = (int)c;
            float dx = 0.f, dy = 0.f, dz = 0.f;
            if (v) {
                dx = coord[r*3+0] - coord[c*3+0];
                dy = coord[r*3+1] - coord[c*3+1];
                dz = coord[r*3+2] - coord[c*3+2];
            }
            float rad = dx*dx + dy*dy + dz*dz;
            XeT[el] = rad;
            float inv = 1.0f / fmaxf(sqrtf(rad), 1e-12f);
            cd[el] = make_float4(dx, dy, dz, inv);
        } else if (part == 1) {
            const float4* ea = reinterpret_cast<const float4*>(eattr) + (long)e * 4;
#pragma unroll
            for (int i = 0; i < 4; i++) {
                float4 a = v ? __ldg(ea + i) : make_float4(0.f, 0.f, 0.f, 0.f);
                int k = 1 + 4 * i;
                XeT[(k+0)*64 + el] = a.x; XeT[(k+1)*64 + el] = a.y;
                XeT[(k+2)*64 + el] = a.z; XeT[(k+3)*64 + el] = a.w;
            }
        }
    }
    CPA_WAIT0();
    __syncthreads();

    const int e0 = (wid >> 2) * 32 + (lane >> 2) * 4;
    const int c0 = (wid & 3) * 32 + (lane & 3) * 8;

    UL acc[16];

    // ------- acc init: eb1_eff + P1[row] + P2[col] -----------------------
    {
        float4 b0 = __ldg(reinterpret_cast<const float4*>(g_eb1 + c0));
        float4 b1 = __ldg(reinterpret_cast<const float4*>(g_eb1 + c0 + 4));
#pragma unroll
        for (int j = 0; j < 4; j++) {
            int r = rowi[e0 + j], cc = coli[e0 + j];
            const float* pr = g_P + (long)r  * 256 + c0;
            const float* pc = g_P + (long)cc * 256 + 128 + c0;
            float4 p0 = __ldg(reinterpret_cast<const float4*>(pr));
            float4 p1 = __ldg(reinterpret_cast<const float4*>(pr + 4));
            float4 q0 = __ldg(reinterpret_cast<const float4*>(pc));
            float4 q1 = __ldg(reinterpret_cast<const float4*>(pc + 4));
            acc[j*4+0] = pk2(b0.x + p0.x + q0.x, b0.y + p0.y + q0.y);
            acc[j*4+1] = pk2(b0.z + p0.z + q0.z, b0.w + p0.w + q0.w);
            acc[j*4+2] = pk2(b1.x + p1.x + q1.x, b1.y + p1.y + q1.y);
            acc[j*4+3] = pk2(b1.z + p1.z + q1.z, b1.w + p1.w + q1.w);
        }
    }

    // ------- GEMM1 (K=17, f32x2) from W1s/XeT scratch ---------------------
#pragma unroll
    for (int k = 0; k < 17; k++) {
        float4 xv = *reinterpret_cast<const float4*>(XeT + k * 64 + e0);
        const float* wb = W1s + k * 128 + c0;
        ulonglong2 a = *reinterpret_cast<const ulonglong2*>(wb);
        ulonglong2 b = *reinterpret_cast<const ulonglong2*>(wb + 4);
        UL s0 = bc2(xv.x), s1 = bc2(xv.y), s2 = bc2(xv.z), s3 = bc2(xv.w);
        FMAROW(a, b, s0, s1, s2, s3);
    }
    __syncthreads();   // everyone done reading W1s/XeT before A-tile writes
#pragma unroll
    for (int j = 0; j < 4; j++) {
        int r = e0 + j;
#pragma unroll
        for (int p = 0; p < 4; p++) {
            float2 f = up2(acc[j*4+p]);
            store_bf16_pair(AhB, AlB, r, c0 + 2*p, silu_f(f.x), silu_f(f.y));
        }
    }
    if (tid < 64) sES[tid] = 0.0f;
    __syncthreads();

    const int m0 = (wid >> 2) * 32;
    const int n0 = (wid & 3) * 32;
    const int g  = lane >> 2;
    const int q  = lane & 3;

    float c[2][4][4];
#pragma unroll
    for (int i = 0; i < 2; i++)
#pragma unroll
        for (int jt = 0; jt < 4; jt++)
#pragma unroll
            for (int t = 0; t < 4; t++) c[i][jt][t] = 0.0f;

    // ------- GEMM2: Y @ e_w2, terms (AhBh + AlBh) then (AhBl) ------------
    mma_2t(smem_u, smem_u + EOFF_AL, uB, m0, n0, lane, c);
    __syncthreads();               // Bh consumed
    stage_B32(uB, g_Bw2l, tid);    // B <- e_w2 LO
    CPA_WAIT0();
    __syncthreads();
    mma_1t(smem_u, uB, m0, n0, lane, c);
    __syncthreads();               // A and B consumed

    // stage B <- ae_w1 HI (overlaps epilogue)
    stage_B32(uB, g_Baeh, tid);

    // epilogue: bias+silu, store edge_feat to A tiles, g_agg atomics
#pragma unroll
    for (int i = 0; i < 2; i++) {
        int r0 = m0 + 16 * i + g;
#pragma unroll
        for (int jt = 0; jt < 4; jt++) {
            int col = n0 + 8 * jt + q * 2;
            float bx = __ldg(e_b2 + col), by = __ldg(e_b2 + col + 1);
            float z0 = silu_f(c[i][jt][0] + bx);
            float z1 = silu_f(c[i][jt][1] + by);
            float z2 = silu_f(c[i][jt][2] + bx);
            float z3 = silu_f(c[i][jt][3] + by);
            store_bf16_pair(AhB, AlB, r0,     col, z0, z1);
            store_bf16_pair(AhB, AlB, r0 + 8, col, z2, z3);
            if (e_base + r0 < E)
                atomicAdd(reinterpret_cast<float2*>(
                    g_agg + (long)rowi[r0] * 128 + col), make_float2(z0, z1));
            if (e_base + r0 + 8 < E)
                atomicAdd(reinterpret_cast<float2*>(
                    g_agg + (long)rowi[r0 + 8] * 128 + col), make_float2(z2, z3));
        }
    }
    CPA_WAIT0();
    __syncthreads();   // edge_feat + ae HI tiles visible

    // ------- GEMM3: edge_feat @ ae_w1, same term schedule ----------------
#pragma unroll
    for (int i = 0; i < 2; i++)
#pragma unroll
        for (int jt = 0; jt < 4; jt++)
#pragma unroll
            for (int t = 0; t < 4; t++) c[i][jt][t] = 0.0f;

    mma_2t(smem_u, smem_u + EOFF_AL, uB, m0, n0, lane, c);
    __syncthreads();
    stage_B32(uB, g_Bael, tid);    // B <- ae_w1 LO
    CPA_WAIT0();
    __syncthreads();
    mma_1t(smem_u, uB, m0, n0, lane, c);

    // epilogue: silu(c + aeb1) dot ae_w2 -> per-row sums in sES
    {
        float s[4] = {0.f, 0.f, 0.f, 0.f};
#pragma unroll
        for (int i = 0; i < 2; i++) {
#pragma unroll
            for (int jt = 0; jt < 4; jt++) {
                int col = n0 + 8 * jt + q * 2;
                float bx = __ldg(g_aeb1 + col), by = __ldg(g_aeb1 + col + 1);
                float wx = __ldg(ae_w2 + col),  wy = __ldg(ae_w2 + col + 1);
                s[2*i]   += silu_f(c[i][jt][0] + bx) * wx
                          + silu_f(c[i][jt][1] + by) * wy;
                s[2*i+1] += silu_f(c[i][jt][2] + bx) * wx
                          + silu_f(c[i][jt][3] + by) * wy;
            }
        }
#pragma unroll
        for (int t = 0; t < 4; t++) {
            s[t] += __shfl_xor_sync(0xffffffffu, s[t], 1);
            s[t] += __shfl_xor_sync(0xffffffffu, s[t], 2);
        }
        if (q == 0) {
            atomicAdd(&sES[m0 + g],      s[0]);
            atomicAdd(&sES[m0 + 8 + g],  s[1]);
            atomicAdd(&sES[m0 + 16 + g], s[2]);
            atomicAdd(&sES[m0 + 24 + g], s[3]);
        }
    }
    __syncthreads();

    if (tid < 64) {
        int eg = e_base + tid;
        if (eg < E) {
            float sv = sES[tid];
            float4 cdl = cd[tid];
            float f = sv * cdl.w;
            float* dst = g_aggc + (long)rowi[tid] * 3;
            atomicAdd(dst + 0, cdl.x * f);
            atomicAdd(dst + 1, cdl.y * f);
            atomicAdd(dst + 2, cdl.z * f);
        }
    }
}

// ---------------- fused node kernel (mma.sync, unchanged) ----------------
#define NODE_SMEM 98560

__global__ void __launch_bounds__(256, 2) node_kernel(
    const float* __restrict__ h, const float* __restrict__ coordg,
    const float* __restrict__ n_b2, float* __restrict__ out, int N)
{
    extern __shared__ float sm[];
    char* base = reinterpret_cast<char*>(sm);
    char* AhB = base;
    char* AlB = base + 16384;
    float* sES = reinterpret_cast<float*>(base + 98304);
    unsigned smem_u = (unsigned)__cvta_generic_to_shared(base);
    const unsigned uBh = smem_u + 32768, uBl = smem_u + 65536;

    const int tid = threadIdx.x;
    const int wid = tid >> 5, lane = tid & 31;
    const long nb = (long)blockIdx.x * 64;

    if (tid < 64) sES[tid] = 0.0f;

    stage_B(uBh, uBl, g_Bn1ah, g_Bn1al, tid);
    stage_A_split(AhB, AlB, h, nb, N, tid);
    CPA_WAIT0();
    __syncthreads();

    const int m0 = (wid >> 2) * 32;
    const int n0 = (wid & 3) * 32;
    const int g  = lane >> 2;
    const int q  = lane & 3;

    float c[2][4][4];

    mma_gemm(smem_u, smem_u + 16384, uBh, uBl, m0, n0, lane, c, true);
    __syncthreads();

    stage_B(uBh, uBl, g_Bn1bh, g_Bn1bl, tid);
    stage_A_split(AhB, AlB, g_agg, nb, N, tid);
    CPA_WAIT0();
    __syncthreads();

    mma_gemm(smem_u, smem_u + 16384, uBh, uBl, m0, n0, lane, c, false);
    __syncthreads();

    stage_B(uBh, uBl, g_Bn2h, g_Bn2l, tid);
#pragma unroll
    for (int i = 0; i < 2; i++) {
        int r0 = m0 + 16 * i + g;
#pragma unroll
        for (int jt = 0; jt < 4; jt++) {
            int col = n0 + 8 * jt + q * 2;
            float bx = __ldg(g_nb1 + col), by = __ldg(g_nb1 + col + 1);
            store_bf16_pair(AhB, AlB, r0, col,
                            silu_f(c[i][jt][0] + bx), silu_f(c[i][jt][1] + by));
            store_bf16_pair(AhB, AlB, r0 + 8, col,
                            silu_f(c[i][jt][2] + bx), silu_f(c[i][jt][3] + by));
        }
    }
    CPA_WAIT0();
    __syncthreads();

    mma_gemm(smem_u, smem_u + 16384, uBh, uBl, m0, n0, lane, c, true);
    __syncthreads();

    stage_B(uBh, uBl, g_Baph, g_Bapl, tid);
#pragma unroll
    for (int i = 0; i < 2; i++) {
        int r0 = m0 + 16 * i + g;
        long na = nb + r0, nbr = nb + r0 + 8;
#pragma unroll
        for (int jt = 0; jt < 4; jt++) {
            int col = n0 + 8 * jt + q * 2;
            float bx = __ldg(n_b2 + col), by = __ldg(n_b2 + col + 1);
            float2 hA = (na  < N) ? *reinterpret_cast<const float2*>(h + na  * 128 + col)
                                  : make_float2(0.f, 0.f);
            float2 hBv = (nbr < N) ? *reinterpret_cast<const float2*>(h + nbr * 128 + col)
                                   : make_float2(0.f, 0.f);
            float z0 = silu_f(c[i][jt][0] + bx) + hA.x;
            float z1 = silu_f(c[i][jt][1] + by) + hA.y;
            float z2 = silu_f(c[i][jt][2] + bx) + hBv.x;
            float z3 = silu_f(c[i][jt][3] + by) + hBv.y;
            store_bf16_pair(AhB, AlB, r0,     col, z0, z1);
            store_bf16_pair(AhB, AlB, r0 + 8, col, z2, z3);
            if (na < N)
                *reinterpret_cast<float2*>(out + na * 128 + col) = make_float2(z0, z1);
            if (nbr < N)
                *reinterpret_cast<float2*>(out + nbr * 128 + col) = make_float2(z2, z3);
        }
    }
    CPA_WAIT0();
    __syncthreads();

    mma_gemm(smem_u, smem_u + 16384, uBh, uBl, m0, n0, lane, c, true);

    {
        float s[4] = {0.f, 0.f, 0.f, 0.f};
#pragma unroll
        for (int i = 0; i < 2; i++) {
#pragma unroll
            for (int jt = 0; jt < 4; jt++) {
                int col = n0 + 8 * jt + q * 2;
                float bx = __ldg(g_apb1 + col), by = __ldg(g_apb1 + col + 1);
                s[2*i]   += silu_f(c[i][jt][0] + bx) * g_apw2c[col]
                          + silu_f(c[i][jt][1] + by) * g_apw2c[col + 1];
                s[2*i+1] += silu_f(c[i][jt][2] + bx) * g_apw2c[col]
                          + silu_f(c[i][jt][3] + by) * g_apw2c[col + 1];
            }
        }
#pragma unroll
        for (int t = 0; t < 4; t++) {
            s[t] += __shfl_xor_sync(0xffffffffu, s[t], 1);
            s[t] += __shfl_xor_sync(0xffffffffu, s[t], 2);
        }
        if (q == 0) {
            atomicAdd(&sES[m0 + g],      s[0]);
            atomicAdd(&sES[m0 + 8 + g],  s[1]);
            atomicAdd(&sES[m0 + 16 + g], s[2]);
            atomicAdd(&sES[m0 + 24 + g], s[3]);
        }
    }
    __syncthreads();

    if (tid < 64) {
        long n = nb + tid;
        if (n < N) {
            float s = sES[tid];
            long base_c = (long)N * 128;
            long base_a = (long)N * 131;
            out[base_c + n*3 + 0] = coordg[n*3+0];
            out[base_c + n*3 + 1] = coordg[n*3+1];
            out[base_c + n*3 + 2] = coordg[n*3+2];
            out[base_a + n*3 + 0] = g_aggc[n*3+0] * s;
            out[base_a + n*3 + 1] = g_aggc[n*3+1] * s;
            out[base_a + n*3 + 2] = g_aggc[n*3+2] * s;
        }
    }
}

// ---------------- launch ----------------
extern "C" void kernel_launch(void* const* d_in, const int* in_sizes, int n_in,
                              void* d_out, int out_size)
{
    const float* h      = (const float*)d_in[0];
    const int*   ei     = (const int*)  d_in[1];
    const float* coord  = (const float*)d_in[2];
    const float* eattr  = (const float*)d_in[3];
    const float* prompt = (const float*)d_in[4];
    const float* e_w1   = (const float*)d_in[5];
    const float* e_b1   = (const float*)d_in[6];
    const float* e_w2   = (const float*)d_in[7];
    const float* e_b2   = (const float*)d_in[8];
    const float* n_w1   = (const float*)d_in[9];
    const float* n_b1   = (const float*)d_in[10];
    const float* n_w2   = (const float*)d_in[11];
    const float* n_b2   = (const float*)d_in[12];
    const float* ae_w1  = (const float*)d_in[13];
    const float* ae_b1  = (const float*)d_in[14];
    const float* ae_w2  = (const float*)d_in[15];
    const float* ap_w1  = (const float*)d_in[16];
    const float* ap_b1  = (const float*)d_in[17];
    const float* ap_w2  = (const float*)d_in[18];
    float* out = (float*)d_out;

    int N = in_sizes[0] / 128;
    int E = in_sizes[1] / 2;

    cudaFuncSetAttribute(proj_kernel, cudaFuncAttributeMaxDynamicSharedMemorySize, PROJ_SMEM);
    cudaFuncSetAttribute(edge_kernel, cudaFuncAttributeMaxDynamicSharedMemorySize, EDGE_SMEM);
    cudaFuncSetAttribute(node_kernel, cudaFuncAttributeMaxDynamicSharedMemorySize, NODE_SMEM);

    prep_kernel<<<12, 128>>>(prompt, e_w1, e_b1, n_w1, n_b1,
                             ae_w1, ae_b1, ap_w1, ap_b1, e_w2, n_w2);
    copy_apw2<<<1, 128>>>(ap_w2);
    proj_kernel<<<(N + 63) / 64, 256, PROJ_SMEM>>>(h, N);
    edge_kernel<<<(E + 63) / 64, 256, EDGE_SMEM>>>(ei, coord, eattr,
                                                   e_w1, e_b2, ae_w2, E);
    node_kernel<<<(N + 63) / 64, 256, NODE_SMEM>>>(h, coord, n_b2, out, N);
}